// round 8
// baseline (speedup 1.0000x reference)
#include <cuda_runtime.h>
#include <cuda_bf16.h>
#include <cstdint>

// ---------------- problem constants ----------------
#define T_LEN 2048
#define DM    1024
#define NHEAD 16
#define HDIM  64
#define NB    32
#define SSEL  16
#define NEGV  (-1e30f)
#define NEGS  (-1.25e29f)

// ---------------- scratch ----------------------------------------------------
__device__ float g_q   [T_LEN * DM];
__device__ float g_k   [T_LEN * HDIM];
__device__ float g_v   [T_LEN * HDIM];
__device__ float g_g   [T_LEN * 48];
__device__ float g_kc  [NB * HDIM];
__device__ float g_vc  [NB * HDIM];
__device__ float g_ocmp[T_LEN * DM];
__device__ int   g_blk [T_LEN * SSEL];

__device__ __nv_bfloat16 g_xh [T_LEN * DM], g_xl [T_LEN * DM];
__device__ __nv_bfloat16 g_qh [T_LEN * DM], g_ql [T_LEN * DM];
__device__ __nv_bfloat16 g_ch [T_LEN * DM], g_cl [T_LEN * DM];
__device__ __nv_bfloat16 g_kh [T_LEN * HDIM], g_kl [T_LEN * HDIM];
__device__ __nv_bfloat16 g_vh [T_LEN * HDIM], g_vl [T_LEN * HDIM];
__device__ __nv_bfloat16 g_wch[1280 * DM], g_wcl[1280 * DM];   // stacked Wq|Wk|Wv|Wg|pad
__device__ __nv_bfloat16 g_woh[DM * DM],   g_wol[DM * DM];

// ================= helpers ==================================================
__device__ __forceinline__ uint32_t smem_u32(const void* p) {
    uint32_t a;
    asm("{ .reg .u64 t; cvta.to.shared.u64 t, %1; cvt.u32.u64 %0, t; }"
        : "=r"(a) : "l"(p));
    return a;
}
__device__ __forceinline__ void cp_async16(uint32_t saddr, const void* gaddr) {
    asm volatile("cp.async.cg.shared.global [%0], [%1], 16;"
                 :: "r"(saddr), "l"(gaddr));
}
__device__ __forceinline__ void cp_commit() {
    asm volatile("cp.async.commit_group;" ::: "memory");
}
__device__ __forceinline__ void cp_wait0() {
    asm volatile("cp.async.wait_group 0;" ::: "memory");
}
__device__ __forceinline__ void cp_wait1() {
    asm volatile("cp.async.wait_group 1;" ::: "memory");
}
__device__ __forceinline__ void ldsm4(uint32_t* r, uint32_t addr) {
    asm volatile("ldmatrix.sync.aligned.m8n8.x4.shared.b16 {%0,%1,%2,%3}, [%4];"
                 : "=r"(r[0]), "=r"(r[1]), "=r"(r[2]), "=r"(r[3]) : "r"(addr));
}
__device__ __forceinline__ void ldsm2(uint32_t* r, uint32_t addr) {
    asm volatile("ldmatrix.sync.aligned.m8n8.x2.shared.b16 {%0,%1}, [%2];"
                 : "=r"(r[0]), "=r"(r[1]) : "r"(addr));
}
__device__ __forceinline__ void ldsm4t(uint32_t* r, uint32_t addr) {
    asm volatile("ldmatrix.sync.aligned.m8n8.x4.trans.shared.b16 {%0,%1,%2,%3}, [%4];"
                 : "=r"(r[0]), "=r"(r[1]), "=r"(r[2]), "=r"(r[3]) : "r"(addr));
}
__device__ __forceinline__ void mma16816(float* d, const uint32_t* a, const uint32_t* b) {
    asm volatile(
        "mma.sync.aligned.m16n8k16.row.col.f32.bf16.bf16.f32 "
        "{%0,%1,%2,%3}, {%4,%5,%6,%7}, {%8,%9}, {%0,%1,%2,%3};"
        : "+f"(d[0]), "+f"(d[1]), "+f"(d[2]), "+f"(d[3])
        : "r"(a[0]), "r"(a[1]), "r"(a[2]), "r"(a[3]), "r"(b[0]), "r"(b[1]));
}
__device__ __forceinline__ void mma16808(float* d, uint32_t a0, uint32_t a1, uint32_t b0) {
    asm volatile(
        "mma.sync.aligned.m16n8k8.row.col.f32.bf16.bf16.f32 "
        "{%0,%1,%2,%3}, {%4,%5}, {%6}, {%0,%1,%2,%3};"
        : "+f"(d[0]), "+f"(d[1]), "+f"(d[2]), "+f"(d[3])
        : "r"(a0), "r"(a1), "r"(b0));
}
__device__ __forceinline__ uint32_t pack_bf16x2(float lo, float hi) {
    uint32_t r;
    asm("cvt.rn.bf16x2.f32 %0, %1, %2;" : "=r"(r) : "f"(hi), "f"(lo));
    return r;
}
__device__ __forceinline__ uint32_t pack_hi(float a, float b, __nv_bfloat16& ha, __nv_bfloat16& hb) {
    ha = __float2bfloat16(a); hb = __float2bfloat16(b);
    return (uint32_t)__bfloat16_as_ushort(ha) | ((uint32_t)__bfloat16_as_ushort(hb) << 16);
}

// ================= fp32 -> bf16 hi/lo conversion ============================
__global__ __launch_bounds__(256) void conv_hilo(const float4* __restrict__ src,
                                                 uint2* __restrict__ h,
                                                 uint2* __restrict__ l, int n4) {
    int i = blockIdx.x * 256 + threadIdx.x;
    if (i >= n4) return;
    float4 v = src[i];
    __nv_bfloat16 h0, h1, h2, h3;
    uint32_t a = pack_hi(v.x, v.y, h0, h1);
    uint32_t b = pack_hi(v.z, v.w, h2, h3);
    uint2 hv, lv;
    hv.x = a; hv.y = b;
    lv.x = pack_bf16x2(v.x - __bfloat162float(h0), v.y - __bfloat162float(h1));
    lv.y = pack_bf16x2(v.z - __bfloat162float(h2), v.w - __bfloat162float(h3));
    h[i] = hv;
    l[i] = lv;
}

// ================= tensor-core GEMM via mma.sync (bf16x3, 3-stage) ==========
#define TSTRIDE 80
#define TILE_BYTES (128 * TSTRIDE)
#define BUF_BYTES  (4 * TILE_BYTES)
#define GEMM_SMEM  (3 * BUF_BYTES)    // 122880

__global__ __launch_bounds__(256) void gemm_mma(const __nv_bfloat16* __restrict__ Ah,
                                                const __nv_bfloat16* __restrict__ Al,
                                                const __nv_bfloat16* __restrict__ Bh,
                                                const __nv_bfloat16* __restrict__ Bl,
                                                float* __restrict__ C,
                                                int mode) {
    extern __shared__ char sm[];
    const uint32_t sbase = smem_u32(sm);
    const int tid = threadIdx.x;
    const int lane = tid & 31, wid = tid >> 5;
    const int m0 = blockIdx.y * 128;
    const int n0 = blockIdx.x * 128;
    const int wm = (wid >> 2) * 64;
    const int wn = (wid & 3) * 32;

    const __nv_bfloat16* gsrc[4] = {Ah, Al, Bh, Bl};

    float acc[4][4][4];
#pragma unroll
    for (int i = 0; i < 4; i++)
#pragma unroll
        for (int j = 0; j < 4; j++)
#pragma unroll
            for (int k = 0; k < 4; k++) acc[i][j][k] = 0.f;

    const int arow = wm + (lane & 15);
    const int akc  = (lane >> 4) << 3;
    const int brow = wn + (lane & 7) + ((lane >> 4) << 3);
    const int bkc  = ((lane >> 3) & 1) << 3;

    auto issue = [&](int c, int buf) {
#pragma unroll
        for (int T = 0; T < 4; T++) {
            const __nv_bfloat16* src = gsrc[T];
            const int rb = (T < 2) ? m0 : n0;
#pragma unroll
            for (int i = 0; i < 2; i++) {
                int idx = i * 256 + tid;
                int row = idx >> 2;
                int u   = idx & 3;
                uint32_t sa = sbase + buf * BUF_BYTES + T * TILE_BYTES + row * TSTRIDE + u * 16;
                cp_async16(sa, src + (size_t)(rb + row) * 1024 + c * 32 + u * 8);
            }
        }
        cp_commit();
    };

    issue(0, 0);
    issue(1, 1);

    for (int c = 0; c < 32; c++) {
        if (c + 1 < 32) cp_wait1(); else cp_wait0();
        __syncthreads();
        if (c + 2 < 32) issue(c + 2, (c + 2) % 3);

        const uint32_t base = sbase + (c % 3) * BUF_BYTES;
#pragma unroll
        for (int ks = 0; ks < 2; ks++) {
            uint32_t ah[4][4], al[4][4], bh[2][4], bl[2][4];
#pragma unroll
            for (int mt = 0; mt < 4; mt++) {
                uint32_t aa = base + (arow + mt * 16) * TSTRIDE + (ks * 16 + akc) * 2;
                ldsm4(ah[mt], aa);
                ldsm4(al[mt], aa + TILE_BYTES);
            }
#pragma unroll
            for (int np = 0; np < 2; np++) {
                uint32_t ba = base + 2 * TILE_BYTES + (brow + np * 16) * TSTRIDE + (ks * 16 + bkc) * 2;
                ldsm4(bh[np], ba);
                ldsm4(bl[np], ba + TILE_BYTES);
            }
#pragma unroll
            for (int mt = 0; mt < 4; mt++)
#pragma unroll
                for (int nt = 0; nt < 4; nt++) {
                    const uint32_t* ph = &bh[nt >> 1][(nt & 1) * 2];
                    const uint32_t* pl = &bl[nt >> 1][(nt & 1) * 2];
                    mma16816(acc[mt][nt], ah[mt], ph);
                    mma16816(acc[mt][nt], al[mt], ph);
                    mma16816(acc[mt][nt], ah[mt], pl);
                }
        }
    }

    const int g = lane >> 2, t4 = lane & 3;
#pragma unroll
    for (int mt = 0; mt < 4; mt++)
#pragma unroll
        for (int nt = 0; nt < 4; nt++) {
            int r = m0 + wm + mt * 16 + g;
            int cc = n0 + wn + nt * 8 + t4 * 2;
#pragma unroll
            for (int half = 0; half < 2; half++) {
                int rr = r + half * 8;
                float v0 = acc[mt][nt][half * 2], v1 = acc[mt][nt][half * 2 + 1];
                if (mode == 0) {
                    *(float2*)(C + (size_t)rr * 1024 + cc) = make_float2(v0, v1);
                } else {
                    __nv_bfloat16 b0, b1;
                    if (cc < 1024) {
                        *(float2*)(g_q + (size_t)rr * 1024 + cc) = make_float2(v0, v1);
                        uint32_t hh = pack_hi(v0, v1, b0, b1);
                        *(uint32_t*)(g_qh + (size_t)rr * 1024 + cc) = hh;
                        *(uint32_t*)(g_ql + (size_t)rr * 1024 + cc) =
                            pack_bf16x2(v0 - __bfloat162float(b0), v1 - __bfloat162float(b1));
                    } else if (cc < 1088) {
                        int k = cc - 1024;
                        *(float2*)(g_k + (size_t)rr * 64 + k) = make_float2(v0, v1);
                        uint32_t hh = pack_hi(v0, v1, b0, b1);
                        *(uint32_t*)(g_kh + (size_t)rr * 64 + k) = hh;
                        *(uint32_t*)(g_kl + (size_t)rr * 64 + k) =
                            pack_bf16x2(v0 - __bfloat162float(b0), v1 - __bfloat162float(b1));
                    } else if (cc < 1152) {
                        int k = cc - 1088;
                        *(float2*)(g_v + (size_t)rr * 64 + k) = make_float2(v0, v1);
                        uint32_t hh = pack_hi(v0, v1, b0, b1);
                        *(uint32_t*)(g_vh + (size_t)rr * 64 + k) = hh;
                        *(uint32_t*)(g_vl + (size_t)rr * 64 + k) =
                            pack_bf16x2(v0 - __bfloat162float(b0), v1 - __bfloat162float(b1));
                    } else if (cc < 1200) {
                        int k = cc - 1152;
                        *(float2*)(g_g + (size_t)rr * 48 + k) = make_float2(v0, v1);
                    }
                }
            }
        }
}

// ---------------- mean-pool K,V ---------------------------------------------
__global__ void pool_kv() {
    int c = blockIdx.x, d = threadIdx.x;
    float sk = 0.f, sv = 0.f;
    for (int i = 0; i < 64; i++) {
        sk += g_k[(size_t)(c * 64 + i) * 64 + d];
        sv += g_v[(size_t)(c * 64 + i) * 64 + d];
    }
    g_kc[c * 64 + d] = sk * (1.f / 64.f);
    g_vc[c * 64 + d] = sv * (1.f / 64.f);
}

// --------- compressed attention + top-k, 4 tokens per CTA (256 thr) ---------
__global__ __launch_bounds__(256) void cmp4() {
    __shared__ float sq  [4 * 1024];
    __shared__ float skc [NB * 64];
    __shared__ float svc [NB * 64];
    __shared__ float sp  [4 * NHEAD * NB];
    __shared__ float simp[4 * NB];

    const int T0 = blockIdx.x * 4, tid = threadIdx.x;

    for (int i = tid; i < 1024; i += 256) {
        int tok = i >> 8, e = i & 255;
        ((float4*)sq)[i] = ((const float4*)(g_q + (size_t)(T0 + tok) * 1024))[e];
    }
    for (int i = tid; i < 512; i += 256) {
        ((float4*)skc)[i] = ((const float4*)g_kc)[i];
        ((float4*)svc)[i] = ((const float4*)g_vc)[i];
    }
    __syncthreads();

    const float scale = 0.125f;

    for (int idx = tid; idx < 4 * NHEAD * NB; idx += 256) {
        int tok = idx >> 9, rem = idx & 511;
        int h = rem >> 5, c = rem & 31;
        int nvis = (T0 + tok + 1) >> 6;
        float s;
        if (c < nvis) {
            const float4* qa = (const float4*)(sq + tok * 1024 + h * 64);
            const float4* ka = (const float4*)(skc + c * 64);
            s = 0.f;
#pragma unroll
            for (int i = 0; i < 16; i++) {
                float4 x = qa[i], y = ka[i];
                s += x.x * y.x + x.y * y.y + x.z * y.z + x.w * y.w;
            }
            s *= scale;
        } else s = NEGV;
        sp[idx] = s;
    }
    __syncthreads();

    if (tid < 64) {
        int tok = tid >> 4;
        int nvis = (T0 + tok + 1) >> 6;
        float* row = sp + tok * 512 + (tid & 15) * 32;
        if (nvis == 0) {
            for (int c = 0; c < NB; c++) row[c] = 0.f;
        } else {
            float m = -INFINITY;
            for (int c = 0; c < nvis; c++) m = fmaxf(m, row[c]);
            float sum = 0.f;
            for (int c = 0; c < nvis; c++) { float e = __expf(row[c] - m); row[c] = e; sum += e; }
            float inv = 1.f / sum;
            for (int c = 0; c < nvis; c++) row[c] *= inv;
            for (int c = nvis; c < NB; c++) row[c] = 0.f;
        }
    }
    __syncthreads();

    for (int idx = tid; idx < 4 * NHEAD * HDIM; idx += 256) {
        int tok = idx >> 10, rem = idx & 1023;
        int h = rem >> 6, d = rem & 63;
        int nvis = (T0 + tok + 1) >> 6;
        float o = 0.f;
        for (int c = 0; c < nvis; c++) o += sp[tok * 512 + h * NB + c] * svc[c * 64 + d];
        g_ocmp[(size_t)(T0 + tok) * 1024 + rem] = o;
    }

    if (tid < 128) {
        int tok = tid >> 5, c = tid & 31;
        int cur = (T0 + tok) >> 6;
        float im;
        if (c == 0 || c == cur) im = INFINITY;
        else if (c <= cur) {
            im = 0.f;
            for (int h = 0; h < NHEAD; h++) im += sp[tok * 512 + h * NB + c];
        } else im = NEGV;
        simp[tok * 32 + c] = im;
    }
    __syncthreads();

    const int w = tid >> 5, lane = tid & 31;
    if (w < 4) {
        float v = simp[w * 32 + lane];
#pragma unroll
        for (int s = 0; s < SSEL; s++) {
            float bv = v; int bi = lane;
#pragma unroll
            for (int off = 16; off >= 1; off >>= 1) {
                float ov = __shfl_xor_sync(0xffffffffu, bv, off);
                int   oi = __shfl_xor_sync(0xffffffffu, bi, off);
                if (ov > bv || (ov == bv && oi < bi)) { bv = ov; bi = oi; }
            }
            if (lane == 0) g_blk[(T0 + w) * SSEL + s] = bi;
            if (lane == bi) v = -INFINITY;
        }
    }
}

// ====== union-block selected attention, 16 tokens/CTA, 1 token/warp, 3-stage
// 512 threads. smem: Qh 256x144 | Ql | 3 KV stages | meta. 184576 B
#define SQL_OFF   36864
#define STG_OFF   73728
#define STG_SZ    36864
#define KV_T      9216
#define META_OFF  184320
#define SLC16_SMEM (184320 + 256)

__global__ __launch_bounds__(512, 1) void slc16() {
    extern __shared__ char smc[];
    const uint32_t sb0 = smem_u32(smc);
    const int tid = threadIdx.x;
    const int lane = tid & 31, w = tid >> 5;   // w = 0..15, one token per warp
    const int T0 = blockIdx.x * 16;
    const int tt = T0 + w;

    uint32_t* smask = (uint32_t*)(smc + META_OFF);
    int* ulist = (int*)(smc + META_OFF + 64);
    int* ucnt  = (int*)(smc + META_OFF + 192);

    // ---- stage Q hi/lo (row = token*16+head) ----
#pragma unroll
    for (int i = 0; i < 8; i++) {
        int idx = i * 512 + tid;                 // 0..4095
        int tile = idx >> 11;
        int row = (idx >> 3) & 255, u = idx & 7;
        int token = T0 + (row >> 4), head = row & 15;
        size_t go = (size_t)token * 1024 + head * 64 + u * 8;
        cp_async16(sb0 + tile * SQL_OFF + row * 144 + u * 16, (tile ? g_ql : g_qh) + go);
    }
    cp_commit();

    // ---- per-token selection masks + union list ----
    if (tid < 16) {
        uint32_t m = 0;
        for (int s = 0; s < SSEL; s++) m |= 1u << g_blk[(T0 + tid) * SSEL + s];
        smask[tid] = m;
    }
    __syncthreads();
    if (tid == 0) {
        uint32_t u = 0;
        for (int i = 0; i < 16; i++) u |= smask[i];
        int cnt = 0;
        for (int c = 0; c < NB; c++)
            if ((u >> c) & 1u) ulist[cnt++] = c;
        *ucnt = cnt;
    }
    __syncthreads();
    const int nu = *ucnt;

    auto issueKV = [&](int c, int stage) {
        uint32_t base = sb0 + STG_OFF + stage * STG_SZ;
#pragma unroll
        for (int i = 0; i < 4; i++) {
            int cid = i * 512 + tid;             // 0..2047
            int tile = cid >> 9, r = (cid >> 3) & 63, u = cid & 7;
            const __nv_bfloat16* gp = (tile == 0) ? g_kh : (tile == 1) ? g_kl
                                    : (tile == 2) ? g_vh : g_vl;
            cp_async16(base + tile * KV_T + r * 144 + u * 16,
                       gp + (size_t)(c * 64 + r) * 64 + u * 8);
        }
        cp_commit();
    };

    issueKV(ulist[0], 0);
    if (nu > 1) issueKV(ulist[1], 1);

    const uint32_t msk = smask[w];

    float ov[8][4];
#pragma unroll
    for (int vt = 0; vt < 8; vt++)
#pragma unroll
        for (int j = 0; j < 4; j++) ov[vt][j] = 0.f;
    float mrow[2] = {NEGS, NEGS};
    float srow[2] = {0.f, 0.f};

    for (int i = 0; i < nu; i++) {
        if (i + 1 < nu) cp_wait1(); else cp_wait0();
        __syncthreads();
        if (i + 2 < nu) issueKV(ulist[i + 2], (i + 2) % 3);

        const int c = ulist[i];
        if ((msk >> c) & 1u) {
            const uint32_t base = sb0 + STG_OFF + (i % 3) * STG_SZ;

            // ---- QK (bf16x3): D[8 ntiles][4] ----
            float d[8][4];
#pragma unroll
            for (int nt = 0; nt < 8; nt++)
#pragma unroll
                for (int j = 0; j < 4; j++) d[nt][j] = 0.f;

#pragma unroll
            for (int ks = 0; ks < 4; ks++) {
                uint32_t qa = sb0 + (w * 16 + (lane & 15)) * 144 + ((lane >> 4) << 4) + ks * 32;
                uint32_t qh4[4], ql4[4];
                ldsm4(qh4, qa);
                ldsm4(ql4, qa + SQL_OFF);
#pragma unroll
                for (int nt = 0; nt < 8; nt++) {
                    uint32_t bh2[2], bl2[2];
                    uint32_t ba = base + (nt * 8 + (lane & 7)) * 144 + ((lane >> 3) & 1) * 16 + ks * 32;
                    ldsm2(bh2, ba);
                    ldsm2(bl2, ba + KV_T);
                    mma16816(d[nt], qh4, bh2);
                    mma16816(d[nt], ql4, bh2);
                    mma16816(d[nt], qh4, bl2);
                }
            }

            // ---- scale + causal mask + online max/rescale ----
            const int colb = c * 64 + ((lane & 3) << 1);
            float bm0 = NEGS, bm1 = NEGS;
#pragma unroll
            for (int nt = 0; nt < 8; nt++) {
                int tok0 = colb + nt * 8;
                bool v0 = tok0 <= tt, v1 = tok0 + 1 <= tt;
                d[nt][0] = v0 ? d[nt][0] * 0.125f : NEGS;
                d[nt][1] = v1 ? d[nt][1] * 0.125f : NEGS;
                d[nt][2] = v0 ? d[nt][2] * 0.125f : NEGS;
                d[nt][3] = v1 ? d[nt][3] * 0.125f : NEGS;
                bm0 = fmaxf(bm0, fmaxf(d[nt][0], d[nt][1]));
                bm1 = fmaxf(bm1, fmaxf(d[nt][2], d[nt][3]));
            }
            bm0 = fmaxf(bm0, __shfl_xor_sync(0xffffffffu, bm0, 1));
            bm0 = fmaxf(bm0, __shfl_xor_sync(0xffffffffu, bm0, 2));
            bm1 = fmaxf(bm1, __shfl_xor_sync(0xffffffffu, bm1, 1));
            bm1 = fmaxf(bm1, __shfl_xor_sync(0xffffffffu, bm1, 2));
            float mn0 = fmaxf(mrow[0], bm0), mn1 = fmaxf(mrow[1], bm1);
            float a0 = __expf(mrow[0] - mn0), a1 = __expf(mrow[1] - mn1);
            mrow[0] = mn0; mrow[1] = mn1;
            srow[0] *= a0; srow[1] *= a1;
#pragma unroll
            for (int vt = 0; vt < 8; vt++) {
                ov[vt][0] *= a0; ov[vt][1] *= a0;
                ov[vt][2] *= a1; ov[vt][3] *= a1;
            }

            // ---- exp + PV (bf16x3) ----
#pragma unroll
            for (int nt = 0; nt < 8; nt++) {
                uint32_t vh8[8], vl8[8];
                uint32_t va = base + 2 * KV_T + (nt * 8 + (lane & 7)) * 144 + (lane >> 3) * 16;
                ldsm4t(vh8, va);        ldsm4t(vh8 + 4, va + 64);
                ldsm4t(vl8, va + KV_T); ldsm4t(vl8 + 4, va + KV_T + 64);
                float p0 = __expf(d[nt][0] - mrow[0]);
                float p1 = __expf(d[nt][1] - mrow[0]);
                float p2 = __expf(d[nt][2] - mrow[1]);
                float p3 = __expf(d[nt][3] - mrow[1]);
                srow[0] += p0 + p1;
                srow[1] += p2 + p3;
                __nv_bfloat16 b0, b1, b2, b3;
                uint32_t ah0 = pack_hi(p0, p1, b0, b1);
                uint32_t ah1 = pack_hi(p2, p3, b2, b3);
                uint32_t al0 = pack_bf16x2(p0 - __bfloat162float(b0), p1 - __bfloat162float(b1));
                uint32_t al1 = pack_bf16x2(p2 - __bfloat162float(b2), p3 - __bfloat162float(b3));
#pragma unroll
                for (int vt = 0; vt < 8; vt++) {
                    mma16808(ov[vt], ah0, ah1, vh8[vt]);
                    mma16808(ov[vt], al0, al1, vh8[vt]);
                    mma16808(ov[vt], ah0, ah1, vl8[vt]);
                }
            }
        }
    }

    // ---- epilogue: quad-reduce sums, normalize, gate, add ocmp, emit hi/lo ----
#pragma unroll
    for (int half = 0; half < 2; half++) {
        float s = srow[half];
        s += __shfl_xor_sync(0xffffffffu, s, 1);
        s += __shfl_xor_sync(0xffffffffu, s, 2);
        float inv = 1.f / s;
        int h = (lane >> 2) + half * 8;
        float gc = 1.f / (1.f + __expf(-g_g[tt * 48 + h * 3]));
        float gs = 1.f / (1.f + __expf(-g_g[tt * 48 + h * 3 + 1]));
#pragma unroll
        for (int vt = 0; vt < 8; vt++) {
            int col = vt * 8 + ((lane & 3) << 1);
            size_t off = (size_t)tt * 1024 + h * 64 + col;
            float2 oc = *(const float2*)(g_ocmp + off);
            float c0 = ov[vt][half * 2]     * inv * gs + oc.x * gc;
            float c1 = ov[vt][half * 2 + 1] * inv * gs + oc.y * gc;
            __nv_bfloat16 b0, b1;
            *(uint32_t*)(g_ch + off) = pack_hi(c0, c1, b0, b1);
            *(uint32_t*)(g_cl + off) =
                pack_bf16x2(c0 - __bfloat162float(b0), c1 - __bfloat162float(b1));
        }
    }
}

// ---------------- launch ----------------------------------------------------
extern "C" void kernel_launch(void* const* d_in, const int* in_sizes, int n_in,
                              void* d_out, int out_size) {
    const float* x  = (const float*)d_in[0];
    const float* Wq = (const float*)d_in[1];
    const float* Wk = (const float*)d_in[2];
    const float* Wv = (const float*)d_in[3];
    const float* Wg = (const float*)d_in[4];
    const float* Wo = (const float*)d_in[5];
    float* out = (float*)d_out;

    void *pq, *pxh, *pxl, *pch, *pcl, *pwch, *pwcl, *pwoh, *pwol;
    cudaGetSymbolAddress(&pq, g_q);
    cudaGetSymbolAddress(&pxh, g_xh);   cudaGetSymbolAddress(&pxl, g_xl);
    cudaGetSymbolAddress(&pch, g_ch);   cudaGetSymbolAddress(&pcl, g_cl);
    cudaGetSymbolAddress(&pwch, g_wch); cudaGetSymbolAddress(&pwcl, g_wcl);
    cudaGetSymbolAddress(&pwoh, g_woh); cudaGetSymbolAddress(&pwol, g_wol);

    __nv_bfloat16* wch = (__nv_bfloat16*)pwch;
    __nv_bfloat16* wcl = (__nv_bfloat16*)pwcl;

    cudaFuncSetAttribute(gemm_mma, cudaFuncAttributeMaxDynamicSharedMemorySize, GEMM_SMEM);
    cudaFuncSetAttribute(slc16, cudaFuncAttributeMaxDynamicSharedMemorySize, SLC16_SMEM);

    // conversions
    conv_hilo<<<2048, 256>>>((const float4*)x, (uint2*)pxh, (uint2*)pxl, 524288);
    conv_hilo<<<1024, 256>>>((const float4*)Wq, (uint2*)wch, (uint2*)wcl, 262144);
    conv_hilo<<<64, 256>>>((const float4*)Wk, (uint2*)(wch + 1024 * 1024), (uint2*)(wcl + 1024 * 1024), 16384);
    conv_hilo<<<64, 256>>>((const float4*)Wv, (uint2*)(wch + 1088 * 1024), (uint2*)(wcl + 1088 * 1024), 16384);
    conv_hilo<<<48, 256>>>((const float4*)Wg, (uint2*)(wch + 1152 * 1024), (uint2*)(wcl + 1152 * 1024), 12288);
    cudaMemsetAsync(wch + 1200 * 1024, 0, 80 * 1024 * 2);
    cudaMemsetAsync(wcl + 1200 * 1024, 0, 80 * 1024 * 2);
    conv_hilo<<<1024, 256>>>((const float4*)Wo, (uint2*)pwoh, (uint2*)pwol, 262144);

    // fused projections: [Q | K | V | G] = x @ [Wq;Wk;Wv;Wg]^T
    gemm_mma<<<dim3(10, 16), 256, GEMM_SMEM>>>((const __nv_bfloat16*)pxh, (const __nv_bfloat16*)pxl,
                                               wch, wcl, (float*)pq, 1);
    pool_kv<<<NB, 64>>>();
    cmp4<<<T_LEN / 4, 256>>>();
    slc16<<<T_LEN / 16, 512, SLC16_SMEM>>>();

    // out = comb @ Wo^T
    gemm_mma<<<dim3(8, 16), 256, GEMM_SMEM>>>((const __nv_bfloat16*)pch, (const __nv_bfloat16*)pcl,
                                              (const __nv_bfloat16*)pwoh, (const __nv_bfloat16*)pwol,
                                              out, 0);
}

// round 9
// speedup vs baseline: 1.0122x; 1.0122x over previous
#include <cuda_runtime.h>
#include <cuda_bf16.h>
#include <cstdint>

// ---------------- problem constants ----------------
#define T_LEN 2048
#define DM    1024
#define NHEAD 16
#define HDIM  64
#define NB    32
#define SSEL  16
#define NEGV  (-1e30f)
#define NEGS  (-1.25e29f)

// ---------------- scratch ----------------------------------------------------
__device__ float g_q   [T_LEN * DM];
__device__ float g_k   [T_LEN * HDIM];
__device__ float g_v   [T_LEN * HDIM];
__device__ float g_g   [T_LEN * 48];
__device__ float g_kc  [NB * HDIM];
__device__ float g_vc  [NB * HDIM];
__device__ float g_ocmp[T_LEN * DM];
__device__ int   g_blk [T_LEN * SSEL];

__device__ __nv_bfloat16 g_xh [T_LEN * DM], g_xl [T_LEN * DM];
__device__ __nv_bfloat16 g_qh [T_LEN * DM], g_ql [T_LEN * DM];
__device__ __nv_bfloat16 g_ch [T_LEN * DM], g_cl [T_LEN * DM];
__device__ __nv_bfloat16 g_kh [T_LEN * HDIM], g_kl [T_LEN * HDIM];
__device__ __nv_bfloat16 g_vh [T_LEN * HDIM], g_vl [T_LEN * HDIM];
__device__ __nv_bfloat16 g_wch[1280 * DM], g_wcl[1280 * DM];   // stacked Wq|Wk|Wv|Wg|pad
__device__ __nv_bfloat16 g_woh[DM * DM],   g_wol[DM * DM];

// ================= helpers ==================================================
__device__ __forceinline__ uint32_t smem_u32(const void* p) {
    uint32_t a;
    asm("{ .reg .u64 t; cvta.to.shared.u64 t, %1; cvt.u32.u64 %0, t; }"
        : "=r"(a) : "l"(p));
    return a;
}
__device__ __forceinline__ void cp_async16(uint32_t saddr, const void* gaddr) {
    asm volatile("cp.async.cg.shared.global [%0], [%1], 16;"
                 :: "r"(saddr), "l"(gaddr));
}
__device__ __forceinline__ void cp_commit() {
    asm volatile("cp.async.commit_group;" ::: "memory");
}
__device__ __forceinline__ void cp_wait0() {
    asm volatile("cp.async.wait_group 0;" ::: "memory");
}
__device__ __forceinline__ void cp_wait1() {
    asm volatile("cp.async.wait_group 1;" ::: "memory");
}
__device__ __forceinline__ void ldsm4(uint32_t* r, uint32_t addr) {
    asm volatile("ldmatrix.sync.aligned.m8n8.x4.shared.b16 {%0,%1,%2,%3}, [%4];"
                 : "=r"(r[0]), "=r"(r[1]), "=r"(r[2]), "=r"(r[3]) : "r"(addr));
}
__device__ __forceinline__ void ldsm2(uint32_t* r, uint32_t addr) {
    asm volatile("ldmatrix.sync.aligned.m8n8.x2.shared.b16 {%0,%1}, [%2];"
                 : "=r"(r[0]), "=r"(r[1]) : "r"(addr));
}
__device__ __forceinline__ void ldsm4t(uint32_t* r, uint32_t addr) {
    asm volatile("ldmatrix.sync.aligned.m8n8.x4.trans.shared.b16 {%0,%1,%2,%3}, [%4];"
                 : "=r"(r[0]), "=r"(r[1]), "=r"(r[2]), "=r"(r[3]) : "r"(addr));
}
__device__ __forceinline__ void mma16816(float* d, const uint32_t* a, const uint32_t* b) {
    asm volatile(
        "mma.sync.aligned.m16n8k16.row.col.f32.bf16.bf16.f32 "
        "{%0,%1,%2,%3}, {%4,%5,%6,%7}, {%8,%9}, {%0,%1,%2,%3};"
        : "+f"(d[0]), "+f"(d[1]), "+f"(d[2]), "+f"(d[3])
        : "r"(a[0]), "r"(a[1]), "r"(a[2]), "r"(a[3]), "r"(b[0]), "r"(b[1]));
}
__device__ __forceinline__ void mma16808(float* d, uint32_t a0, uint32_t a1, uint32_t b0) {
    asm volatile(
        "mma.sync.aligned.m16n8k8.row.col.f32.bf16.bf16.f32 "
        "{%0,%1,%2,%3}, {%4,%5}, {%6}, {%0,%1,%2,%3};"
        : "+f"(d[0]), "+f"(d[1]), "+f"(d[2]), "+f"(d[3])
        : "r"(a0), "r"(a1), "r"(b0));
}
__device__ __forceinline__ uint32_t pack_bf16x2(float lo, float hi) {
    uint32_t r;
    asm("cvt.rn.bf16x2.f32 %0, %1, %2;" : "=r"(r) : "f"(hi), "f"(lo));
    return r;
}
__device__ __forceinline__ uint32_t pack_hi(float a, float b, __nv_bfloat16& ha, __nv_bfloat16& hb) {
    ha = __float2bfloat16(a); hb = __float2bfloat16(b);
    return (uint32_t)__bfloat16_as_ushort(ha) | ((uint32_t)__bfloat16_as_ushort(hb) << 16);
}

// ================= fp32 -> bf16 hi/lo conversion ============================
__global__ __launch_bounds__(256) void conv_hilo(const float4* __restrict__ src,
                                                 uint2* __restrict__ h,
                                                 uint2* __restrict__ l, int n4) {
    int i = blockIdx.x * 256 + threadIdx.x;
    if (i >= n4) return;
    float4 v = src[i];
    __nv_bfloat16 h0, h1, h2, h3;
    uint32_t a = pack_hi(v.x, v.y, h0, h1);
    uint32_t b = pack_hi(v.z, v.w, h2, h3);
    uint2 hv, lv;
    hv.x = a; hv.y = b;
    lv.x = pack_bf16x2(v.x - __bfloat162float(h0), v.y - __bfloat162float(h1));
    lv.y = pack_bf16x2(v.z - __bfloat162float(h2), v.w - __bfloat162float(h3));
    h[i] = hv;
    l[i] = lv;
}

// ================= tensor-core GEMM via mma.sync (bf16x3, 2-stage) ==========
#define TSTRIDE 80
#define TILE_BYTES (128 * TSTRIDE)
#define BUF_BYTES  (4 * TILE_BYTES)
#define GEMM_SMEM  (2 * BUF_BYTES)    // 81920 -> 2 CTAs/SM

__global__ __launch_bounds__(256) void gemm_mma(const __nv_bfloat16* __restrict__ Ah,
                                                const __nv_bfloat16* __restrict__ Al,
                                                const __nv_bfloat16* __restrict__ Bh,
                                                const __nv_bfloat16* __restrict__ Bl,
                                                float* __restrict__ C,
                                                int mode) {
    extern __shared__ char sm[];
    const uint32_t sbase = smem_u32(sm);
    const int tid = threadIdx.x;
    const int lane = tid & 31, wid = tid >> 5;
    const int m0 = blockIdx.y * 128;
    const int n0 = blockIdx.x * 128;
    const int wm = (wid >> 2) * 64;
    const int wn = (wid & 3) * 32;

    const __nv_bfloat16* gsrc[4] = {Ah, Al, Bh, Bl};

    float acc[4][4][4];
#pragma unroll
    for (int i = 0; i < 4; i++)
#pragma unroll
        for (int j = 0; j < 4; j++)
#pragma unroll
            for (int k = 0; k < 4; k++) acc[i][j][k] = 0.f;

    const int arow = wm + (lane & 15);
    const int akc  = (lane >> 4) << 3;
    const int brow = wn + (lane & 7) + ((lane >> 4) << 3);
    const int bkc  = ((lane >> 3) & 1) << 3;

    auto issue = [&](int c, int buf) {
#pragma unroll
        for (int T = 0; T < 4; T++) {
            const __nv_bfloat16* src = gsrc[T];
            const int rb = (T < 2) ? m0 : n0;
#pragma unroll
            for (int i = 0; i < 2; i++) {
                int idx = i * 256 + tid;
                int row = idx >> 2;
                int u   = idx & 3;
                uint32_t sa = sbase + buf * BUF_BYTES + T * TILE_BYTES + row * TSTRIDE + u * 16;
                cp_async16(sa, src + (size_t)(rb + row) * 1024 + c * 32 + u * 8);
            }
        }
        cp_commit();
    };

    issue(0, 0);

    for (int c = 0; c < 32; c++) {
        const int buf = c & 1;
        cp_wait0();
        __syncthreads();
        if (c + 1 < 32) issue(c + 1, buf ^ 1);

        const uint32_t base = sbase + buf * BUF_BYTES;
#pragma unroll
        for (int ks = 0; ks < 2; ks++) {
            uint32_t ah[4][4], al[4][4], bh[2][4], bl[2][4];
#pragma unroll
            for (int mt = 0; mt < 4; mt++) {
                uint32_t aa = base + (arow + mt * 16) * TSTRIDE + (ks * 16 + akc) * 2;
                ldsm4(ah[mt], aa);
                ldsm4(al[mt], aa + TILE_BYTES);
            }
#pragma unroll
            for (int np = 0; np < 2; np++) {
                uint32_t ba = base + 2 * TILE_BYTES + (brow + np * 16) * TSTRIDE + (ks * 16 + bkc) * 2;
                ldsm4(bh[np], ba);
                ldsm4(bl[np], ba + TILE_BYTES);
            }
#pragma unroll
            for (int mt = 0; mt < 4; mt++)
#pragma unroll
                for (int nt = 0; nt < 4; nt++) {
                    const uint32_t* ph = &bh[nt >> 1][(nt & 1) * 2];
                    const uint32_t* pl = &bl[nt >> 1][(nt & 1) * 2];
                    mma16816(acc[mt][nt], ah[mt], ph);
                    mma16816(acc[mt][nt], al[mt], ph);
                    mma16816(acc[mt][nt], ah[mt], pl);
                }
        }
        __syncthreads();
    }

    const int g = lane >> 2, t4 = lane & 3;
#pragma unroll
    for (int mt = 0; mt < 4; mt++)
#pragma unroll
        for (int nt = 0; nt < 4; nt++) {
            int r = m0 + wm + mt * 16 + g;
            int cc = n0 + wn + nt * 8 + t4 * 2;
#pragma unroll
            for (int half = 0; half < 2; half++) {
                int rr = r + half * 8;
                float v0 = acc[mt][nt][half * 2], v1 = acc[mt][nt][half * 2 + 1];
                if (mode == 0) {
                    *(float2*)(C + (size_t)rr * 1024 + cc) = make_float2(v0, v1);
                } else {
                    __nv_bfloat16 b0, b1;
                    if (cc < 1024) {
                        *(float2*)(g_q + (size_t)rr * 1024 + cc) = make_float2(v0, v1);
                        uint32_t hh = pack_hi(v0, v1, b0, b1);
                        *(uint32_t*)(g_qh + (size_t)rr * 1024 + cc) = hh;
                        *(uint32_t*)(g_ql + (size_t)rr * 1024 + cc) =
                            pack_bf16x2(v0 - __bfloat162float(b0), v1 - __bfloat162float(b1));
                    } else if (cc < 1088) {
                        int k = cc - 1024;
                        *(float2*)(g_k + (size_t)rr * 64 + k) = make_float2(v0, v1);
                        uint32_t hh = pack_hi(v0, v1, b0, b1);
                        *(uint32_t*)(g_kh + (size_t)rr * 64 + k) = hh;
                        *(uint32_t*)(g_kl + (size_t)rr * 64 + k) =
                            pack_bf16x2(v0 - __bfloat162float(b0), v1 - __bfloat162float(b1));
                    } else if (cc < 1152) {
                        int k = cc - 1088;
                        *(float2*)(g_v + (size_t)rr * 64 + k) = make_float2(v0, v1);
                        uint32_t hh = pack_hi(v0, v1, b0, b1);
                        *(uint32_t*)(g_vh + (size_t)rr * 64 + k) = hh;
                        *(uint32_t*)(g_vl + (size_t)rr * 64 + k) =
                            pack_bf16x2(v0 - __bfloat162float(b0), v1 - __bfloat162float(b1));
                    } else if (cc < 1200) {
                        int k = cc - 1152;
                        *(float2*)(g_g + (size_t)rr * 48 + k) = make_float2(v0, v1);
                    }
                }
            }
        }
}

// ---------------- mean-pool K,V ---------------------------------------------
__global__ void pool_kv() {
    int c = blockIdx.x, d = threadIdx.x;
    float sk = 0.f, sv = 0.f;
    for (int i = 0; i < 64; i++) {
        sk += g_k[(size_t)(c * 64 + i) * 64 + d];
        sv += g_v[(size_t)(c * 64 + i) * 64 + d];
    }
    g_kc[c * 64 + d] = sk * (1.f / 64.f);
    g_vc[c * 64 + d] = sv * (1.f / 64.f);
}

// --------- compressed attention + top-k, 4 tokens per CTA (256 thr) ---------
__global__ __launch_bounds__(256) void cmp4() {
    __shared__ float sq  [4 * 1024];
    __shared__ float skc [NB * 64];
    __shared__ float svc [NB * 64];
    __shared__ float sp  [4 * NHEAD * NB];
    __shared__ float simp[4 * NB];

    const int T0 = blockIdx.x * 4, tid = threadIdx.x;

    for (int i = tid; i < 1024; i += 256) {
        int tok = i >> 8, e = i & 255;
        ((float4*)sq)[i] = ((const float4*)(g_q + (size_t)(T0 + tok) * 1024))[e];
    }
    for (int i = tid; i < 512; i += 256) {
        ((float4*)skc)[i] = ((const float4*)g_kc)[i];
        ((float4*)svc)[i] = ((const float4*)g_vc)[i];
    }
    __syncthreads();

    const float scale = 0.125f;

    for (int idx = tid; idx < 4 * NHEAD * NB; idx += 256) {
        int tok = idx >> 9, rem = idx & 511;
        int h = rem >> 5, c = rem & 31;
        int nvis = (T0 + tok + 1) >> 6;
        float s;
        if (c < nvis) {
            const float4* qa = (const float4*)(sq + tok * 1024 + h * 64);
            const float4* ka = (const float4*)(skc + c * 64);
            s = 0.f;
#pragma unroll
            for (int i = 0; i < 16; i++) {
                float4 x = qa[i], y = ka[i];
                s += x.x * y.x + x.y * y.y + x.z * y.z + x.w * y.w;
            }
            s *= scale;
        } else s = NEGV;
        sp[idx] = s;
    }
    __syncthreads();

    if (tid < 64) {
        int tok = tid >> 4;
        int nvis = (T0 + tok + 1) >> 6;
        float* row = sp + tok * 512 + (tid & 15) * 32;
        if (nvis == 0) {
            for (int c = 0; c < NB; c++) row[c] = 0.f;
        } else {
            float m = -INFINITY;
            for (int c = 0; c < nvis; c++) m = fmaxf(m, row[c]);
            float sum = 0.f;
            for (int c = 0; c < nvis; c++) { float e = __expf(row[c] - m); row[c] = e; sum += e; }
            float inv = 1.f / sum;
            for (int c = 0; c < nvis; c++) row[c] *= inv;
            for (int c = nvis; c < NB; c++) row[c] = 0.f;
        }
    }
    __syncthreads();

    for (int idx = tid; idx < 4 * NHEAD * HDIM; idx += 256) {
        int tok = idx >> 10, rem = idx & 1023;
        int h = rem >> 6, d = rem & 63;
        int nvis = (T0 + tok + 1) >> 6;
        float o = 0.f;
        for (int c = 0; c < nvis; c++) o += sp[tok * 512 + h * NB + c] * svc[c * 64 + d];
        g_ocmp[(size_t)(T0 + tok) * 1024 + rem] = o;
    }

    if (tid < 128) {
        int tok = tid >> 5, c = tid & 31;
        int cur = (T0 + tok) >> 6;
        float im;
        if (c == 0 || c == cur) im = INFINITY;
        else if (c <= cur) {
            im = 0.f;
            for (int h = 0; h < NHEAD; h++) im += sp[tok * 512 + h * NB + c];
        } else im = NEGV;
        simp[tok * 32 + c] = im;
    }
    __syncthreads();

    const int w = tid >> 5, lane = tid & 31;
    if (w < 4) {
        float v = simp[w * 32 + lane];
#pragma unroll
        for (int s = 0; s < SSEL; s++) {
            float bv = v; int bi = lane;
#pragma unroll
            for (int off = 16; off >= 1; off >>= 1) {
                float ov = __shfl_xor_sync(0xffffffffu, bv, off);
                int   oi = __shfl_xor_sync(0xffffffffu, bi, off);
                if (ov > bv || (ov == bv && oi < bi)) { bv = ov; bi = oi; }
            }
            if (lane == 0) g_blk[(T0 + w) * SSEL + s] = bi;
            if (lane == bi) v = -INFINITY;
        }
    }
}

// ====== union-block selected attention, 16 tokens/CTA, 1 token/warp, 2-stage
// 512 threads. smem: Qh 256x144 | Ql | 2 KV stages | meta.
#define SQL_OFF   36864
#define STG_OFF   73728
#define STG_SZ    36864
#define KV_T      9216
#define META_OFF  147456
#define SLC16_SMEM (147456 + 256)

__global__ __launch_bounds__(512, 1) void slc16() {
    extern __shared__ char smc[];
    const uint32_t sb0 = smem_u32(smc);
    const int tid = threadIdx.x;
    const int lane = tid & 31, w = tid >> 5;   // w = 0..15, one token per warp
    const int T0 = blockIdx.x * 16;
    const int tt = T0 + w;

    uint32_t* smask = (uint32_t*)(smc + META_OFF);
    int* ulist = (int*)(smc + META_OFF + 64);
    int* ucnt  = (int*)(smc + META_OFF + 192);

    // ---- stage Q hi/lo (row = token*16+head) ----
#pragma unroll
    for (int i = 0; i < 8; i++) {
        int idx = i * 512 + tid;                 // 0..4095
        int tile = idx >> 11;                    // 0 = hi, 1 = lo
        int row = (idx >> 3) & 255, u = idx & 7;
        int token = T0 + (row >> 4), head = row & 15;
        size_t go = (size_t)token * 1024 + head * 64 + u * 8;
        cp_async16(sb0 + tile * SQL_OFF + row * 144 + u * 16, (tile ? g_ql : g_qh) + go);
    }
    cp_commit();

    // ---- per-token selection masks + union list ----
    if (tid < 16) {
        uint32_t m = 0;
        for (int s = 0; s < SSEL; s++) m |= 1u << g_blk[(T0 + tid) * SSEL + s];
        smask[tid] = m;
    }
    __syncthreads();
    if (tid == 0) {
        uint32_t u = 0;
        for (int i = 0; i < 16; i++) u |= smask[i];
        int cnt = 0;
        for (int c = 0; c < NB; c++)
            if ((u >> c) & 1u) ulist[cnt++] = c;
        *ucnt = cnt;
    }
    __syncthreads();
    const int nu = *ucnt;

    auto issueKV = [&](int c, int stage) {
        uint32_t base = sb0 + STG_OFF + stage * STG_SZ;
#pragma unroll
        for (int i = 0; i < 4; i++) {
            int cid = i * 512 + tid;             // 0..2047
            int tile = cid >> 9, r = (cid >> 3) & 63, u = cid & 7;
            const __nv_bfloat16* gp = (tile == 0) ? g_kh : (tile == 1) ? g_kl
                                    : (tile == 2) ? g_vh : g_vl;
            cp_async16(base + tile * KV_T + r * 144 + u * 16,
                       gp + (size_t)(c * 64 + r) * 64 + u * 8);
        }
        cp_commit();
    };

    issueKV(ulist[0], 0);
    cp_wait1();        // Q group complete (KV stage 0 may still be in flight)
    __syncthreads();

    const uint32_t msk = smask[w];

    float ov[8][4];
#pragma unroll
    for (int vt = 0; vt < 8; vt++)
#pragma unroll
        for (int j = 0; j < 4; j++) ov[vt][j] = 0.f;
    float mrow[2] = {NEGS, NEGS};
    float srow[2] = {0.f, 0.f};

    for (int i = 0; i < nu; i++) {
        cp_wait0();
        __syncthreads();
        if (i + 1 < nu) issueKV(ulist[i + 1], (i + 1) & 1);

        const int c = ulist[i];
        if ((msk >> c) & 1u) {
            const uint32_t base = sb0 + STG_OFF + (i & 1) * STG_SZ;

            // ---- QK (bf16x3): D[8 ntiles][4] ----
            float d[8][4];
#pragma unroll
            for (int nt = 0; nt < 8; nt++)
#pragma unroll
                for (int j = 0; j < 4; j++) d[nt][j] = 0.f;

#pragma unroll
            for (int ks = 0; ks < 4; ks++) {
                uint32_t qa = sb0 + (w * 16 + (lane & 15)) * 144 + ((lane >> 4) << 4) + ks * 32;
                uint32_t qh4[4], ql4[4];
                ldsm4(qh4, qa);
                ldsm4(ql4, qa + SQL_OFF);
#pragma unroll
                for (int nt = 0; nt < 8; nt++) {
                    uint32_t bh2[2], bl2[2];
                    uint32_t ba = base + (nt * 8 + (lane & 7)) * 144 + ((lane >> 3) & 1) * 16 + ks * 32;
                    ldsm2(bh2, ba);
                    ldsm2(bl2, ba + KV_T);
                    mma16816(d[nt], qh4, bh2);
                    mma16816(d[nt], ql4, bh2);
                    mma16816(d[nt], qh4, bl2);
                }
            }

            // ---- scale + causal mask + online max/rescale ----
            const int colb = c * 64 + ((lane & 3) << 1);
            float bm0 = NEGS, bm1 = NEGS;
#pragma unroll
            for (int nt = 0; nt < 8; nt++) {
                int tok0 = colb + nt * 8;
                bool v0 = tok0 <= tt, v1 = tok0 + 1 <= tt;
                d[nt][0] = v0 ? d[nt][0] * 0.125f : NEGS;
                d[nt][1] = v1 ? d[nt][1] * 0.125f : NEGS;
                d[nt][2] = v0 ? d[nt][2] * 0.125f : NEGS;
                d[nt][3] = v1 ? d[nt][3] * 0.125f : NEGS;
                bm0 = fmaxf(bm0, fmaxf(d[nt][0], d[nt][1]));
                bm1 = fmaxf(bm1, fmaxf(d[nt][2], d[nt][3]));
            }
            bm0 = fmaxf(bm0, __shfl_xor_sync(0xffffffffu, bm0, 1));
            bm0 = fmaxf(bm0, __shfl_xor_sync(0xffffffffu, bm0, 2));
            bm1 = fmaxf(bm1, __shfl_xor_sync(0xffffffffu, bm1, 1));
            bm1 = fmaxf(bm1, __shfl_xor_sync(0xffffffffu, bm1, 2));
            float mn0 = fmaxf(mrow[0], bm0), mn1 = fmaxf(mrow[1], bm1);
            float a0 = __expf(mrow[0] - mn0), a1 = __expf(mrow[1] - mn1);
            mrow[0] = mn0; mrow[1] = mn1;
            srow[0] *= a0; srow[1] *= a1;
#pragma unroll
            for (int vt = 0; vt < 8; vt++) {
                ov[vt][0] *= a0; ov[vt][1] *= a0;
                ov[vt][2] *= a1; ov[vt][3] *= a1;
            }

            // ---- exp + PV (bf16x3) ----
#pragma unroll
            for (int nt = 0; nt < 8; nt++) {
                uint32_t vh8[8], vl8[8];
                uint32_t va = base + 2 * KV_T + (nt * 8 + (lane & 7)) * 144 + (lane >> 3) * 16;
                ldsm4t(vh8, va);        ldsm4t(vh8 + 4, va + 64);
                ldsm4t(vl8, va + KV_T); ldsm4t(vl8 + 4, va + KV_T + 64);
                float p0 = __expf(d[nt][0] - mrow[0]);
                float p1 = __expf(d[nt][1] - mrow[0]);
                float p2 = __expf(d[nt][2] - mrow[1]);
                float p3 = __expf(d[nt][3] - mrow[1]);
                srow[0] += p0 + p1;
                srow[1] += p2 + p3;
                __nv_bfloat16 b0, b1, b2, b3;
                uint32_t ah0 = pack_hi(p0, p1, b0, b1);
                uint32_t ah1 = pack_hi(p2, p3, b2, b3);
                uint32_t al0 = pack_bf16x2(p0 - __bfloat162float(b0), p1 - __bfloat162float(b1));
                uint32_t al1 = pack_bf16x2(p2 - __bfloat162float(b2), p3 - __bfloat162float(b3));
#pragma unroll
                for (int vt = 0; vt < 8; vt++) {
                    mma16808(ov[vt], ah0, ah1, vh8[vt]);
                    mma16808(ov[vt], al0, al1, vh8[vt]);
                    mma16808(ov[vt], ah0, ah1, vl8[vt]);
                }
            }
        }
        __syncthreads();
    }

    // ---- epilogue: quad-reduce sums, normalize, gate, add ocmp, emit hi/lo ----
#pragma unroll
    for (int half = 0; half < 2; half++) {
        float s = srow[half];
        s += __shfl_xor_sync(0xffffffffu, s, 1);
        s += __shfl_xor_sync(0xffffffffu, s, 2);
        float inv = 1.f / s;
        int h = (lane >> 2) + half * 8;
        float gc = 1.f / (1.f + __expf(-g_g[tt * 48 + h * 3]));
        float gs = 1.f / (1.f + __expf(-g_g[tt * 48 + h * 3 + 1]));
#pragma unroll
        for (int vt = 0; vt < 8; vt++) {
            int col = vt * 8 + ((lane & 3) << 1);
            size_t off = (size_t)tt * 1024 + h * 64 + col;
            float2 oc = *(const float2*)(g_ocmp + off);
            float c0 = ov[vt][half * 2]     * inv * gs + oc.x * gc;
            float c1 = ov[vt][half * 2 + 1] * inv * gs + oc.y * gc;
            __nv_bfloat16 b0, b1;
            *(uint32_t*)(g_ch + off) = pack_hi(c0, c1, b0, b1);
            *(uint32_t*)(g_cl + off) =
                pack_bf16x2(c0 - __bfloat162float(b0), c1 - __bfloat162float(b1));
        }
    }
}

// ---------------- launch ----------------------------------------------------
extern "C" void kernel_launch(void* const* d_in, const int* in_sizes, int n_in,
                              void* d_out, int out_size) {
    const float* x  = (const float*)d_in[0];
    const float* Wq = (const float*)d_in[1];
    const float* Wk = (const float*)d_in[2];
    const float* Wv = (const float*)d_in[3];
    const float* Wg = (const float*)d_in[4];
    const float* Wo = (const float*)d_in[5];
    float* out = (float*)d_out;

    void *pq, *pxh, *pxl, *pch, *pcl, *pwch, *pwcl, *pwoh, *pwol;
    cudaGetSymbolAddress(&pq, g_q);
    cudaGetSymbolAddress(&pxh, g_xh);   cudaGetSymbolAddress(&pxl, g_xl);
    cudaGetSymbolAddress(&pch, g_ch);   cudaGetSymbolAddress(&pcl, g_cl);
    cudaGetSymbolAddress(&pwch, g_wch); cudaGetSymbolAddress(&pwcl, g_wcl);
    cudaGetSymbolAddress(&pwoh, g_woh); cudaGetSymbolAddress(&pwol, g_wol);

    __nv_bfloat16* wch = (__nv_bfloat16*)pwch;
    __nv_bfloat16* wcl = (__nv_bfloat16*)pwcl;

    cudaFuncSetAttribute(gemm_mma, cudaFuncAttributeMaxDynamicSharedMemorySize, GEMM_SMEM);
    cudaFuncSetAttribute(slc16, cudaFuncAttributeMaxDynamicSharedMemorySize, SLC16_SMEM);

    // conversions
    conv_hilo<<<2048, 256>>>((const float4*)x, (uint2*)pxh, (uint2*)pxl, 524288);
    conv_hilo<<<1024, 256>>>((const float4*)Wq, (uint2*)wch, (uint2*)wcl, 262144);
    conv_hilo<<<64, 256>>>((const float4*)Wk, (uint2*)(wch + 1024 * 1024), (uint2*)(wcl + 1024 * 1024), 16384);
    conv_hilo<<<64, 256>>>((const float4*)Wv, (uint2*)(wch + 1088 * 1024), (uint2*)(wcl + 1088 * 1024), 16384);
    conv_hilo<<<48, 256>>>((const float4*)Wg, (uint2*)(wch + 1152 * 1024), (uint2*)(wcl + 1152 * 1024), 12288);
    cudaMemsetAsync(wch + 1200 * 1024, 0, 80 * 1024 * 2);
    cudaMemsetAsync(wcl + 1200 * 1024, 0, 80 * 1024 * 2);
    conv_hilo<<<1024, 256>>>((const float4*)Wo, (uint2*)pwoh, (uint2*)pwol, 262144);

    // fused projections: [Q | K | V | G] = x @ [Wq;Wk;Wv;Wg]^T
    gemm_mma<<<dim3(10, 16), 256, GEMM_SMEM>>>((const __nv_bfloat16*)pxh, (const __nv_bfloat16*)pxl,
                                               wch, wcl, (float*)pq, 1);
    pool_kv<<<NB, 64>>>();
    cmp4<<<T_LEN / 4, 256>>>();
    slc16<<<T_LEN / 16, 512, SLC16_SMEM>>>();

    // out = comb @ Wo^T
    gemm_mma<<<dim3(8, 16), 256, GEMM_SMEM>>>((const __nv_bfloat16*)pch, (const __nv_bfloat16*)pcl,
                                              (const __nv_bfloat16*)pwoh, (const __nv_bfloat16*)pwol,
                                              out, 0);
}

// round 10
// speedup vs baseline: 1.2425x; 1.2276x over previous
#include <cuda_runtime.h>
#include <cuda_bf16.h>
#include <cstdint>

// ---------------- problem constants ----------------
#define T_LEN 2048
#define DM    1024
#define NHEAD 16
#define HDIM  64
#define NB    32
#define SSEL  16
#define NEGV  (-1e30f)
#define NEGS  (-1.25e29f)

// ---------------- scratch ----------------------------------------------------
__device__ float g_q   [T_LEN * DM];
__device__ float g_k   [T_LEN * HDIM];
__device__ float g_v   [T_LEN * HDIM];
__device__ float g_g   [T_LEN * 48];

__device__ __nv_bfloat16 g_xh [T_LEN * DM], g_xl [T_LEN * DM];
__device__ __nv_bfloat16 g_qh [T_LEN * DM], g_ql [T_LEN * DM];
__device__ __nv_bfloat16 g_ch [T_LEN * DM], g_cl [T_LEN * DM];
__device__ __nv_bfloat16 g_kh [T_LEN * HDIM], g_kl [T_LEN * HDIM];
__device__ __nv_bfloat16 g_vh [T_LEN * HDIM], g_vl [T_LEN * HDIM];
__device__ __nv_bfloat16 g_kch[NB * HDIM], g_kcl[NB * HDIM];
__device__ __nv_bfloat16 g_vch[NB * HDIM], g_vcl[NB * HDIM];
__device__ __nv_bfloat16 g_wch[1280 * DM], g_wcl[1280 * DM];   // stacked Wq|Wk|Wv|Wg|pad
__device__ __nv_bfloat16 g_woh[DM * DM],   g_wol[DM * DM];

// ================= helpers ==================================================
__device__ __forceinline__ uint32_t smem_u32(const void* p) {
    uint32_t a;
    asm("{ .reg .u64 t; cvta.to.shared.u64 t, %1; cvt.u32.u64 %0, t; }"
        : "=r"(a) : "l"(p));
    return a;
}
__device__ __forceinline__ void cp_async16(uint32_t saddr, const void* gaddr) {
    asm volatile("cp.async.cg.shared.global [%0], [%1], 16;"
                 :: "r"(saddr), "l"(gaddr));
}
__device__ __forceinline__ void cp_commit() {
    asm volatile("cp.async.commit_group;" ::: "memory");
}
__device__ __forceinline__ void cp_wait0() {
    asm volatile("cp.async.wait_group 0;" ::: "memory");
}
__device__ __forceinline__ void cp_wait1() {
    asm volatile("cp.async.wait_group 1;" ::: "memory");
}
__device__ __forceinline__ void ldsm4(uint32_t* r, uint32_t addr) {
    asm volatile("ldmatrix.sync.aligned.m8n8.x4.shared.b16 {%0,%1,%2,%3}, [%4];"
                 : "=r"(r[0]), "=r"(r[1]), "=r"(r[2]), "=r"(r[3]) : "r"(addr));
}
__device__ __forceinline__ void ldsm2(uint32_t* r, uint32_t addr) {
    asm volatile("ldmatrix.sync.aligned.m8n8.x2.shared.b16 {%0,%1}, [%2];"
                 : "=r"(r[0]), "=r"(r[1]) : "r"(addr));
}
__device__ __forceinline__ void ldsm4t(uint32_t* r, uint32_t addr) {
    asm volatile("ldmatrix.sync.aligned.m8n8.x4.trans.shared.b16 {%0,%1,%2,%3}, [%4];"
                 : "=r"(r[0]), "=r"(r[1]), "=r"(r[2]), "=r"(r[3]) : "r"(addr));
}
__device__ __forceinline__ void mma16816(float* d, const uint32_t* a, const uint32_t* b) {
    asm volatile(
        "mma.sync.aligned.m16n8k16.row.col.f32.bf16.bf16.f32 "
        "{%0,%1,%2,%3}, {%4,%5,%6,%7}, {%8,%9}, {%0,%1,%2,%3};"
        : "+f"(d[0]), "+f"(d[1]), "+f"(d[2]), "+f"(d[3])
        : "r"(a[0]), "r"(a[1]), "r"(a[2]), "r"(a[3]), "r"(b[0]), "r"(b[1]));
}
__device__ __forceinline__ void mma16808(float* d, uint32_t a0, uint32_t a1, uint32_t b0) {
    asm volatile(
        "mma.sync.aligned.m16n8k8.row.col.f32.bf16.bf16.f32 "
        "{%0,%1,%2,%3}, {%4,%5}, {%6}, {%0,%1,%2,%3};"
        : "+f"(d[0]), "+f"(d[1]), "+f"(d[2]), "+f"(d[3])
        : "r"(a0), "r"(a1), "r"(b0));
}
__device__ __forceinline__ uint32_t pack_bf16x2(float lo, float hi) {
    uint32_t r;
    asm("cvt.rn.bf16x2.f32 %0, %1, %2;" : "=r"(r) : "f"(hi), "f"(lo));
    return r;
}
__device__ __forceinline__ uint32_t pack_hi(float a, float b, __nv_bfloat16& ha, __nv_bfloat16& hb) {
    ha = __float2bfloat16(a); hb = __float2bfloat16(b);
    return (uint32_t)__bfloat16_as_ushort(ha) | ((uint32_t)__bfloat16_as_ushort(hb) << 16);
}

// ================= fp32 -> bf16 hi/lo conversion ============================
__global__ __launch_bounds__(256) void conv_hilo(const float4* __restrict__ src,
                                                 uint2* __restrict__ h,
                                                 uint2* __restrict__ l, int n4) {
    int i = blockIdx.x * 256 + threadIdx.x;
    if (i >= n4) return;
    float4 v = src[i];
    __nv_bfloat16 h0, h1, h2, h3;
    uint32_t a = pack_hi(v.x, v.y, h0, h1);
    uint32_t b = pack_hi(v.z, v.w, h2, h3);
    uint2 hv, lv;
    hv.x = a; hv.y = b;
    lv.x = pack_bf16x2(v.x - __bfloat162float(h0), v.y - __bfloat162float(h1));
    lv.y = pack_bf16x2(v.z - __bfloat162float(h2), v.w - __bfloat162float(h3));
    h[i] = hv;
    l[i] = lv;
}

// ================= tensor-core GEMM via mma.sync (bf16x3, 2-stage) ==========
#define TSTRIDE 80
#define TILE_BYTES (128 * TSTRIDE)
#define BUF_BYTES  (4 * TILE_BYTES)
#define GEMM_SMEM  (2 * BUF_BYTES)    // 81920; with <=128 regs -> 2 CTAs/SM

__global__ __launch_bounds__(256, 2) void gemm_mma(const __nv_bfloat16* __restrict__ Ah,
                                                   const __nv_bfloat16* __restrict__ Al,
                                                   const __nv_bfloat16* __restrict__ Bh,
                                                   const __nv_bfloat16* __restrict__ Bl,
                                                   float* __restrict__ C,
                                                   int mode) {
    extern __shared__ char sm[];
    const uint32_t sbase = smem_u32(sm);
    const int tid = threadIdx.x;
    const int lane = tid & 31, wid = tid >> 5;
    const int m0 = blockIdx.y * 128;
    const int n0 = blockIdx.x * 128;
    const int wm = (wid >> 2) * 64;
    const int wn = (wid & 3) * 32;

    const __nv_bfloat16* gsrc[4] = {Ah, Al, Bh, Bl};

    float acc[4][4][4];
#pragma unroll
    for (int i = 0; i < 4; i++)
#pragma unroll
        for (int j = 0; j < 4; j++)
#pragma unroll
            for (int k = 0; k < 4; k++) acc[i][j][k] = 0.f;

    const int arow = wm + (lane & 15);
    const int akc  = (lane >> 4) << 3;
    const int brow = wn + (lane & 7) + ((lane >> 4) << 3);
    const int bkc  = ((lane >> 3) & 1) << 3;

    auto issue = [&](int c, int buf) {
#pragma unroll
        for (int T = 0; T < 4; T++) {
            const __nv_bfloat16* src = gsrc[T];
            const int rb = (T < 2) ? m0 : n0;
#pragma unroll
            for (int i = 0; i < 2; i++) {
                int idx = i * 256 + tid;
                int row = idx >> 2;
                int u   = idx & 3;
                uint32_t sa = sbase + buf * BUF_BYTES + T * TILE_BYTES + row * TSTRIDE + u * 16;
                cp_async16(sa, src + (size_t)(rb + row) * 1024 + c * 32 + u * 8);
            }
        }
        cp_commit();
    };

    issue(0, 0);

    for (int c = 0; c < 32; c++) {
        const int buf = c & 1;
        cp_wait0();
        __syncthreads();
        if (c + 1 < 32) issue(c + 1, buf ^ 1);

        const uint32_t base = sbase + buf * BUF_BYTES;
#pragma unroll
        for (int ks = 0; ks < 2; ks++) {
            uint32_t ah[4][4], al[4][4], bh[2][4], bl[2][4];
#pragma unroll
            for (int mt = 0; mt < 4; mt++) {
                uint32_t aa = base + (arow + mt * 16) * TSTRIDE + (ks * 16 + akc) * 2;
                ldsm4(ah[mt], aa);
                ldsm4(al[mt], aa + TILE_BYTES);
            }
#pragma unroll
            for (int np = 0; np < 2; np++) {
                uint32_t ba = base + 2 * TILE_BYTES + (brow + np * 16) * TSTRIDE + (ks * 16 + bkc) * 2;
                ldsm4(bh[np], ba);
                ldsm4(bl[np], ba + TILE_BYTES);
            }
#pragma unroll
            for (int mt = 0; mt < 4; mt++)
#pragma unroll
                for (int nt = 0; nt < 4; nt++) {
                    const uint32_t* ph = &bh[nt >> 1][(nt & 1) * 2];
                    const uint32_t* pl = &bl[nt >> 1][(nt & 1) * 2];
                    mma16816(acc[mt][nt], ah[mt], ph);
                    mma16816(acc[mt][nt], al[mt], ph);
                    mma16816(acc[mt][nt], ah[mt], pl);
                }
        }
        __syncthreads();
    }

    const int g = lane >> 2, t4 = lane & 3;
#pragma unroll
    for (int mt = 0; mt < 4; mt++)
#pragma unroll
        for (int nt = 0; nt < 4; nt++) {
            int r = m0 + wm + mt * 16 + g;
            int cc = n0 + wn + nt * 8 + t4 * 2;
#pragma unroll
            for (int half = 0; half < 2; half++) {
                int rr = r + half * 8;
                float v0 = acc[mt][nt][half * 2], v1 = acc[mt][nt][half * 2 + 1];
                if (mode == 0) {
                    *(float2*)(C + (size_t)rr * 1024 + cc) = make_float2(v0, v1);
                } else {
                    __nv_bfloat16 b0, b1;
                    if (cc < 1024) {
                        *(float2*)(g_q + (size_t)rr * 1024 + cc) = make_float2(v0, v1);
                        uint32_t hh = pack_hi(v0, v1, b0, b1);
                        *(uint32_t*)(g_qh + (size_t)rr * 1024 + cc) = hh;
                        *(uint32_t*)(g_ql + (size_t)rr * 1024 + cc) =
                            pack_bf16x2(v0 - __bfloat162float(b0), v1 - __bfloat162float(b1));
                    } else if (cc < 1088) {
                        int k = cc - 1024;
                        *(float2*)(g_k + (size_t)rr * 64 + k) = make_float2(v0, v1);
                        uint32_t hh = pack_hi(v0, v1, b0, b1);
                        *(uint32_t*)(g_kh + (size_t)rr * 64 + k) = hh;
                        *(uint32_t*)(g_kl + (size_t)rr * 64 + k) =
                            pack_bf16x2(v0 - __bfloat162float(b0), v1 - __bfloat162float(b1));
                    } else if (cc < 1152) {
                        int k = cc - 1088;
                        *(float2*)(g_v + (size_t)rr * 64 + k) = make_float2(v0, v1);
                        uint32_t hh = pack_hi(v0, v1, b0, b1);
                        *(uint32_t*)(g_vh + (size_t)rr * 64 + k) = hh;
                        *(uint32_t*)(g_vl + (size_t)rr * 64 + k) =
                            pack_bf16x2(v0 - __bfloat162float(b0), v1 - __bfloat162float(b1));
                    } else if (cc < 1200) {
                        int k = cc - 1152;
                        *(float2*)(g_g + (size_t)rr * 48 + k) = make_float2(v0, v1);
                    }
                }
            }
        }
}

// ---------------- mean-pool K,V (fp32 + bf16 hi/lo) -------------------------
__global__ void pool_kv() {
    int c = blockIdx.x, d = threadIdx.x;
    float sk = 0.f, sv = 0.f;
    for (int i = 0; i < 64; i++) {
        sk += g_k[(size_t)(c * 64 + i) * 64 + d];
        sv += g_v[(size_t)(c * 64 + i) * 64 + d];
    }
    sk *= (1.f / 64.f); sv *= (1.f / 64.f);
    int idx = c * 64 + d;
    __nv_bfloat16 hk = __float2bfloat16(sk);
    __nv_bfloat16 hv2 = __float2bfloat16(sv);
    g_kch[idx] = hk; g_kcl[idx] = __float2bfloat16(sk - __bfloat162float(hk));
    g_vch[idx] = hv2; g_vcl[idx] = __float2bfloat16(sv - __bfloat162float(hv2));
}

// ====== FUSED: compressed attention + top-k + union selected attention ======
// 16 tokens/CTA, 512 threads (1 token/warp), 2-stage KV pipeline.
// smem: Qh 256x144 | Ql | Kc/Kcl/Vc/Vcl (4x 32x144) | 2 KV stages | meta+imp
#define SQL_OFF   36864
#define KC_OFF    73728
#define KCL_OFF   (KC_OFF + 4608)
#define VCH_OFF   (KC_OFF + 9216)
#define VCL_OFF   (KC_OFF + 13824)
#define STG_OFF   92160
#define STG_SZ    36864
#define KV_T      9216
#define META_OFF  165888
#define IMP_OFF   (META_OFF + 256)
#define SLC16_SMEM (META_OFF + 256 + 2048)   // 168192

__global__ __launch_bounds__(512, 1) void slc16() {
    extern __shared__ char smc[];
    const uint32_t sb0 = smem_u32(smc);
    const int tid = threadIdx.x;
    const int lane = tid & 31, w = tid >> 5;   // one token per warp
    const int T0 = blockIdx.x * 16;
    const int tt = T0 + w;

    uint32_t* smask = (uint32_t*)(smc + META_OFF);
    int* ulist = (int*)(smc + META_OFF + 128);
    int* ucnt  = (int*)(smc + META_OFF + 124);
    float* impsm = (float*)(smc + IMP_OFF);

    // ---- stage Q hi/lo + pooled Kc/Vc hi/lo (group A) ----
#pragma unroll
    for (int i = 0; i < 8; i++) {
        int idx = i * 512 + tid;                 // 0..4095
        int tile = idx >> 11;
        int row = (idx >> 3) & 255, u = idx & 7;
        int token = T0 + (row >> 4), head = row & 15;
        size_t go = (size_t)token * 1024 + head * 64 + u * 8;
        cp_async16(sb0 + tile * SQL_OFF + row * 144 + u * 16, (tile ? g_ql : g_qh) + go);
    }
#pragma unroll
    for (int i = 0; i < 2; i++) {
        int idx = i * 512 + tid;                 // 0..1023
        int tile = idx >> 8, r = (idx >> 3) & 31, u = idx & 7;
        const __nv_bfloat16* gp = (tile == 0) ? g_kch : (tile == 1) ? g_kcl
                                : (tile == 2) ? g_vch : g_vcl;
        cp_async16(sb0 + KC_OFF + tile * 4608 + r * 144 + u * 16, gp + r * 64 + u * 8);
    }
    cp_commit();

    auto issueKV = [&](int c, int stage) {
        uint32_t base = sb0 + STG_OFF + stage * STG_SZ;
#pragma unroll
        for (int i = 0; i < 4; i++) {
            int cid = i * 512 + tid;
            int tile = cid >> 9, r = (cid >> 3) & 63, u = cid & 7;
            const __nv_bfloat16* gp = (tile == 0) ? g_kh : (tile == 1) ? g_kl
                                    : (tile == 2) ? g_vh : g_vl;
            cp_async16(base + tile * KV_T + r * 144 + u * 16,
                       gp + (size_t)(c * 64 + r) * 64 + u * 8);
        }
        cp_commit();
    };

    // block 0 is always selected (forced) -> ulist[0] == 0; pre-issue it (group B)
    issueKV(0, 0);
    cp_wait1();          // group A (Q + Kc/Vc) complete; KV0 may be in flight
    __syncthreads();

    const int nvis = (tt + 1) >> 6;
    const int cur = tt >> 6;

    // =========== compressed branch: QK over pooled Kc (bf16x3) ===========
    float d4[4][4];
#pragma unroll
    for (int nt = 0; nt < 4; nt++)
#pragma unroll
        for (int j = 0; j < 4; j++) d4[nt][j] = 0.f;

#pragma unroll
    for (int ks = 0; ks < 4; ks++) {
        uint32_t qa = sb0 + (w * 16 + (lane & 15)) * 144 + ((lane >> 4) << 4) + ks * 32;
        uint32_t qh4[4], ql4[4];
        ldsm4(qh4, qa);
        ldsm4(ql4, qa + SQL_OFF);
#pragma unroll
        for (int nt = 0; nt < 4; nt++) {
            uint32_t bh2[2], bl2[2];
            uint32_t ba = sb0 + KC_OFF + (nt * 8 + (lane & 7)) * 144 + ((lane >> 3) & 1) * 16 + ks * 32;
            ldsm2(bh2, ba);
            ldsm2(bl2, ba + 4608);
            mma16816(d4[nt], qh4, bh2);
            mma16816(d4[nt], ql4, bh2);
            mma16816(d4[nt], qh4, bl2);
        }
    }

    // mask (block visibility) + softmax over 32 blocks
    float bm0 = NEGS, bm1 = NEGS;
#pragma unroll
    for (int nt = 0; nt < 4; nt++) {
        int c0 = nt * 8 + ((lane & 3) << 1);
        bool v0 = c0 < nvis, v1 = c0 + 1 < nvis;
        d4[nt][0] = v0 ? d4[nt][0] * 0.125f : NEGS;
        d4[nt][1] = v1 ? d4[nt][1] * 0.125f : NEGS;
        d4[nt][2] = v0 ? d4[nt][2] * 0.125f : NEGS;
        d4[nt][3] = v1 ? d4[nt][3] * 0.125f : NEGS;
        bm0 = fmaxf(bm0, fmaxf(d4[nt][0], d4[nt][1]));
        bm1 = fmaxf(bm1, fmaxf(d4[nt][2], d4[nt][3]));
    }
    bm0 = fmaxf(bm0, __shfl_xor_sync(0xffffffffu, bm0, 1));
    bm0 = fmaxf(bm0, __shfl_xor_sync(0xffffffffu, bm0, 2));
    bm1 = fmaxf(bm1, __shfl_xor_sync(0xffffffffu, bm1, 1));
    bm1 = fmaxf(bm1, __shfl_xor_sync(0xffffffffu, bm1, 2));

    float ps0 = 0.f, ps1 = 0.f;
#pragma unroll
    for (int nt = 0; nt < 4; nt++) {
        d4[nt][0] = __expf(d4[nt][0] - bm0);
        d4[nt][1] = __expf(d4[nt][1] - bm0);
        d4[nt][2] = __expf(d4[nt][2] - bm1);
        d4[nt][3] = __expf(d4[nt][3] - bm1);
        ps0 += d4[nt][0] + d4[nt][1];
        ps1 += d4[nt][2] + d4[nt][3];
    }
    ps0 += __shfl_xor_sync(0xffffffffu, ps0, 1);
    ps0 += __shfl_xor_sync(0xffffffffu, ps0, 2);
    ps1 += __shfl_xor_sync(0xffffffffu, ps1, 1);
    ps1 += __shfl_xor_sync(0xffffffffu, ps1, 2);
    float iv0 = (nvis > 0) ? 1.f / ps0 : 0.f;
    float iv1 = (nvis > 0) ? 1.f / ps1 : 0.f;
#pragma unroll
    for (int nt = 0; nt < 4; nt++) {
        d4[nt][0] *= iv0; d4[nt][1] *= iv0;
        d4[nt][2] *= iv1; d4[nt][3] *= iv1;
    }

    // importance = sum over 16 heads of normalized p, per block
#pragma unroll
    for (int nt = 0; nt < 4; nt++) {
        float t0 = d4[nt][0] + d4[nt][2];
        float t1 = d4[nt][1] + d4[nt][3];
        t0 += __shfl_xor_sync(0xffffffffu, t0, 4);
        t0 += __shfl_xor_sync(0xffffffffu, t0, 8);
        t0 += __shfl_xor_sync(0xffffffffu, t0, 16);
        t1 += __shfl_xor_sync(0xffffffffu, t1, 4);
        t1 += __shfl_xor_sync(0xffffffffu, t1, 8);
        t1 += __shfl_xor_sync(0xffffffffu, t1, 16);
        int c0 = nt * 8 + ((lane & 3) << 1);
        impsm[w * 32 + c0] = t0;
        impsm[w * 32 + c0 + 1] = t1;
    }
    __syncwarp();

    // stable top-16 (desc, lowest index on tie) -> selection bitmask
    uint32_t mymsk = 0;
    {
        float base = impsm[w * 32 + lane];
        float v = (lane == 0 || lane == cur) ? INFINITY
                : (lane > cur ? NEGV : base);
#pragma unroll
        for (int s = 0; s < SSEL; s++) {
            float bv = v; int bi = lane;
#pragma unroll
            for (int off = 16; off >= 1; off >>= 1) {
                float ov2 = __shfl_xor_sync(0xffffffffu, bv, off);
                int   oi = __shfl_xor_sync(0xffffffffu, bi, off);
                if (ov2 > bv || (ov2 == bv && oi < bi)) { bv = ov2; bi = oi; }
            }
            mymsk |= 1u << bi;
            if (lane == bi) v = -INFINITY;
        }
        if (lane == 0) smask[w] = mymsk;
    }

    // pack p_cmp * gc into bf16 hi/lo A-fragments (kept for post-loop PV)
    uint32_t pch0[4], pch1[4], pcl0[4], pcl1[4];
    {
        float gc0 = 1.f / (1.f + __expf(-g_g[tt * 48 + (lane >> 2) * 3]));
        float gc1 = 1.f / (1.f + __expf(-g_g[tt * 48 + ((lane >> 2) + 8) * 3]));
#pragma unroll
        for (int nt = 0; nt < 4; nt++) {
            float q0 = d4[nt][0] * gc0, q1 = d4[nt][1] * gc0;
            float q2 = d4[nt][2] * gc1, q3 = d4[nt][3] * gc1;
            __nv_bfloat16 b0, b1, b2, b3;
            pch0[nt] = pack_hi(q0, q1, b0, b1);
            pch1[nt] = pack_hi(q2, q3, b2, b3);
            pcl0[nt] = pack_bf16x2(q0 - __bfloat162float(b0), q1 - __bfloat162float(b1));
            pcl1[nt] = pack_bf16x2(q2 - __bfloat162float(b2), q3 - __bfloat162float(b3));
        }
    }

    __syncthreads();
    if (tid == 0) {
        uint32_t u = 0;
        for (int i = 0; i < 16; i++) u |= smask[i];
        int cnt = 0;
        for (int c = 0; c < NB; c++)
            if ((u >> c) & 1u) ulist[cnt++] = c;
        *ucnt = cnt;          // ulist[0] == 0 always (forced)
    }
    __syncthreads();
    const int nu = *ucnt;

    // =========== selected block-sparse attention over the union ===========
    float ov[8][4];
#pragma unroll
    for (int vt = 0; vt < 8; vt++)
#pragma unroll
        for (int j = 0; j < 4; j++) ov[vt][j] = 0.f;
    float mrow[2] = {NEGS, NEGS};
    float srow[2] = {0.f, 0.f};

    for (int i = 0; i < nu; i++) {
        cp_wait0();
        __syncthreads();
        if (i + 1 < nu) issueKV(ulist[i + 1], (i + 1) & 1);

        const int c = ulist[i];
        if ((mymsk >> c) & 1u) {
            const uint32_t base = sb0 + STG_OFF + (i & 1) * STG_SZ;

            float d[8][4];
#pragma unroll
            for (int nt = 0; nt < 8; nt++)
#pragma unroll
                for (int j = 0; j < 4; j++) d[nt][j] = 0.f;

#pragma unroll
            for (int ks = 0; ks < 4; ks++) {
                uint32_t qa = sb0 + (w * 16 + (lane & 15)) * 144 + ((lane >> 4) << 4) + ks * 32;
                uint32_t qh4[4], ql4[4];
                ldsm4(qh4, qa);
                ldsm4(ql4, qa + SQL_OFF);
#pragma unroll
                for (int nt = 0; nt < 8; nt++) {
                    uint32_t bh2[2], bl2[2];
                    uint32_t ba = base + (nt * 8 + (lane & 7)) * 144 + ((lane >> 3) & 1) * 16 + ks * 32;
                    ldsm2(bh2, ba);
                    ldsm2(bl2, ba + KV_T);
                    mma16816(d[nt], qh4, bh2);
                    mma16816(d[nt], ql4, bh2);
                    mma16816(d[nt], qh4, bl2);
                }
            }

            const int colb = c * 64 + ((lane & 3) << 1);
            float bq0 = NEGS, bq1 = NEGS;
#pragma unroll
            for (int nt = 0; nt < 8; nt++) {
                int tok0 = colb + nt * 8;
                bool v0 = tok0 <= tt, v1 = tok0 + 1 <= tt;
                d[nt][0] = v0 ? d[nt][0] * 0.125f : NEGS;
                d[nt][1] = v1 ? d[nt][1] * 0.125f : NEGS;
                d[nt][2] = v0 ? d[nt][2] * 0.125f : NEGS;
                d[nt][3] = v1 ? d[nt][3] * 0.125f : NEGS;
                bq0 = fmaxf(bq0, fmaxf(d[nt][0], d[nt][1]));
                bq1 = fmaxf(bq1, fmaxf(d[nt][2], d[nt][3]));
            }
            bq0 = fmaxf(bq0, __shfl_xor_sync(0xffffffffu, bq0, 1));
            bq0 = fmaxf(bq0, __shfl_xor_sync(0xffffffffu, bq0, 2));
            bq1 = fmaxf(bq1, __shfl_xor_sync(0xffffffffu, bq1, 1));
            bq1 = fmaxf(bq1, __shfl_xor_sync(0xffffffffu, bq1, 2));
            float mn0 = fmaxf(mrow[0], bq0), mn1 = fmaxf(mrow[1], bq1);
            float a0 = __expf(mrow[0] - mn0), a1 = __expf(mrow[1] - mn1);
            mrow[0] = mn0; mrow[1] = mn1;
            srow[0] *= a0; srow[1] *= a1;
#pragma unroll
            for (int vt = 0; vt < 8; vt++) {
                ov[vt][0] *= a0; ov[vt][1] *= a0;
                ov[vt][2] *= a1; ov[vt][3] *= a1;
            }

#pragma unroll
            for (int nt = 0; nt < 8; nt++) {
                uint32_t vh8[8], vl8[8];
                uint32_t va = base + 2 * KV_T + (nt * 8 + (lane & 7)) * 144 + (lane >> 3) * 16;
                ldsm4t(vh8, va);        ldsm4t(vh8 + 4, va + 64);
                ldsm4t(vl8, va + KV_T); ldsm4t(vl8 + 4, va + KV_T + 64);
                float p0 = __expf(d[nt][0] - mrow[0]);
                float p1 = __expf(d[nt][1] - mrow[0]);
                float p2 = __expf(d[nt][2] - mrow[1]);
                float p3 = __expf(d[nt][3] - mrow[1]);
                srow[0] += p0 + p1;
                srow[1] += p2 + p3;
                __nv_bfloat16 b0, b1, b2, b3;
                uint32_t ah0 = pack_hi(p0, p1, b0, b1);
                uint32_t ah1 = pack_hi(p2, p3, b2, b3);
                uint32_t al0 = pack_bf16x2(p0 - __bfloat162float(b0), p1 - __bfloat162float(b1));
                uint32_t al1 = pack_bf16x2(p2 - __bfloat162float(b2), p3 - __bfloat162float(b3));
#pragma unroll
                for (int vt = 0; vt < 8; vt++) {
                    mma16808(ov[vt], ah0, ah1, vh8[vt]);
                    mma16808(ov[vt], al0, al1, vh8[vt]);
                    mma16808(ov[vt], ah0, ah1, vl8[vt]);
                }
            }
        }
        __syncthreads();
    }

    // ---- epilogue: normalize + gate slc, then accumulate gated cmp PV ----
    {
        float s0 = srow[0], s1 = srow[1];
        s0 += __shfl_xor_sync(0xffffffffu, s0, 1);
        s0 += __shfl_xor_sync(0xffffffffu, s0, 2);
        s1 += __shfl_xor_sync(0xffffffffu, s1, 1);
        s1 += __shfl_xor_sync(0xffffffffu, s1, 2);
        float gs0 = 1.f / (1.f + __expf(-g_g[tt * 48 + (lane >> 2) * 3 + 1]));
        float gs1 = 1.f / (1.f + __expf(-g_g[tt * 48 + ((lane >> 2) + 8) * 3 + 1]));
        float f0 = gs0 / s0, f1 = gs1 / s1;
#pragma unroll
        for (int vt = 0; vt < 8; vt++) {
            ov[vt][0] *= f0; ov[vt][1] *= f0;
            ov[vt][2] *= f1; ov[vt][3] *= f1;
        }
    }
    // cmp PV: ov += (p_cmp*gc) @ Vc  (Kc/Vc region still intact)
#pragma unroll
    for (int kc = 0; kc < 4; kc++) {
        uint32_t vh8[8], vl8[8];
        uint32_t va = sb0 + VCH_OFF + (kc * 8 + (lane & 7)) * 144 + (lane >> 3) * 16;
        ldsm4t(vh8, va);        ldsm4t(vh8 + 4, va + 64);
        ldsm4t(vl8, va + 4608); ldsm4t(vl8 + 4, va + 4608 + 64);
#pragma unroll
        for (int vt = 0; vt < 8; vt++) {
            mma16808(ov[vt], pch0[kc], pch1[kc], vh8[vt]);
            mma16808(ov[vt], pcl0[kc], pcl1[kc], vh8[vt]);
            mma16808(ov[vt], pch0[kc], pch1[kc], vl8[vt]);
        }
    }

    // ---- write comb as bf16 hi/lo ----
#pragma unroll
    for (int half = 0; half < 2; half++) {
        int h = (lane >> 2) + half * 8;
#pragma unroll
        for (int vt = 0; vt < 8; vt++) {
            int col = vt * 8 + ((lane & 3) << 1);
            size_t off = (size_t)tt * 1024 + h * 64 + col;
            float c0 = ov[vt][half * 2], c1 = ov[vt][half * 2 + 1];
            __nv_bfloat16 b0, b1;
            *(uint32_t*)(g_ch + off) = pack_hi(c0, c1, b0, b1);
            *(uint32_t*)(g_cl + off) =
                pack_bf16x2(c0 - __bfloat162float(b0), c1 - __bfloat162float(b1));
        }
    }
}

// ---------------- launch ----------------------------------------------------
extern "C" void kernel_launch(void* const* d_in, const int* in_sizes, int n_in,
                              void* d_out, int out_size) {
    const float* x  = (const float*)d_in[0];
    const float* Wq = (const float*)d_in[1];
    const float* Wk = (const float*)d_in[2];
    const float* Wv = (const float*)d_in[3];
    const float* Wg = (const float*)d_in[4];
    const float* Wo = (const float*)d_in[5];
    float* out = (float*)d_out;

    void *pq, *pxh, *pxl, *pch, *pcl, *pwch, *pwcl, *pwoh, *pwol;
    cudaGetSymbolAddress(&pq, g_q);
    cudaGetSymbolAddress(&pxh, g_xh);   cudaGetSymbolAddress(&pxl, g_xl);
    cudaGetSymbolAddress(&pch, g_ch);   cudaGetSymbolAddress(&pcl, g_cl);
    cudaGetSymbolAddress(&pwch, g_wch); cudaGetSymbolAddress(&pwcl, g_wcl);
    cudaGetSymbolAddress(&pwoh, g_woh); cudaGetSymbolAddress(&pwol, g_wol);

    __nv_bfloat16* wch = (__nv_bfloat16*)pwch;
    __nv_bfloat16* wcl = (__nv_bfloat16*)pwcl;

    cudaFuncSetAttribute(gemm_mma, cudaFuncAttributeMaxDynamicSharedMemorySize, GEMM_SMEM);
    cudaFuncSetAttribute(slc16, cudaFuncAttributeMaxDynamicSharedMemorySize, SLC16_SMEM);

    // conversions
    conv_hilo<<<2048, 256>>>((const float4*)x, (uint2*)pxh, (uint2*)pxl, 524288);
    conv_hilo<<<1024, 256>>>((const float4*)Wq, (uint2*)wch, (uint2*)wcl, 262144);
    conv_hilo<<<64, 256>>>((const float4*)Wk, (uint2*)(wch + 1024 * 1024), (uint2*)(wcl + 1024 * 1024), 16384);
    conv_hilo<<<64, 256>>>((const float4*)Wv, (uint2*)(wch + 1088 * 1024), (uint2*)(wcl + 1088 * 1024), 16384);
    conv_hilo<<<48, 256>>>((const float4*)Wg, (uint2*)(wch + 1152 * 1024), (uint2*)(wcl + 1152 * 1024), 12288);
    cudaMemsetAsync(wch + 1200 * 1024, 0, 80 * 1024 * 2);
    cudaMemsetAsync(wcl + 1200 * 1024, 0, 80 * 1024 * 2);
    conv_hilo<<<1024, 256>>>((const float4*)Wo, (uint2*)pwoh, (uint2*)pwol, 262144);

    // fused projections: [Q | K | V | G] = x @ [Wq;Wk;Wv;Wg]^T
    gemm_mma<<<dim3(10, 16), 256, GEMM_SMEM>>>((const __nv_bfloat16*)pxh, (const __nv_bfloat16*)pxl,
                                               wch, wcl, (float*)pq, 1);
    pool_kv<<<NB, 64>>>();
    slc16<<<T_LEN / 16, 512, SLC16_SMEM>>>();   // fused cmp + topk + selected attn

    // out = comb @ Wo^T
    gemm_mma<<<dim3(8, 16), 256, GEMM_SMEM>>>((const __nv_bfloat16*)pch, (const __nv_bfloat16*)pcl,
                                              (const __nv_bfloat16*)pwoh, (const __nv_bfloat16*)pwol,
                                              out, 0);
}

// round 11
// speedup vs baseline: 1.3082x; 1.0528x over previous
#include <cuda_runtime.h>
#include <cuda_bf16.h>
#include <cstdint>

// ---------------- problem constants ----------------
#define T_LEN 2048
#define DM    1024
#define NHEAD 16
#define HDIM  64
#define NB    32
#define SSEL  16
#define NEGV  (-1e30f)
#define NEGS  (-1.25e29f)

// ---------------- scratch ----------------------------------------------------
__device__ float g_q   [T_LEN * DM];
__device__ float g_k   [T_LEN * HDIM];
__device__ float g_v   [T_LEN * HDIM];
__device__ float g_g   [T_LEN * 48];

__device__ __nv_bfloat16 g_xh [T_LEN * DM], g_xl [T_LEN * DM];
__device__ __nv_bfloat16 g_qh [T_LEN * DM], g_ql [T_LEN * DM];
__device__ __nv_bfloat16 g_ch [T_LEN * DM], g_cl [T_LEN * DM];
__device__ __nv_bfloat16 g_kh [T_LEN * HDIM], g_kl [T_LEN * HDIM];
__device__ __nv_bfloat16 g_vh [T_LEN * HDIM], g_vl [T_LEN * HDIM];
__device__ __nv_bfloat16 g_kch[NB * HDIM], g_kcl[NB * HDIM];
__device__ __nv_bfloat16 g_vch[NB * HDIM], g_vcl[NB * HDIM];
__device__ __nv_bfloat16 g_wch[1280 * DM], g_wcl[1280 * DM];   // stacked Wq|Wk|Wv|Wg|pad
__device__ __nv_bfloat16 g_woh[DM * DM],   g_wol[DM * DM];

// ================= helpers ==================================================
__device__ __forceinline__ uint32_t smem_u32(const void* p) {
    uint32_t a;
    asm("{ .reg .u64 t; cvta.to.shared.u64 t, %1; cvt.u32.u64 %0, t; }"
        : "=r"(a) : "l"(p));
    return a;
}
__device__ __forceinline__ void cp_async16(uint32_t saddr, const void* gaddr) {
    asm volatile("cp.async.cg.shared.global [%0], [%1], 16;"
                 :: "r"(saddr), "l"(gaddr));
}
__device__ __forceinline__ void cp_commit() {
    asm volatile("cp.async.commit_group;" ::: "memory");
}
__device__ __forceinline__ void cp_wait0() {
    asm volatile("cp.async.wait_group 0;" ::: "memory");
}
__device__ __forceinline__ void cp_wait1() {
    asm volatile("cp.async.wait_group 1;" ::: "memory");
}
__device__ __forceinline__ void ldsm4(uint32_t* r, uint32_t addr) {
    asm volatile("ldmatrix.sync.aligned.m8n8.x4.shared.b16 {%0,%1,%2,%3}, [%4];"
                 : "=r"(r[0]), "=r"(r[1]), "=r"(r[2]), "=r"(r[3]) : "r"(addr));
}
__device__ __forceinline__ void ldsm2(uint32_t* r, uint32_t addr) {
    asm volatile("ldmatrix.sync.aligned.m8n8.x2.shared.b16 {%0,%1}, [%2];"
                 : "=r"(r[0]), "=r"(r[1]) : "r"(addr));
}
__device__ __forceinline__ void ldsm4t(uint32_t* r, uint32_t addr) {
    asm volatile("ldmatrix.sync.aligned.m8n8.x4.trans.shared.b16 {%0,%1,%2,%3}, [%4];"
                 : "=r"(r[0]), "=r"(r[1]), "=r"(r[2]), "=r"(r[3]) : "r"(addr));
}
__device__ __forceinline__ void mma16816(float* d, const uint32_t* a, const uint32_t* b) {
    asm volatile(
        "mma.sync.aligned.m16n8k16.row.col.f32.bf16.bf16.f32 "
        "{%0,%1,%2,%3}, {%4,%5,%6,%7}, {%8,%9}, {%0,%1,%2,%3};"
        : "+f"(d[0]), "+f"(d[1]), "+f"(d[2]), "+f"(d[3])
        : "r"(a[0]), "r"(a[1]), "r"(a[2]), "r"(a[3]), "r"(b[0]), "r"(b[1]));
}
__device__ __forceinline__ void mma16808(float* d, uint32_t a0, uint32_t a1, uint32_t b0) {
    asm volatile(
        "mma.sync.aligned.m16n8k8.row.col.f32.bf16.bf16.f32 "
        "{%0,%1,%2,%3}, {%4,%5}, {%6}, {%0,%1,%2,%3};"
        : "+f"(d[0]), "+f"(d[1]), "+f"(d[2]), "+f"(d[3])
        : "r"(a0), "r"(a1), "r"(b0));
}
__device__ __forceinline__ uint32_t pack_bf16x2(float lo, float hi) {
    uint32_t r;
    asm("cvt.rn.bf16x2.f32 %0, %1, %2;" : "=r"(r) : "f"(hi), "f"(lo));
    return r;
}
__device__ __forceinline__ uint32_t pack_hi(float a, float b, __nv_bfloat16& ha, __nv_bfloat16& hb) {
    ha = __float2bfloat16(a); hb = __float2bfloat16(b);
    return (uint32_t)__bfloat16_as_ushort(ha) | ((uint32_t)__bfloat16_as_ushort(hb) << 16);
}

// ====== single-launch fp32 -> bf16 hi/lo conversion for all weights/x =======
// segments (float4 index): x[0,524288) Wq[..786432) Wk[..802816) Wv[..819200)
// Wg[..831488) Wo[..1093632) pad-zero[..1114112)
__global__ __launch_bounds__(256) void conv_all(const float4* __restrict__ x,
                                                const float4* __restrict__ Wq,
                                                const float4* __restrict__ Wk,
                                                const float4* __restrict__ Wv,
                                                const float4* __restrict__ Wg,
                                                const float4* __restrict__ Wo) {
    int i = blockIdx.x * 256 + threadIdx.x;
    const float4* src; uint2 *h, *l; int di;
    if (i < 524288)       { src = x;  di = i;           h = (uint2*)g_xh;  l = (uint2*)g_xl; }
    else if (i < 786432)  { src = Wq; di = i - 524288;  h = (uint2*)g_wch; l = (uint2*)g_wcl; }
    else if (i < 802816)  { src = Wk; di = i - 786432;  h = (uint2*)g_wch + 262144; l = (uint2*)g_wcl + 262144; }
    else if (i < 819200)  { src = Wv; di = i - 802816;  h = (uint2*)g_wch + 278528; l = (uint2*)g_wcl + 278528; }
    else if (i < 831488)  { src = Wg; di = i - 819200;  h = (uint2*)g_wch + 294912; l = (uint2*)g_wcl + 294912; }
    else if (i < 1093632) { src = Wo; di = i - 831488;  h = (uint2*)g_woh; l = (uint2*)g_wol; }
    else {
        int dz = i - 1093632;                       // 20480 pad uint2s
        uint2 z = make_uint2(0u, 0u);
        ((uint2*)g_wch)[307200 + dz] = z;
        ((uint2*)g_wcl)[307200 + dz] = z;
        return;
    }
    float4 v = src[di];
    __nv_bfloat16 h0, h1, h2, h3;
    uint2 hv, lv;
    hv.x = pack_hi(v.x, v.y, h0, h1);
    hv.y = pack_hi(v.z, v.w, h2, h3);
    lv.x = pack_bf16x2(v.x - __bfloat162float(h0), v.y - __bfloat162float(h1));
    lv.y = pack_bf16x2(v.z - __bfloat162float(h2), v.w - __bfloat162float(h3));
    h[di] = hv;
    l[di] = lv;
}

// ================= tensor-core GEMM via mma.sync (bf16x3, 2-stage) ==========
#define TSTRIDE 80
#define TILE_BYTES (128 * TSTRIDE)
#define BUF_BYTES  (4 * TILE_BYTES)
#define GEMM_SMEM  (2 * BUF_BYTES)    // 81920; with <=128 regs -> 2 CTAs/SM

__global__ __launch_bounds__(256, 2) void gemm_mma(const __nv_bfloat16* __restrict__ Ah,
                                                   const __nv_bfloat16* __restrict__ Al,
                                                   const __nv_bfloat16* __restrict__ Bh,
                                                   const __nv_bfloat16* __restrict__ Bl,
                                                   float* __restrict__ C,
                                                   int mode) {
    extern __shared__ char sm[];
    const uint32_t sbase = smem_u32(sm);
    const int tid = threadIdx.x;
    const int lane = tid & 31, wid = tid >> 5;
    const int m0 = blockIdx.y * 128;
    const int n0 = blockIdx.x * 128;
    const int wm = (wid >> 2) * 64;
    const int wn = (wid & 3) * 32;

    const __nv_bfloat16* gsrc[4] = {Ah, Al, Bh, Bl};

    float acc[4][4][4];
#pragma unroll
    for (int i = 0; i < 4; i++)
#pragma unroll
        for (int j = 0; j < 4; j++)
#pragma unroll
            for (int k = 0; k < 4; k++) acc[i][j][k] = 0.f;

    const int arow = wm + (lane & 15);
    const int akc  = (lane >> 4) << 3;
    const int brow = wn + (lane & 7) + ((lane >> 4) << 3);
    const int bkc  = ((lane >> 3) & 1) << 3;

    auto issue = [&](int c, int buf) {
#pragma unroll
        for (int T = 0; T < 4; T++) {
            const __nv_bfloat16* src = gsrc[T];
            const int rb = (T < 2) ? m0 : n0;
#pragma unroll
            for (int i = 0; i < 2; i++) {
                int idx = i * 256 + tid;
                int row = idx >> 2;
                int u   = idx & 3;
                uint32_t sa = sbase + buf * BUF_BYTES + T * TILE_BYTES + row * TSTRIDE + u * 16;
                cp_async16(sa, src + (size_t)(rb + row) * 1024 + c * 32 + u * 8);
            }
        }
        cp_commit();
    };

    issue(0, 0);

    for (int c = 0; c < 32; c++) {
        const int buf = c & 1;
        cp_wait0();
        __syncthreads();
        if (c + 1 < 32) issue(c + 1, buf ^ 1);

        const uint32_t base = sbase + buf * BUF_BYTES;
#pragma unroll
        for (int ks = 0; ks < 2; ks++) {
            uint32_t ah[4][4], al[4][4], bh[2][4], bl[2][4];
#pragma unroll
            for (int mt = 0; mt < 4; mt++) {
                uint32_t aa = base + (arow + mt * 16) * TSTRIDE + (ks * 16 + akc) * 2;
                ldsm4(ah[mt], aa);
                ldsm4(al[mt], aa + TILE_BYTES);
            }
#pragma unroll
            for (int np = 0; np < 2; np++) {
                uint32_t ba = base + 2 * TILE_BYTES + (brow + np * 16) * TSTRIDE + (ks * 16 + bkc) * 2;
                ldsm4(bh[np], ba);
                ldsm4(bl[np], ba + TILE_BYTES);
            }
#pragma unroll
            for (int mt = 0; mt < 4; mt++)
#pragma unroll
                for (int nt = 0; nt < 4; nt++) {
                    const uint32_t* ph = &bh[nt >> 1][(nt & 1) * 2];
                    const uint32_t* pl = &bl[nt >> 1][(nt & 1) * 2];
                    mma16816(acc[mt][nt], ah[mt], ph);
                    mma16816(acc[mt][nt], al[mt], ph);
                    mma16816(acc[mt][nt], ah[mt], pl);
                }
        }
        __syncthreads();
    }

    const int g = lane >> 2, t4 = lane & 3;
#pragma unroll
    for (int mt = 0; mt < 4; mt++)
#pragma unroll
        for (int nt = 0; nt < 4; nt++) {
            int r = m0 + wm + mt * 16 + g;
            int cc = n0 + wn + nt * 8 + t4 * 2;
#pragma unroll
            for (int half = 0; half < 2; half++) {
                int rr = r + half * 8;
                float v0 = acc[mt][nt][half * 2], v1 = acc[mt][nt][half * 2 + 1];
                if (mode == 0) {
                    *(float2*)(C + (size_t)rr * 1024 + cc) = make_float2(v0, v1);
                } else {
                    __nv_bfloat16 b0, b1;
                    if (cc < 1024) {
                        *(float2*)(g_q + (size_t)rr * 1024 + cc) = make_float2(v0, v1);
                        uint32_t hh = pack_hi(v0, v1, b0, b1);
                        *(uint32_t*)(g_qh + (size_t)rr * 1024 + cc) = hh;
                        *(uint32_t*)(g_ql + (size_t)rr * 1024 + cc) =
                            pack_bf16x2(v0 - __bfloat162float(b0), v1 - __bfloat162float(b1));
                    } else if (cc < 1088) {
                        int k = cc - 1024;
                        *(float2*)(g_k + (size_t)rr * 64 + k) = make_float2(v0, v1);
                        uint32_t hh = pack_hi(v0, v1, b0, b1);
                        *(uint32_t*)(g_kh + (size_t)rr * 64 + k) = hh;
                        *(uint32_t*)(g_kl + (size_t)rr * 64 + k) =
                            pack_bf16x2(v0 - __bfloat162float(b0), v1 - __bfloat162float(b1));
                    } else if (cc < 1152) {
                        int k = cc - 1088;
                        *(float2*)(g_v + (size_t)rr * 64 + k) = make_float2(v0, v1);
                        uint32_t hh = pack_hi(v0, v1, b0, b1);
                        *(uint32_t*)(g_vh + (size_t)rr * 64 + k) = hh;
                        *(uint32_t*)(g_vl + (size_t)rr * 64 + k) =
                            pack_bf16x2(v0 - __bfloat162float(b0), v1 - __bfloat162float(b1));
                    } else if (cc < 1200) {
                        int k = cc - 1152;
                        *(float2*)(g_g + (size_t)rr * 48 + k) = make_float2(v0, v1);
                    }
                }
            }
        }
}

// ---------------- mean-pool K,V (bf16 hi/lo) ---------------------------------
__global__ void pool_kv() {
    int c = blockIdx.x, d = threadIdx.x;
    float sk = 0.f, sv = 0.f;
    for (int i = 0; i < 64; i++) {
        sk += g_k[(size_t)(c * 64 + i) * 64 + d];
        sv += g_v[(size_t)(c * 64 + i) * 64 + d];
    }
    sk *= (1.f / 64.f); sv *= (1.f / 64.f);
    int idx = c * 64 + d;
    __nv_bfloat16 hk = __float2bfloat16(sk);
    __nv_bfloat16 hv2 = __float2bfloat16(sv);
    g_kch[idx] = hk; g_kcl[idx] = __float2bfloat16(sk - __bfloat162float(hk));
    g_vch[idx] = hv2; g_vcl[idx] = __float2bfloat16(sv - __bfloat162float(hv2));
}

// ====== FUSED: cmp attn + top-k + union selected attn, 14 tokens/CTA ========
// 448 threads (1 token/warp), grid 147 (full wave on 148 SMs), 2-stage KV.
// smem: Qh 224x144 | Ql | Kc/Kcl/Vc/Vcl (4x 32x144) | 2 KV stages | meta+imp
#define SQL14     32256
#define KC14      64512
#define STG14     82944
#define STG_SZ    36864
#define KV_T      9216
#define META14    156672
#define IMP14     (META14 + 256)
#define SLC14_SMEM (IMP14 + 2048)   // 158976

__global__ __launch_bounds__(448, 1) void slc14() {
    extern __shared__ char smc[];
    const uint32_t sb0 = smem_u32(smc);
    const int tid = threadIdx.x;
    const int lane = tid & 31, w = tid >> 5;   // w = 0..13, one token per warp
    const int T0 = blockIdx.x * 14;
    const int ntok = min(14, T_LEN - T0);
    const bool act = (w < ntok);
    const int tt = act ? (T0 + w) : (T_LEN - 1);

    uint32_t* smask = (uint32_t*)(smc + META14);
    int* ulist = (int*)(smc + META14 + 128);
    int* ucnt  = (int*)(smc + META14 + 124);
    float* impsm = (float*)(smc + IMP14);

    // ---- stage Q hi/lo (row = localtoken*16+head), 224 rows x 2 tiles ----
#pragma unroll
    for (int i = 0; i < 8; i++) {
        int idx = i * 448 + tid;                 // 0..3583
        int tile = idx / 1792;                   // 0 = hi, 1 = lo
        int wi = idx - tile * 1792;
        int row = wi >> 3, u = wi & 7;
        int token = T0 + (row >> 4);
        if (token > T_LEN - 1) token = T_LEN - 1;
        int head = row & 15;
        size_t go = (size_t)token * 1024 + head * 64 + u * 8;
        cp_async16(sb0 + tile * SQL14 + row * 144 + u * 16, (tile ? g_ql : g_qh) + go);
    }
    // ---- stage pooled Kc/Vc hi/lo ----
#pragma unroll
    for (int i = 0; i < 3; i++) {
        int idx = i * 448 + tid;                 // 0..1023 valid
        if (idx < 1024) {
            int tile = idx >> 8, r = (idx >> 3) & 31, u = idx & 7;
            const __nv_bfloat16* gp = (tile == 0) ? g_kch : (tile == 1) ? g_kcl
                                    : (tile == 2) ? g_vch : g_vcl;
            cp_async16(sb0 + KC14 + tile * 4608 + r * 144 + u * 16, gp + r * 64 + u * 8);
        }
    }
    cp_commit();

    auto issueKV = [&](int c, int stage) {
        uint32_t base = sb0 + STG14 + stage * STG_SZ;
#pragma unroll
        for (int i = 0; i < 5; i++) {
            int cid = i * 448 + tid;
            if (cid < 2048) {
                int tile = cid >> 9, r = (cid >> 3) & 63, u = cid & 7;
                const __nv_bfloat16* gp = (tile == 0) ? g_kh : (tile == 1) ? g_kl
                                        : (tile == 2) ? g_vh : g_vl;
                cp_async16(base + tile * KV_T + r * 144 + u * 16,
                           gp + (size_t)(c * 64 + r) * 64 + u * 8);
            }
        }
        cp_commit();
    };

    // block 0 always forced into every active mask -> pre-issue it
    issueKV(0, 0);
    cp_wait1();          // Q + Kc/Vc complete; KV0 may be in flight
    __syncthreads();

    const int nvis = (tt + 1) >> 6;
    const int cur = tt >> 6;

    uint32_t mymsk = 0;
    uint32_t pch0[4], pch1[4], pcl0[4], pcl1[4];

    if (act) {
        // =========== compressed branch: QK over pooled Kc (bf16x3) ===========
        float d4[4][4];
#pragma unroll
        for (int nt = 0; nt < 4; nt++)
#pragma unroll
            for (int j = 0; j < 4; j++) d4[nt][j] = 0.f;

#pragma unroll
        for (int ks = 0; ks < 4; ks++) {
            uint32_t qa = sb0 + (w * 16 + (lane & 15)) * 144 + ((lane >> 4) << 4) + ks * 32;
            uint32_t qh4[4], ql4[4];
            ldsm4(qh4, qa);
            ldsm4(ql4, qa + SQL14);
#pragma unroll
            for (int nt = 0; nt < 4; nt++) {
                uint32_t bh2[2], bl2[2];
                uint32_t ba = sb0 + KC14 + (nt * 8 + (lane & 7)) * 144 + ((lane >> 3) & 1) * 16 + ks * 32;
                ldsm2(bh2, ba);
                ldsm2(bl2, ba + 4608);
                mma16816(d4[nt], qh4, bh2);
                mma16816(d4[nt], ql4, bh2);
                mma16816(d4[nt], qh4, bl2);
            }
        }

        // mask + softmax over 32 blocks
        float bm0 = NEGS, bm1 = NEGS;
#pragma unroll
        for (int nt = 0; nt < 4; nt++) {
            int c0 = nt * 8 + ((lane & 3) << 1);
            bool v0 = c0 < nvis, v1 = c0 + 1 < nvis;
            d4[nt][0] = v0 ? d4[nt][0] * 0.125f : NEGS;
            d4[nt][1] = v1 ? d4[nt][1] * 0.125f : NEGS;
            d4[nt][2] = v0 ? d4[nt][2] * 0.125f : NEGS;
            d4[nt][3] = v1 ? d4[nt][3] * 0.125f : NEGS;
            bm0 = fmaxf(bm0, fmaxf(d4[nt][0], d4[nt][1]));
            bm1 = fmaxf(bm1, fmaxf(d4[nt][2], d4[nt][3]));
        }
        bm0 = fmaxf(bm0, __shfl_xor_sync(0xffffffffu, bm0, 1));
        bm0 = fmaxf(bm0, __shfl_xor_sync(0xffffffffu, bm0, 2));
        bm1 = fmaxf(bm1, __shfl_xor_sync(0xffffffffu, bm1, 1));
        bm1 = fmaxf(bm1, __shfl_xor_sync(0xffffffffu, bm1, 2));

        float ps0 = 0.f, ps1 = 0.f;
#pragma unroll
        for (int nt = 0; nt < 4; nt++) {
            d4[nt][0] = __expf(d4[nt][0] - bm0);
            d4[nt][1] = __expf(d4[nt][1] - bm0);
            d4[nt][2] = __expf(d4[nt][2] - bm1);
            d4[nt][3] = __expf(d4[nt][3] - bm1);
            ps0 += d4[nt][0] + d4[nt][1];
            ps1 += d4[nt][2] + d4[nt][3];
        }
        ps0 += __shfl_xor_sync(0xffffffffu, ps0, 1);
        ps0 += __shfl_xor_sync(0xffffffffu, ps0, 2);
        ps1 += __shfl_xor_sync(0xffffffffu, ps1, 1);
        ps1 += __shfl_xor_sync(0xffffffffu, ps1, 2);
        float iv0 = (nvis > 0) ? 1.f / ps0 : 0.f;
        float iv1 = (nvis > 0) ? 1.f / ps1 : 0.f;
#pragma unroll
        for (int nt = 0; nt < 4; nt++) {
            d4[nt][0] *= iv0; d4[nt][1] *= iv0;
            d4[nt][2] *= iv1; d4[nt][3] *= iv1;
        }

        // importance = sum over 16 heads per block
#pragma unroll
        for (int nt = 0; nt < 4; nt++) {
            float t0 = d4[nt][0] + d4[nt][2];
            float t1 = d4[nt][1] + d4[nt][3];
            t0 += __shfl_xor_sync(0xffffffffu, t0, 4);
            t0 += __shfl_xor_sync(0xffffffffu, t0, 8);
            t0 += __shfl_xor_sync(0xffffffffu, t0, 16);
            t1 += __shfl_xor_sync(0xffffffffu, t1, 4);
            t1 += __shfl_xor_sync(0xffffffffu, t1, 8);
            t1 += __shfl_xor_sync(0xffffffffu, t1, 16);
            int c0 = nt * 8 + ((lane & 3) << 1);
            impsm[w * 32 + c0] = t0;
            impsm[w * 32 + c0 + 1] = t1;
        }
        __syncwarp();

        // stable top-16 (desc, lowest index on tie)
        {
            float base = impsm[w * 32 + lane];
            float v = (lane == 0 || lane == cur) ? INFINITY
                    : (lane > cur ? NEGV : base);
#pragma unroll
            for (int s = 0; s < SSEL; s++) {
                float bv = v; int bi = lane;
#pragma unroll
                for (int off = 16; off >= 1; off >>= 1) {
                    float ov2 = __shfl_xor_sync(0xffffffffu, bv, off);
                    int   oi = __shfl_xor_sync(0xffffffffu, bi, off);
                    if (ov2 > bv || (ov2 == bv && oi < bi)) { bv = ov2; bi = oi; }
                }
                mymsk |= 1u << bi;
                if (lane == bi) v = -INFINITY;
            }
        }

        // pack p_cmp * gc into bf16 hi/lo A-fragments
        {
            float gc0 = 1.f / (1.f + __expf(-g_g[tt * 48 + (lane >> 2) * 3]));
            float gc1 = 1.f / (1.f + __expf(-g_g[tt * 48 + ((lane >> 2) + 8) * 3]));
#pragma unroll
            for (int nt = 0; nt < 4; nt++) {
                float q0 = d4[nt][0] * gc0, q1 = d4[nt][1] * gc0;
                float q2 = d4[nt][2] * gc1, q3 = d4[nt][3] * gc1;
                __nv_bfloat16 b0, b1, b2, b3;
                pch0[nt] = pack_hi(q0, q1, b0, b1);
                pch1[nt] = pack_hi(q2, q3, b2, b3);
                pcl0[nt] = pack_bf16x2(q0 - __bfloat162float(b0), q1 - __bfloat162float(b1));
                pcl1[nt] = pack_bf16x2(q2 - __bfloat162float(b2), q3 - __bfloat162float(b3));
            }
        }
    }
    if (lane == 0 && w < 14) smask[w] = mymsk;

    __syncthreads();
    if (tid == 0) {
        uint32_t u = 0;
        for (int i = 0; i < 14; i++) u |= smask[i];
        int cnt = 0;
        for (int c = 0; c < NB; c++)
            if ((u >> c) & 1u) ulist[cnt++] = c;
        *ucnt = cnt;          // ulist[0] == 0 always (forced)
    }
    __syncthreads();
    const int nu = *ucnt;

    // =========== selected block-sparse attention over the union ===========
    float ov[8][4];
#pragma unroll
    for (int vt = 0; vt < 8; vt++)
#pragma unroll
        for (int j = 0; j < 4; j++) ov[vt][j] = 0.f;
    float mrow[2] = {NEGS, NEGS};
    float srow[2] = {0.f, 0.f};

    for (int i = 0; i < nu; i++) {
        cp_wait0();
        __syncthreads();
        if (i + 1 < nu) issueKV(ulist[i + 1], (i + 1) & 1);

        const int c = ulist[i];
        if ((mymsk >> c) & 1u) {
            const uint32_t base = sb0 + STG14 + (i & 1) * STG_SZ;

            float d[8][4];
#pragma unroll
            for (int nt = 0; nt < 8; nt++)
#pragma unroll
                for (int j = 0; j < 4; j++) d[nt][j] = 0.f;

#pragma unroll
            for (int ks = 0; ks < 4; ks++) {
                uint32_t qa = sb0 + (w * 16 + (lane & 15)) * 144 + ((lane >> 4) << 4) + ks * 32;
                uint32_t qh4[4], ql4[4];
                ldsm4(qh4, qa);
                ldsm4(ql4, qa + SQL14);
#pragma unroll
                for (int nt = 0; nt < 8; nt++) {
                    uint32_t bh2[2], bl2[2];
                    uint32_t ba = base + (nt * 8 + (lane & 7)) * 144 + ((lane >> 3) & 1) * 16 + ks * 32;
                    ldsm2(bh2, ba);
                    ldsm2(bl2, ba + KV_T);
                    mma16816(d[nt], qh4, bh2);
                    mma16816(d[nt], ql4, bh2);
                    mma16816(d[nt], qh4, bl2);
                }
            }

            const int colb = c * 64 + ((lane & 3) << 1);
            float bq0 = NEGS, bq1 = NEGS;
#pragma unroll
            for (int nt = 0; nt < 8; nt++) {
                int tok0 = colb + nt * 8;
                bool v0 = tok0 <= tt, v1 = tok0 + 1 <= tt;
                d[nt][0] = v0 ? d[nt][0] * 0.125f : NEGS;
                d[nt][1] = v1 ? d[nt][1] * 0.125f : NEGS;
                d[nt][2] = v0 ? d[nt][2] * 0.125f : NEGS;
                d[nt][3] = v1 ? d[nt][3] * 0.125f : NEGS;
                bq0 = fmaxf(bq0, fmaxf(d[nt][0], d[nt][1]));
                bq1 = fmaxf(bq1, fmaxf(d[nt][2], d[nt][3]));
            }
            bq0 = fmaxf(bq0, __shfl_xor_sync(0xffffffffu, bq0, 1));
            bq0 = fmaxf(bq0, __shfl_xor_sync(0xffffffffu, bq0, 2));
            bq1 = fmaxf(bq1, __shfl_xor_sync(0xffffffffu, bq1, 1));
            bq1 = fmaxf(bq1, __shfl_xor_sync(0xffffffffu, bq1, 2));
            float mn0 = fmaxf(mrow[0], bq0), mn1 = fmaxf(mrow[1], bq1);
            float a0 = __expf(mrow[0] - mn0), a1 = __expf(mrow[1] - mn1);
            mrow[0] = mn0; mrow[1] = mn1;
            srow[0] *= a0; srow[1] *= a1;
#pragma unroll
            for (int vt = 0; vt < 8; vt++) {
                ov[vt][0] *= a0; ov[vt][1] *= a0;
                ov[vt][2] *= a1; ov[vt][3] *= a1;
            }

#pragma unroll
            for (int nt = 0; nt < 8; nt++) {
                uint32_t vh8[8], vl8[8];
                uint32_t va = base + 2 * KV_T + (nt * 8 + (lane & 7)) * 144 + (lane >> 3) * 16;
                ldsm4t(vh8, va);        ldsm4t(vh8 + 4, va + 64);
                ldsm4t(vl8, va + KV_T); ldsm4t(vl8 + 4, va + KV_T + 64);
                float p0 = __expf(d[nt][0] - mrow[0]);
                float p1 = __expf(d[nt][1] - mrow[0]);
                float p2 = __expf(d[nt][2] - mrow[1]);
                float p3 = __expf(d[nt][3] - mrow[1]);
                srow[0] += p0 + p1;
                srow[1] += p2 + p3;
                __nv_bfloat16 b0, b1, b2, b3;
                uint32_t ah0 = pack_hi(p0, p1, b0, b1);
                uint32_t ah1 = pack_hi(p2, p3, b2, b3);
                uint32_t al0 = pack_bf16x2(p0 - __bfloat162float(b0), p1 - __bfloat162float(b1));
                uint32_t al1 = pack_bf16x2(p2 - __bfloat162float(b2), p3 - __bfloat162float(b3));
#pragma unroll
                for (int vt = 0; vt < 8; vt++) {
                    mma16808(ov[vt], ah0, ah1, vh8[vt]);
                    mma16808(ov[vt], al0, al1, vh8[vt]);
                    mma16808(ov[vt], ah0, ah1, vl8[vt]);
                }
            }
        }
        __syncthreads();
    }

    if (act) {
        // ---- normalize + gate slc, then accumulate gated cmp PV ----
        {
            float s0 = srow[0], s1 = srow[1];
            s0 += __shfl_xor_sync(0xffffffffu, s0, 1);
            s0 += __shfl_xor_sync(0xffffffffu, s0, 2);
            s1 += __shfl_xor_sync(0xffffffffu, s1, 1);
            s1 += __shfl_xor_sync(0xffffffffu, s1, 2);
            float gs0 = 1.f / (1.f + __expf(-g_g[tt * 48 + (lane >> 2) * 3 + 1]));
            float gs1 = 1.f / (1.f + __expf(-g_g[tt * 48 + ((lane >> 2) + 8) * 3 + 1]));
            float f0 = gs0 / s0, f1 = gs1 / s1;
#pragma unroll
            for (int vt = 0; vt < 8; vt++) {
                ov[vt][0] *= f0; ov[vt][1] *= f0;
                ov[vt][2] *= f1; ov[vt][3] *= f1;
            }
        }
        // cmp PV: ov += (p_cmp*gc) @ Vc
#pragma unroll
        for (int kc = 0; kc < 4; kc++) {
            uint32_t vh8[8], vl8[8];
            uint32_t va = sb0 + KC14 + 9216 + (kc * 8 + (lane & 7)) * 144 + (lane >> 3) * 16;
            ldsm4t(vh8, va);        ldsm4t(vh8 + 4, va + 64);
            ldsm4t(vl8, va + 4608); ldsm4t(vl8 + 4, va + 4608 + 64);
#pragma unroll
            for (int vt = 0; vt < 8; vt++) {
                mma16808(ov[vt], pch0[kc], pch1[kc], vh8[vt]);
                mma16808(ov[vt], pcl0[kc], pcl1[kc], vh8[vt]);
                mma16808(ov[vt], pch0[kc], pch1[kc], vl8[vt]);
            }
        }

        // ---- write comb as bf16 hi/lo ----
#pragma unroll
        for (int half = 0; half < 2; half++) {
            int h = (lane >> 2) + half * 8;
#pragma unroll
            for (int vt = 0; vt < 8; vt++) {
                int col = vt * 8 + ((lane & 3) << 1);
                size_t off = (size_t)tt * 1024 + h * 64 + col;
                float c0 = ov[vt][half * 2], c1 = ov[vt][half * 2 + 1];
                __nv_bfloat16 b0, b1;
                *(uint32_t*)(g_ch + off) = pack_hi(c0, c1, b0, b1);
                *(uint32_t*)(g_cl + off) =
                    pack_bf16x2(c0 - __bfloat162float(b0), c1 - __bfloat162float(b1));
            }
        }
    }
}

// ---------------- launch ----------------------------------------------------
extern "C" void kernel_launch(void* const* d_in, const int* in_sizes, int n_in,
                              void* d_out, int out_size) {
    const float* x  = (const float*)d_in[0];
    const float* Wq = (const float*)d_in[1];
    const float* Wk = (const float*)d_in[2];
    const float* Wv = (const float*)d_in[3];
    const float* Wg = (const float*)d_in[4];
    const float* Wo = (const float*)d_in[5];
    float* out = (float*)d_out;

    void *pq, *pxh, *pxl, *pch, *pcl, *pwch, *pwcl, *pwoh, *pwol;
    cudaGetSymbolAddress(&pq, g_q);
    cudaGetSymbolAddress(&pxh, g_xh);   cudaGetSymbolAddress(&pxl, g_xl);
    cudaGetSymbolAddress(&pch, g_ch);   cudaGetSymbolAddress(&pcl, g_cl);
    cudaGetSymbolAddress(&pwch, g_wch); cudaGetSymbolAddress(&pwcl, g_wcl);
    cudaGetSymbolAddress(&pwoh, g_woh); cudaGetSymbolAddress(&pwol, g_wol);

    cudaFuncSetAttribute(gemm_mma, cudaFuncAttributeMaxDynamicSharedMemorySize, GEMM_SMEM);
    cudaFuncSetAttribute(slc14, cudaFuncAttributeMaxDynamicSharedMemorySize, SLC14_SMEM);

    // all conversions + pad-zero in one launch
    conv_all<<<4352, 256>>>((const float4*)x, (const float4*)Wq, (const float4*)Wk,
                            (const float4*)Wv, (const float4*)Wg, (const float4*)Wo);

    // fused projections: [Q | K | V | G] = x @ [Wq;Wk;Wv;Wg]^T
    gemm_mma<<<dim3(10, 16), 256, GEMM_SMEM>>>((const __nv_bfloat16*)pxh, (const __nv_bfloat16*)pxl,
                                               (const __nv_bfloat16*)pwch, (const __nv_bfloat16*)pwcl,
                                               (float*)pq, 1);
    pool_kv<<<NB, 64>>>();
    slc14<<<(T_LEN + 13) / 14, 448, SLC14_SMEM>>>();   // fused cmp + topk + selected attn

    // out = comb @ Wo^T
    gemm_mma<<<dim3(8, 16), 256, GEMM_SMEM>>>((const __nv_bfloat16*)pch, (const __nv_bfloat16*)pcl,
                                              (const __nv_bfloat16*)pwoh, (const __nv_bfloat16*)pwol,
                                              out, 0);
}

// round 12
// speedup vs baseline: 1.4335x; 1.0958x over previous
#include <cuda_runtime.h>
#include <cuda_bf16.h>
#include <cstdint>

// ---------------- problem constants ----------------
#define T_LEN 2048
#define DM    1024
#define NHEAD 16
#define HDIM  64
#define NB    32
#define SSEL  16
#define NEGV  (-1e30f)
#define NEGS  (-1.25e29f)

// ---------------- scratch ----------------------------------------------------
__device__ float g_q   [T_LEN * DM];
__device__ float g_k   [T_LEN * HDIM];
__device__ float g_v   [T_LEN * HDIM];
__device__ float g_g   [T_LEN * 48];

__device__ __nv_bfloat16 g_xh [T_LEN * DM], g_xl [T_LEN * DM];
__device__ __nv_bfloat16 g_qh [T_LEN * DM], g_ql [T_LEN * DM];
__device__ __nv_bfloat16 g_ch [T_LEN * DM], g_cl [T_LEN * DM];
__device__ __nv_bfloat16 g_kh [T_LEN * HDIM], g_kl [T_LEN * HDIM];
__device__ __nv_bfloat16 g_vh [T_LEN * HDIM], g_vl [T_LEN * HDIM];
__device__ __nv_bfloat16 g_kch[NB * HDIM], g_kcl[NB * HDIM];
__device__ __nv_bfloat16 g_vch[NB * HDIM], g_vcl[NB * HDIM];
__device__ __nv_bfloat16 g_wch[1280 * DM], g_wcl[1280 * DM];   // stacked Wq|Wk|Wv|Wg|pad
__device__ __nv_bfloat16 g_woh[DM * DM],   g_wol[DM * DM];

// ================= helpers ==================================================
__device__ __forceinline__ uint32_t smem_u32(const void* p) {
    uint32_t a;
    asm("{ .reg .u64 t; cvta.to.shared.u64 t, %1; cvt.u32.u64 %0, t; }"
        : "=r"(a) : "l"(p));
    return a;
}
__device__ __forceinline__ void cp_async16(uint32_t saddr, const void* gaddr) {
    asm volatile("cp.async.cg.shared.global [%0], [%1], 16;"
                 :: "r"(saddr), "l"(gaddr));
}
__device__ __forceinline__ void cp_commit() {
    asm volatile("cp.async.commit_group;" ::: "memory");
}
__device__ __forceinline__ void cp_wait0() {
    asm volatile("cp.async.wait_group 0;" ::: "memory");
}
__device__ __forceinline__ void cp_wait1() {
    asm volatile("cp.async.wait_group 1;" ::: "memory");
}
__device__ __forceinline__ void ldsm4(uint32_t* r, uint32_t addr) {
    asm volatile("ldmatrix.sync.aligned.m8n8.x4.shared.b16 {%0,%1,%2,%3}, [%4];"
                 : "=r"(r[0]), "=r"(r[1]), "=r"(r[2]), "=r"(r[3]) : "r"(addr));
}
__device__ __forceinline__ void ldsm2(uint32_t* r, uint32_t addr) {
    asm volatile("ldmatrix.sync.aligned.m8n8.x2.shared.b16 {%0,%1}, [%2];"
                 : "=r"(r[0]), "=r"(r[1]) : "r"(addr));
}
__device__ __forceinline__ void ldsm4t(uint32_t* r, uint32_t addr) {
    asm volatile("ldmatrix.sync.aligned.m8n8.x4.trans.shared.b16 {%0,%1,%2,%3}, [%4];"
                 : "=r"(r[0]), "=r"(r[1]), "=r"(r[2]), "=r"(r[3]) : "r"(addr));
}
__device__ __forceinline__ void mma16816(float* d, const uint32_t* a, const uint32_t* b) {
    asm volatile(
        "mma.sync.aligned.m16n8k16.row.col.f32.bf16.bf16.f32 "
        "{%0,%1,%2,%3}, {%4,%5,%6,%7}, {%8,%9}, {%0,%1,%2,%3};"
        : "+f"(d[0]), "+f"(d[1]), "+f"(d[2]), "+f"(d[3])
        : "r"(a[0]), "r"(a[1]), "r"(a[2]), "r"(a[3]), "r"(b[0]), "r"(b[1]));
}
__device__ __forceinline__ uint32_t pack_bf16x2(float lo, float hi) {
    uint32_t r;
    asm("cvt.rn.bf16x2.f32 %0, %1, %2;" : "=r"(r) : "f"(hi), "f"(lo));
    return r;
}
__device__ __forceinline__ uint32_t pack_hi(float a, float b, __nv_bfloat16& ha, __nv_bfloat16& hb) {
    ha = __float2bfloat16(a); hb = __float2bfloat16(b);
    return (uint32_t)__bfloat16_as_ushort(ha) | ((uint32_t)__bfloat16_as_ushort(hb) << 16);
}

// ====== single-launch fp32 -> bf16 hi/lo conversion for all weights/x =======
__global__ __launch_bounds__(256) void conv_all(const float4* __restrict__ x,
                                                const float4* __restrict__ Wq,
                                                const float4* __restrict__ Wk,
                                                const float4* __restrict__ Wv,
                                                const float4* __restrict__ Wg,
                                                const float4* __restrict__ Wo) {
    int i = blockIdx.x * 256 + threadIdx.x;
    const float4* src; uint2 *h, *l; int di;
    if (i < 524288)       { src = x;  di = i;           h = (uint2*)g_xh;  l = (uint2*)g_xl; }
    else if (i < 786432)  { src = Wq; di = i - 524288;  h = (uint2*)g_wch; l = (uint2*)g_wcl; }
    else if (i < 802816)  { src = Wk; di = i - 786432;  h = (uint2*)g_wch + 262144; l = (uint2*)g_wcl + 262144; }
    else if (i < 819200)  { src = Wv; di = i - 802816;  h = (uint2*)g_wch + 278528; l = (uint2*)g_wcl + 278528; }
    else if (i < 831488)  { src = Wg; di = i - 819200;  h = (uint2*)g_wch + 294912; l = (uint2*)g_wcl + 294912; }
    else if (i < 1093632) { src = Wo; di = i - 831488;  h = (uint2*)g_woh; l = (uint2*)g_wol; }
    else {
        int dz = i - 1093632;
        uint2 z = make_uint2(0u, 0u);
        ((uint2*)g_wch)[307200 + dz] = z;
        ((uint2*)g_wcl)[307200 + dz] = z;
        return;
    }
    float4 v = src[di];
    __nv_bfloat16 h0, h1, h2, h3;
    uint2 hv, lv;
    hv.x = pack_hi(v.x, v.y, h0, h1);
    hv.y = pack_hi(v.z, v.w, h2, h3);
    lv.x = pack_bf16x2(v.x - __bfloat162float(h0), v.y - __bfloat162float(h1));
    lv.y = pack_bf16x2(v.z - __bfloat162float(h2), v.w - __bfloat162float(h3));
    h[di] = hv;
    l[di] = lv;
}

// ================= tensor-core GEMM via mma.sync (bf16x3, 2-stage) ==========
#define TSTRIDE 80
#define TILE_BYTES (128 * TSTRIDE)
#define BUF_BYTES  (4 * TILE_BYTES)
#define GEMM_SMEM  (2 * BUF_BYTES)

__global__ __launch_bounds__(256, 2) void gemm_mma(const __nv_bfloat16* __restrict__ Ah,
                                                   const __nv_bfloat16* __restrict__ Al,
                                                   const __nv_bfloat16* __restrict__ Bh,
                                                   const __nv_bfloat16* __restrict__ Bl,
                                                   float* __restrict__ C,
                                                   int mode) {
    extern __shared__ char sm[];
    const uint32_t sbase = smem_u32(sm);
    const int tid = threadIdx.x;
    const int lane = tid & 31, wid = tid >> 5;
    const int m0 = blockIdx.y * 128;
    const int n0 = blockIdx.x * 128;
    const int wm = (wid >> 2) * 64;
    const int wn = (wid & 3) * 32;

    const __nv_bfloat16* gsrc[4] = {Ah, Al, Bh, Bl};

    float acc[4][4][4];
#pragma unroll
    for (int i = 0; i < 4; i++)
#pragma unroll
        for (int j = 0; j < 4; j++)
#pragma unroll
            for (int k = 0; k < 4; k++) acc[i][j][k] = 0.f;

    const int arow = wm + (lane & 15);
    const int akc  = (lane >> 4) << 3;
    const int brow = wn + (lane & 7) + ((lane >> 4) << 3);
    const int bkc  = ((lane >> 3) & 1) << 3;

    auto issue = [&](int c, int buf) {
#pragma unroll
        for (int T = 0; T < 4; T++) {
            const __nv_bfloat16* src = gsrc[T];
            const int rb = (T < 2) ? m0 : n0;
#pragma unroll
            for (int i = 0; i < 2; i++) {
                int idx = i * 256 + tid;
                int row = idx >> 2;
                int u   = idx & 3;
                uint32_t sa = sbase + buf * BUF_BYTES + T * TILE_BYTES + row * TSTRIDE + u * 16;
                cp_async16(sa, src + (size_t)(rb + row) * 1024 + c * 32 + u * 8);
            }
        }
        cp_commit();
    };

    issue(0, 0);

    for (int c = 0; c < 32; c++) {
        const int buf = c & 1;
        cp_wait0();
        __syncthreads();
        if (c + 1 < 32) issue(c + 1, buf ^ 1);

        const uint32_t base = sbase + buf * BUF_BYTES;
#pragma unroll
        for (int ks = 0; ks < 2; ks++) {
            uint32_t ah[4][4], al[4][4], bh[2][4], bl[2][4];
#pragma unroll
            for (int mt = 0; mt < 4; mt++) {
                uint32_t aa = base + (arow + mt * 16) * TSTRIDE + (ks * 16 + akc) * 2;
                ldsm4(ah[mt], aa);
                ldsm4(al[mt], aa + TILE_BYTES);
            }
#pragma unroll
            for (int np = 0; np < 2; np++) {
                uint32_t ba = base + 2 * TILE_BYTES + (brow + np * 16) * TSTRIDE + (ks * 16 + bkc) * 2;
                ldsm4(bh[np], ba);
                ldsm4(bl[np], ba + TILE_BYTES);
            }
#pragma unroll
            for (int mt = 0; mt < 4; mt++)
#pragma unroll
                for (int nt = 0; nt < 4; nt++) {
                    const uint32_t* ph = &bh[nt >> 1][(nt & 1) * 2];
                    const uint32_t* pl = &bl[nt >> 1][(nt & 1) * 2];
                    mma16816(acc[mt][nt], ah[mt], ph);
                    mma16816(acc[mt][nt], al[mt], ph);
                    mma16816(acc[mt][nt], ah[mt], pl);
                }
        }
        __syncthreads();
    }

    const int g = lane >> 2, t4 = lane & 3;
#pragma unroll
    for (int mt = 0; mt < 4; mt++)
#pragma unroll
        for (int nt = 0; nt < 4; nt++) {
            int r = m0 + wm + mt * 16 + g;
            int cc = n0 + wn + nt * 8 + t4 * 2;
#pragma unroll
            for (int half = 0; half < 2; half++) {
                int rr = r + half * 8;
                float v0 = acc[mt][nt][half * 2], v1 = acc[mt][nt][half * 2 + 1];
                if (mode == 0) {
                    *(float2*)(C + (size_t)rr * 1024 + cc) = make_float2(v0, v1);
                } else {
                    __nv_bfloat16 b0, b1;
                    if (cc < 1024) {
                        *(float2*)(g_q + (size_t)rr * 1024 + cc) = make_float2(v0, v1);
                        uint32_t hh = pack_hi(v0, v1, b0, b1);
                        *(uint32_t*)(g_qh + (size_t)rr * 1024 + cc) = hh;
                        *(uint32_t*)(g_ql + (size_t)rr * 1024 + cc) =
                            pack_bf16x2(v0 - __bfloat162float(b0), v1 - __bfloat162float(b1));
                    } else if (cc < 1088) {
                        int k = cc - 1024;
                        *(float2*)(g_k + (size_t)rr * 64 + k) = make_float2(v0, v1);
                        uint32_t hh = pack_hi(v0, v1, b0, b1);
                        *(uint32_t*)(g_kh + (size_t)rr * 64 + k) = hh;
                        *(uint32_t*)(g_kl + (size_t)rr * 64 + k) =
                            pack_bf16x2(v0 - __bfloat162float(b0), v1 - __bfloat162float(b1));
                    } else if (cc < 1152) {
                        int k = cc - 1088;
                        *(float2*)(g_v + (size_t)rr * 64 + k) = make_float2(v0, v1);
                        uint32_t hh = pack_hi(v0, v1, b0, b1);
                        *(uint32_t*)(g_vh + (size_t)rr * 64 + k) = hh;
                        *(uint32_t*)(g_vl + (size_t)rr * 64 + k) =
                            pack_bf16x2(v0 - __bfloat162float(b0), v1 - __bfloat162float(b1));
                    } else if (cc < 1200) {
                        int k = cc - 1152;
                        *(float2*)(g_g + (size_t)rr * 48 + k) = make_float2(v0, v1);
                    }
                }
            }
        }
}

// ---------------- mean-pool K,V (bf16 hi/lo) ---------------------------------
__global__ void pool_kv() {
    int c = blockIdx.x, d = threadIdx.x;
    float sk = 0.f, sv = 0.f;
    for (int i = 0; i < 64; i++) {
        sk += g_k[(size_t)(c * 64 + i) * 64 + d];
        sv += g_v[(size_t)(c * 64 + i) * 64 + d];
    }
    sk *= (1.f / 64.f); sv *= (1.f / 64.f);
    int idx = c * 64 + d;
    __nv_bfloat16 hk = __float2bfloat16(sk);
    __nv_bfloat16 hv2 = __float2bfloat16(sv);
    g_kch[idx] = hk; g_kcl[idx] = __float2bfloat16(sk - __bfloat162float(hk));
    g_vch[idx] = hv2; g_vcl[idx] = __float2bfloat16(sv - __bfloat162float(hv2));
}

// ====== FUSED: cmp attn + top-k + union selected attn, 14 tokens/CTA ========
#define SQL14     32256
#define KC14      64512
#define STG14     82944
#define STG_SZ    36864
#define KV_T      9216
#define META14    156672
#define IMP14     (META14 + 256)
#define SLC14_SMEM (IMP14 + 2048)

__global__ __launch_bounds__(448, 1) void slc14() {
    extern __shared__ char smc[];
    const uint32_t sb0 = smem_u32(smc);
    const int tid = threadIdx.x;
    const int lane = tid & 31, w = tid >> 5;
    const int T0 = blockIdx.x * 14;
    const int ntok = min(14, T_LEN - T0);
    const bool act = (w < ntok);
    const int tt = act ? (T0 + w) : (T_LEN - 1);

    uint32_t* smask = (uint32_t*)(smc + META14);
    int* ulist = (int*)(smc + META14 + 128);
    int* ucnt  = (int*)(smc + META14 + 124);
    float* impsm = (float*)(smc + IMP14);

    // ---- stage Q hi/lo ----
#pragma unroll
    for (int i = 0; i < 8; i++) {
        int idx = i * 448 + tid;
        int tile = idx / 1792;
        int wi = idx - tile * 1792;
        int row = wi >> 3, u = wi & 7;
        int token = T0 + (row >> 4);
        if (token > T_LEN - 1) token = T_LEN - 1;
        int head = row & 15;
        size_t go = (size_t)token * 1024 + head * 64 + u * 8;
        cp_async16(sb0 + tile * SQL14 + row * 144 + u * 16, (tile ? g_ql : g_qh) + go);
    }
    // ---- stage pooled Kc/Vc hi/lo ----
#pragma unroll
    for (int i = 0; i < 3; i++) {
        int idx = i * 448 + tid;
        if (idx < 1024) {
            int tile = idx >> 8, r = (idx >> 3) & 31, u = idx & 7;
            const __nv_bfloat16* gp = (tile == 0) ? g_kch : (tile == 1) ? g_kcl
                                    : (tile == 2) ? g_vch : g_vcl;
            cp_async16(sb0 + KC14 + tile * 4608 + r * 144 + u * 16, gp + r * 64 + u * 8);
        }
    }
    cp_commit();

    auto issueKV = [&](int c, int stage) {
        uint32_t base = sb0 + STG14 + stage * STG_SZ;
#pragma unroll
        for (int i = 0; i < 5; i++) {
            int cid = i * 448 + tid;
            if (cid < 2048) {
                int tile = cid >> 9, r = (cid >> 3) & 63, u = cid & 7;
                const __nv_bfloat16* gp = (tile == 0) ? g_kh : (tile == 1) ? g_kl
                                        : (tile == 2) ? g_vh : g_vl;
                cp_async16(base + tile * KV_T + r * 144 + u * 16,
                           gp + (size_t)(c * 64 + r) * 64 + u * 8);
            }
        }
        cp_commit();
    };

    issueKV(0, 0);
    cp_wait1();
    __syncthreads();

    const int nvis = (tt + 1) >> 6;
    const int cur = tt >> 6;

    uint32_t mymsk = 0;
    uint32_t pch0[4], pch1[4], pcl0[4], pcl1[4];

    if (act) {
        // =========== compressed branch: QK over pooled Kc (bf16x3) ===========
        float d4[4][4];
#pragma unroll
        for (int nt = 0; nt < 4; nt++)
#pragma unroll
            for (int j = 0; j < 4; j++) d4[nt][j] = 0.f;

#pragma unroll
        for (int ks = 0; ks < 4; ks++) {
            uint32_t qa = sb0 + (w * 16 + (lane & 15)) * 144 + ((lane >> 4) << 4) + ks * 32;
            uint32_t qh4[4], ql4[4];
            ldsm4(qh4, qa);
            ldsm4(ql4, qa + SQL14);
#pragma unroll
            for (int nt = 0; nt < 4; nt++) {
                uint32_t bh2[2], bl2[2];
                uint32_t ba = sb0 + KC14 + (nt * 8 + (lane & 7)) * 144 + ((lane >> 3) & 1) * 16 + ks * 32;
                ldsm2(bh2, ba);
                ldsm2(bl2, ba + 4608);
                mma16816(d4[nt], qh4, bh2);
                mma16816(d4[nt], ql4, bh2);
                mma16816(d4[nt], qh4, bl2);
            }
        }

        float bm0 = NEGS, bm1 = NEGS;
#pragma unroll
        for (int nt = 0; nt < 4; nt++) {
            int c0 = nt * 8 + ((lane & 3) << 1);
            bool v0 = c0 < nvis, v1 = c0 + 1 < nvis;
            d4[nt][0] = v0 ? d4[nt][0] * 0.125f : NEGS;
            d4[nt][1] = v1 ? d4[nt][1] * 0.125f : NEGS;
            d4[nt][2] = v0 ? d4[nt][2] * 0.125f : NEGS;
            d4[nt][3] = v1 ? d4[nt][3] * 0.125f : NEGS;
            bm0 = fmaxf(bm0, fmaxf(d4[nt][0], d4[nt][1]));
            bm1 = fmaxf(bm1, fmaxf(d4[nt][2], d4[nt][3]));
        }
        bm0 = fmaxf(bm0, __shfl_xor_sync(0xffffffffu, bm0, 1));
        bm0 = fmaxf(bm0, __shfl_xor_sync(0xffffffffu, bm0, 2));
        bm1 = fmaxf(bm1, __shfl_xor_sync(0xffffffffu, bm1, 1));
        bm1 = fmaxf(bm1, __shfl_xor_sync(0xffffffffu, bm1, 2));

        float ps0 = 0.f, ps1 = 0.f;
#pragma unroll
        for (int nt = 0; nt < 4; nt++) {
            d4[nt][0] = __expf(d4[nt][0] - bm0);
            d4[nt][1] = __expf(d4[nt][1] - bm0);
            d4[nt][2] = __expf(d4[nt][2] - bm1);
            d4[nt][3] = __expf(d4[nt][3] - bm1);
            ps0 += d4[nt][0] + d4[nt][1];
            ps1 += d4[nt][2] + d4[nt][3];
        }
        ps0 += __shfl_xor_sync(0xffffffffu, ps0, 1);
        ps0 += __shfl_xor_sync(0xffffffffu, ps0, 2);
        ps1 += __shfl_xor_sync(0xffffffffu, ps1, 1);
        ps1 += __shfl_xor_sync(0xffffffffu, ps1, 2);
        float iv0 = (nvis > 0) ? 1.f / ps0 : 0.f;
        float iv1 = (nvis > 0) ? 1.f / ps1 : 0.f;
#pragma unroll
        for (int nt = 0; nt < 4; nt++) {
            d4[nt][0] *= iv0; d4[nt][1] *= iv0;
            d4[nt][2] *= iv1; d4[nt][3] *= iv1;
        }

#pragma unroll
        for (int nt = 0; nt < 4; nt++) {
            float t0 = d4[nt][0] + d4[nt][2];
            float t1 = d4[nt][1] + d4[nt][3];
            t0 += __shfl_xor_sync(0xffffffffu, t0, 4);
            t0 += __shfl_xor_sync(0xffffffffu, t0, 8);
            t0 += __shfl_xor_sync(0xffffffffu, t0, 16);
            t1 += __shfl_xor_sync(0xffffffffu, t1, 4);
            t1 += __shfl_xor_sync(0xffffffffu, t1, 8);
            t1 += __shfl_xor_sync(0xffffffffu, t1, 16);
            int c0 = nt * 8 + ((lane & 3) << 1);
            impsm[w * 32 + c0] = t0;
            impsm[w * 32 + c0 + 1] = t1;
        }
        __syncwarp();

        {
            float base = impsm[w * 32 + lane];
            float v = (lane == 0 || lane == cur) ? INFINITY
                    : (lane > cur ? NEGV : base);
#pragma unroll
            for (int s = 0; s < SSEL; s++) {
                float bv = v; int bi = lane;
#pragma unroll
                for (int off = 16; off >= 1; off >>= 1) {
                    float ov2 = __shfl_xor_sync(0xffffffffu, bv, off);
                    int   oi = __shfl_xor_sync(0xffffffffu, bi, off);
                    if (ov2 > bv || (ov2 == bv && oi < bi)) { bv = ov2; bi = oi; }
                }
                mymsk |= 1u << bi;
                if (lane == bi) v = -INFINITY;
            }
        }

        {
            float gc0 = 1.f / (1.f + __expf(-g_g[tt * 48 + (lane >> 2) * 3]));
            float gc1 = 1.f / (1.f + __expf(-g_g[tt * 48 + ((lane >> 2) + 8) * 3]));
#pragma unroll
            for (int nt = 0; nt < 4; nt++) {
                float q0 = d4[nt][0] * gc0, q1 = d4[nt][1] * gc0;
                float q2 = d4[nt][2] * gc1, q3 = d4[nt][3] * gc1;
                __nv_bfloat16 b0, b1, b2, b3;
                pch0[nt] = pack_hi(q0, q1, b0, b1);
                pch1[nt] = pack_hi(q2, q3, b2, b3);
                pcl0[nt] = pack_bf16x2(q0 - __bfloat162float(b0), q1 - __bfloat162float(b1));
                pcl1[nt] = pack_bf16x2(q2 - __bfloat162float(b2), q3 - __bfloat162float(b3));
            }
        }
    }
    if (lane == 0 && w < 14) smask[w] = mymsk;

    __syncthreads();
    if (tid == 0) {
        uint32_t u = 0;
        for (int i = 0; i < 14; i++) u |= smask[i];
        int cnt = 0;
        for (int c = 0; c < NB; c++)
            if ((u >> c) & 1u) ulist[cnt++] = c;
        *ucnt = cnt;
    }
    __syncthreads();
    const int nu = *ucnt;

    // =========== selected block-sparse attention over the union ===========
    float ov[8][4];
#pragma unroll
    for (int vt = 0; vt < 8; vt++)
#pragma unroll
        for (int j = 0; j < 4; j++) ov[vt][j] = 0.f;
    float mrow[2] = {NEGS, NEGS};
    float srow[2] = {0.f, 0.f};

    for (int i = 0; i < nu; i++) {
        cp_wait0();
        __syncthreads();
        if (i + 1 < nu) issueKV(ulist[i + 1], (i + 1) & 1);

        const int c = ulist[i];
        if ((mymsk >> c) & 1u) {
            const uint32_t base = sb0 + STG14 + (i & 1) * STG_SZ;

            float d[8][4];
#pragma unroll
            for (int nt = 0; nt < 8; nt++)
#pragma unroll
                for (int j = 0; j < 4; j++) d[nt][j] = 0.f;

#pragma unroll
            for (int ks = 0; ks < 4; ks++) {
                uint32_t qa = sb0 + (w * 16 + (lane & 15)) * 144 + ((lane >> 4) << 4) + ks * 32;
                uint32_t qh4[4], ql4[4];
                ldsm4(qh4, qa);
                ldsm4(ql4, qa + SQL14);
#pragma unroll
                for (int nt = 0; nt < 8; nt++) {
                    uint32_t bh2[2], bl2[2];
                    uint32_t ba = base + (nt * 8 + (lane & 7)) * 144 + ((lane >> 3) & 1) * 16 + ks * 32;
                    ldsm2(bh2, ba);
                    ldsm2(bl2, ba + KV_T);
                    mma16816(d[nt], qh4, bh2);
                    mma16816(d[nt], ql4, bh2);
                    mma16816(d[nt], qh4, bl2);
                }
            }

            const int colb = c * 64 + ((lane & 3) << 1);
            float bq0 = NEGS, bq1 = NEGS;
#pragma unroll
            for (int nt = 0; nt < 8; nt++) {
                int tok0 = colb + nt * 8;
                bool v0 = tok0 <= tt, v1 = tok0 + 1 <= tt;
                d[nt][0] = v0 ? d[nt][0] * 0.125f : NEGS;
                d[nt][1] = v1 ? d[nt][1] * 0.125f : NEGS;
                d[nt][2] = v0 ? d[nt][2] * 0.125f : NEGS;
                d[nt][3] = v1 ? d[nt][3] * 0.125f : NEGS;
                bq0 = fmaxf(bq0, fmaxf(d[nt][0], d[nt][1]));
                bq1 = fmaxf(bq1, fmaxf(d[nt][2], d[nt][3]));
            }
            bq0 = fmaxf(bq0, __shfl_xor_sync(0xffffffffu, bq0, 1));
            bq0 = fmaxf(bq0, __shfl_xor_sync(0xffffffffu, bq0, 2));
            bq1 = fmaxf(bq1, __shfl_xor_sync(0xffffffffu, bq1, 1));
            bq1 = fmaxf(bq1, __shfl_xor_sync(0xffffffffu, bq1, 2));
            float mn0 = fmaxf(mrow[0], bq0), mn1 = fmaxf(mrow[1], bq1);
            float a0 = __expf(mrow[0] - mn0), a1 = __expf(mrow[1] - mn1);
            mrow[0] = mn0; mrow[1] = mn1;
            srow[0] *= a0; srow[1] *= a1;
#pragma unroll
            for (int vt = 0; vt < 8; vt++) {
                ov[vt][0] *= a0; ov[vt][1] *= a0;
                ov[vt][2] *= a1; ov[vt][3] *= a1;
            }

            // ---- exp + PV via m16n8k16 over token-octet PAIRS (bf16x3) ----
#pragma unroll
            for (int ntp = 0; ntp < 4; ntp++) {
                const int ntE = ntp * 2, ntO = ntE + 1;
                float pE0 = __expf(d[ntE][0] - mrow[0]);
                float pE1 = __expf(d[ntE][1] - mrow[0]);
                float pE2 = __expf(d[ntE][2] - mrow[1]);
                float pE3 = __expf(d[ntE][3] - mrow[1]);
                float pO0 = __expf(d[ntO][0] - mrow[0]);
                float pO1 = __expf(d[ntO][1] - mrow[0]);
                float pO2 = __expf(d[ntO][2] - mrow[1]);
                float pO3 = __expf(d[ntO][3] - mrow[1]);
                srow[0] += pE0 + pE1 + pO0 + pO1;
                srow[1] += pE2 + pE3 + pO2 + pO3;
                __nv_bfloat16 b0, b1, b2, b3, b4, b5, b6, b7;
                uint32_t Ah4[4], Al4[4];
                Ah4[0] = pack_hi(pE0, pE1, b0, b1);   // row g,  k 0-7
                Ah4[1] = pack_hi(pE2, pE3, b2, b3);   // row g+8, k 0-7
                Ah4[2] = pack_hi(pO0, pO1, b4, b5);   // row g,  k 8-15
                Ah4[3] = pack_hi(pO2, pO3, b6, b7);   // row g+8, k 8-15
                Al4[0] = pack_bf16x2(pE0 - __bfloat162float(b0), pE1 - __bfloat162float(b1));
                Al4[1] = pack_bf16x2(pE2 - __bfloat162float(b2), pE3 - __bfloat162float(b3));
                Al4[2] = pack_bf16x2(pO0 - __bfloat162float(b4), pO1 - __bfloat162float(b5));
                Al4[3] = pack_bf16x2(pO2 - __bfloat162float(b6), pO3 - __bfloat162float(b7));

                uint32_t vE[8], vO[8];
                uint32_t vaE = base + 2 * KV_T + (ntE * 8 + (lane & 7)) * 144 + (lane >> 3) * 16;
                uint32_t vaO = vaE + 8 * 144;
                ldsm4t(vE, vaE);     ldsm4t(vE + 4, vaE + 64);
                ldsm4t(vO, vaO);     ldsm4t(vO + 4, vaO + 64);
#pragma unroll
                for (int vt = 0; vt < 8; vt++) {
                    uint32_t bb[2] = {vE[vt], vO[vt]};
                    mma16816(ov[vt], Ah4, bb);
                    mma16816(ov[vt], Al4, bb);
                }
                ldsm4t(vE, vaE + KV_T);  ldsm4t(vE + 4, vaE + KV_T + 64);
                ldsm4t(vO, vaO + KV_T);  ldsm4t(vO + 4, vaO + KV_T + 64);
#pragma unroll
                for (int vt = 0; vt < 8; vt++) {
                    uint32_t bb[2] = {vE[vt], vO[vt]};
                    mma16816(ov[vt], Ah4, bb);
                }
            }
        }
        // NOTE: no bottom barrier — next iteration's top sync provides WAR ordering
    }

    if (act) {
        {
            float s0 = srow[0], s1 = srow[1];
            s0 += __shfl_xor_sync(0xffffffffu, s0, 1);
            s0 += __shfl_xor_sync(0xffffffffu, s0, 2);
            s1 += __shfl_xor_sync(0xffffffffu, s1, 1);
            s1 += __shfl_xor_sync(0xffffffffu, s1, 2);
            float gs0 = 1.f / (1.f + __expf(-g_g[tt * 48 + (lane >> 2) * 3 + 1]));
            float gs1 = 1.f / (1.f + __expf(-g_g[tt * 48 + ((lane >> 2) + 8) * 3 + 1]));
            float f0 = gs0 / s0, f1 = gs1 / s1;
#pragma unroll
            for (int vt = 0; vt < 8; vt++) {
                ov[vt][0] *= f0; ov[vt][1] *= f0;
                ov[vt][2] *= f1; ov[vt][3] *= f1;
            }
        }
        // cmp PV via m16n8k16 pairs: ov += (p_cmp*gc) @ Vc
#pragma unroll
        for (int kp = 0; kp < 2; kp++) {
            const int kE = kp * 2, kO = kE + 1;
            uint32_t A_h[4] = {pch0[kE], pch1[kE], pch0[kO], pch1[kO]};
            uint32_t A_l[4] = {pcl0[kE], pcl1[kE], pcl0[kO], pcl1[kO]};
            uint32_t vE[8], vO[8];
            uint32_t vaE = sb0 + KC14 + 9216 + (kE * 8 + (lane & 7)) * 144 + (lane >> 3) * 16;
            uint32_t vaO = vaE + 8 * 144;
            ldsm4t(vE, vaE);     ldsm4t(vE + 4, vaE + 64);
            ldsm4t(vO, vaO);     ldsm4t(vO + 4, vaO + 64);
#pragma unroll
            for (int vt = 0; vt < 8; vt++) {
                uint32_t bb[2] = {vE[vt], vO[vt]};
                mma16816(ov[vt], A_h, bb);
                mma16816(ov[vt], A_l, bb);
            }
            ldsm4t(vE, vaE + 4608);  ldsm4t(vE + 4, vaE + 4608 + 64);
            ldsm4t(vO, vaO + 4608);  ldsm4t(vO + 4, vaO + 4608 + 64);
#pragma unroll
            for (int vt = 0; vt < 8; vt++) {
                uint32_t bb[2] = {vE[vt], vO[vt]};
                mma16816(ov[vt], A_h, bb);
            }
        }

        // ---- write comb as bf16 hi/lo ----
#pragma unroll
        for (int half = 0; half < 2; half++) {
            int h = (lane >> 2) + half * 8;
#pragma unroll
            for (int vt = 0; vt < 8; vt++) {
                int col = vt * 8 + ((lane & 3) << 1);
                size_t off = (size_t)tt * 1024 + h * 64 + col;
                float c0 = ov[vt][half * 2], c1 = ov[vt][half * 2 + 1];
                __nv_bfloat16 b0, b1;
                *(uint32_t*)(g_ch + off) = pack_hi(c0, c1, b0, b1);
                *(uint32_t*)(g_cl + off) =
                    pack_bf16x2(c0 - __bfloat162float(b0), c1 - __bfloat162float(b1));
            }
        }
    }
}

// ---------------- launch ----------------------------------------------------
extern "C" void kernel_launch(void* const* d_in, const int* in_sizes, int n_in,
                              void* d_out, int out_size) {
    const float* x  = (const float*)d_in[0];
    const float* Wq = (const float*)d_in[1];
    const float* Wk = (const float*)d_in[2];
    const float* Wv = (const float*)d_in[3];
    const float* Wg = (const float*)d_in[4];
    const float* Wo = (const float*)d_in[5];
    float* out = (float*)d_out;

    void *pq, *pxh, *pxl, *pch, *pcl, *pwch, *pwcl, *pwoh, *pwol;
    cudaGetSymbolAddress(&pq, g_q);
    cudaGetSymbolAddress(&pxh, g_xh);   cudaGetSymbolAddress(&pxl, g_xl);
    cudaGetSymbolAddress(&pch, g_ch);   cudaGetSymbolAddress(&pcl, g_cl);
    cudaGetSymbolAddress(&pwch, g_wch); cudaGetSymbolAddress(&pwcl, g_wcl);
    cudaGetSymbolAddress(&pwoh, g_woh); cudaGetSymbolAddress(&pwol, g_wol);

    cudaFuncSetAttribute(gemm_mma, cudaFuncAttributeMaxDynamicSharedMemorySize, GEMM_SMEM);
    cudaFuncSetAttribute(slc14, cudaFuncAttributeMaxDynamicSharedMemorySize, SLC14_SMEM);

    conv_all<<<4352, 256>>>((const float4*)x, (const float4*)Wq, (const float4*)Wk,
                            (const float4*)Wv, (const float4*)Wg, (const float4*)Wo);

    gemm_mma<<<dim3(10, 16), 256, GEMM_SMEM>>>((const __nv_bfloat16*)pxh, (const __nv_bfloat16*)pxl,
                                               (const __nv_bfloat16*)pwch, (const __nv_bfloat16*)pwcl,
                                               (float*)pq, 1);
    pool_kv<<<NB, 64>>>();
    slc14<<<(T_LEN + 13) / 14, 448, SLC14_SMEM>>>();

    gemm_mma<<<dim3(8, 16), 256, GEMM_SMEM>>>((const __nv_bfloat16*)pch, (const __nv_bfloat16*)pcl,
                                              (const __nv_bfloat16*)pwoh, (const __nv_bfloat16*)pwol,
                                              out, 0);
}

// round 14
// speedup vs baseline: 1.4849x; 1.0358x over previous
#include <cuda_runtime.h>
#include <cuda_bf16.h>
#include <cstdint>

// ---------------- problem constants ----------------
#define T_LEN 2048
#define DM    1024
#define NHEAD 16
#define HDIM  64
#define NB    32
#define SSEL  16
#define NEGV  (-1e30f)
#define NEGS  (-1.25e29f)

// ---------------- scratch ----------------------------------------------------
__device__ float g_q   [T_LEN * DM];
__device__ float g_k   [T_LEN * HDIM];
__device__ float g_v   [T_LEN * HDIM];
__device__ float g_g   [T_LEN * 48];

__device__ __nv_bfloat16 g_xh [T_LEN * DM], g_xl [T_LEN * DM];
__device__ __nv_bfloat16 g_qh [T_LEN * DM], g_ql [T_LEN * DM];
__device__ __nv_bfloat16 g_ch [T_LEN * DM], g_cl [T_LEN * DM];
__device__ __nv_bfloat16 g_kh [T_LEN * HDIM], g_kl [T_LEN * HDIM];
__device__ __nv_bfloat16 g_vh [T_LEN * HDIM], g_vl [T_LEN * HDIM];
__device__ __nv_bfloat16 g_kch[NB * HDIM], g_kcl[NB * HDIM];
__device__ __nv_bfloat16 g_vch[NB * HDIM], g_vcl[NB * HDIM];
__device__ __nv_bfloat16 g_wch[1280 * DM], g_wcl[1280 * DM];
__device__ __nv_bfloat16 g_woh[DM * DM],   g_wol[DM * DM];

// ================= helpers ==================================================
__device__ __forceinline__ uint32_t smem_u32(const void* p) {
    uint32_t a;
    asm("{ .reg .u64 t; cvta.to.shared.u64 t, %1; cvt.u32.u64 %0, t; }"
        : "=r"(a) : "l"(p));
    return a;
}
__device__ __forceinline__ void cp_async16(uint32_t saddr, const void* gaddr) {
    asm volatile("cp.async.cg.shared.global [%0], [%1], 16;"
                 :: "r"(saddr), "l"(gaddr));
}
__device__ __forceinline__ void cp_commit() {
    asm volatile("cp.async.commit_group;" ::: "memory");
}
__device__ __forceinline__ void cp_wait0() {
    asm volatile("cp.async.wait_group 0;" ::: "memory");
}
__device__ __forceinline__ void cp_wait1() {
    asm volatile("cp.async.wait_group 1;" ::: "memory");
}
__device__ __forceinline__ void ldsm4(uint32_t* r, uint32_t addr) {
    asm volatile("ldmatrix.sync.aligned.m8n8.x4.shared.b16 {%0,%1,%2,%3}, [%4];"
                 : "=r"(r[0]), "=r"(r[1]), "=r"(r[2]), "=r"(r[3]) : "r"(addr));
}
__device__ __forceinline__ void ldsm4t(uint32_t* r, uint32_t addr) {
    asm volatile("ldmatrix.sync.aligned.m8n8.x4.trans.shared.b16 {%0,%1,%2,%3}, [%4];"
                 : "=r"(r[0]), "=r"(r[1]), "=r"(r[2]), "=r"(r[3]) : "r"(addr));
}
__device__ __forceinline__ void mma16816(float* d, const uint32_t* a, const uint32_t* b) {
    asm volatile(
        "mma.sync.aligned.m16n8k16.row.col.f32.bf16.bf16.f32 "
        "{%0,%1,%2,%3}, {%4,%5,%6,%7}, {%8,%9}, {%0,%1,%2,%3};"
        : "+f"(d[0]), "+f"(d[1]), "+f"(d[2]), "+f"(d[3])
        : "r"(a[0]), "r"(a[1]), "r"(a[2]), "r"(a[3]), "r"(b[0]), "r"(b[1]));
}
__device__ __forceinline__ uint32_t pack_bf16x2(float lo, float hi) {
    uint32_t r;
    asm("cvt.rn.bf16x2.f32 %0, %1, %2;" : "=r"(r) : "f"(hi), "f"(lo));
    return r;
}
__device__ __forceinline__ uint32_t pack_hi(float a, float b, __nv_bfloat16& ha, __nv_bfloat16& hb) {
    ha = __float2bfloat16(a); hb = __float2bfloat16(b);
    return (uint32_t)__bfloat16_as_ushort(ha) | ((uint32_t)__bfloat16_as_ushort(hb) << 16);
}

// ====== single-launch fp32 -> bf16 hi/lo conversion for all weights/x =======
__global__ __launch_bounds__(256) void conv_all(const float4* __restrict__ x,
                                                const float4* __restrict__ Wq,
                                                const float4* __restrict__ Wk,
                                                const float4* __restrict__ Wv,
                                                const float4* __restrict__ Wg,
                                                const float4* __restrict__ Wo) {
    int i = blockIdx.x * 256 + threadIdx.x;
    const float4* src; uint2 *h, *l; int di;
    if (i < 524288)       { src = x;  di = i;           h = (uint2*)g_xh;  l = (uint2*)g_xl; }
    else if (i < 786432)  { src = Wq; di = i - 524288;  h = (uint2*)g_wch; l = (uint2*)g_wcl; }
    else if (i < 802816)  { src = Wk; di = i - 786432;  h = (uint2*)g_wch + 262144; l = (uint2*)g_wcl + 262144; }
    else if (i < 819200)  { src = Wv; di = i - 802816;  h = (uint2*)g_wch + 278528; l = (uint2*)g_wcl + 278528; }
    else if (i < 831488)  { src = Wg; di = i - 819200;  h = (uint2*)g_wch + 294912; l = (uint2*)g_wcl + 294912; }
    else if (i < 1093632) { src = Wo; di = i - 831488;  h = (uint2*)g_woh; l = (uint2*)g_wol; }
    else {
        int dz = i - 1093632;
        uint2 z = make_uint2(0u, 0u);
        ((uint2*)g_wch)[307200 + dz] = z;
        ((uint2*)g_wcl)[307200 + dz] = z;
        return;
    }
    float4 v = src[di];
    __nv_bfloat16 h0, h1, h2, h3;
    uint2 hv, lv;
    hv.x = pack_hi(v.x, v.y, h0, h1);
    hv.y = pack_hi(v.z, v.w, h2, h3);
    lv.x = pack_bf16x2(v.x - __bfloat162float(h0), v.y - __bfloat162float(h1));
    lv.y = pack_bf16x2(v.z - __bfloat162float(h2), v.w - __bfloat162float(h3));
    h[di] = hv;
    l[di] = lv;
}

// ================= tensor-core GEMM via mma.sync (bf16x3, 2-stage) ==========
#define TSTRIDE 80
#define TILE_BYTES (128 * TSTRIDE)
#define BUF_BYTES  (4 * TILE_BYTES)
#define GEMM_SMEM  (2 * BUF_BYTES)

__global__ __launch_bounds__(256, 2) void gemm_mma(const __nv_bfloat16* __restrict__ Ah,
                                                   const __nv_bfloat16* __restrict__ Al,
                                                   const __nv_bfloat16* __restrict__ Bh,
                                                   const __nv_bfloat16* __restrict__ Bl,
                                                   float* __restrict__ C,
                                                   int mode) {
    extern __shared__ char sm[];
    const uint32_t sbase = smem_u32(sm);
    const int tid = threadIdx.x;
    const int lane = tid & 31, wid = tid >> 5;
    const int m0 = blockIdx.y * 128;
    const int n0 = blockIdx.x * 128;
    const int wm = (wid >> 2) * 64;
    const int wn = (wid & 3) * 32;

    const __nv_bfloat16* gsrc[4] = {Ah, Al, Bh, Bl};

    float acc[4][4][4];
#pragma unroll
    for (int i = 0; i < 4; i++)
#pragma unroll
        for (int j = 0; j < 4; j++)
#pragma unroll
            for (int k = 0; k < 4; k++) acc[i][j][k] = 0.f;

    const int arow = wm + (lane & 15);
    const int akc  = (lane >> 4) << 3;
    const int brow = wn + (lane & 7) + ((lane >> 4) << 3);
    const int bkc  = ((lane >> 3) & 1) << 3;

    auto issue = [&](int c, int buf) {
#pragma unroll
        for (int T = 0; T < 4; T++) {
            const __nv_bfloat16* src = gsrc[T];
            const int rb = (T < 2) ? m0 : n0;
#pragma unroll
            for (int i = 0; i < 2; i++) {
                int idx = i * 256 + tid;
                int row = idx >> 2;
                int u   = idx & 3;
                uint32_t sa = sbase + buf * BUF_BYTES + T * TILE_BYTES + row * TSTRIDE + u * 16;
                cp_async16(sa, src + (size_t)(rb + row) * 1024 + c * 32 + u * 8);
            }
        }
        cp_commit();
    };

    issue(0, 0);

    for (int c = 0; c < 32; c++) {
        const int buf = c & 1;
        cp_wait0();
        __syncthreads();
        if (c + 1 < 32) issue(c + 1, buf ^ 1);

        const uint32_t base = sbase + buf * BUF_BYTES;
#pragma unroll
        for (int ks = 0; ks < 2; ks++) {
            uint32_t ah[4][4], al[4][4], bh[2][4], bl[2][4];
#pragma unroll
            for (int mt = 0; mt < 4; mt++) {
                uint32_t aa = base + (arow + mt * 16) * TSTRIDE + (ks * 16 + akc) * 2;
                ldsm4(ah[mt], aa);
                ldsm4(al[mt], aa + TILE_BYTES);
            }
#pragma unroll
            for (int np = 0; np < 2; np++) {
                uint32_t ba = base + 2 * TILE_BYTES + (brow + np * 16) * TSTRIDE + (ks * 16 + bkc) * 2;
                ldsm4(bh[np], ba);
                ldsm4(bl[np], ba + TILE_BYTES);
            }
#pragma unroll
            for (int mt = 0; mt < 4; mt++)
#pragma unroll
                for (int nt = 0; nt < 4; nt++) {
                    const uint32_t* ph = &bh[nt >> 1][(nt & 1) * 2];
                    const uint32_t* pl = &bl[nt >> 1][(nt & 1) * 2];
                    mma16816(acc[mt][nt], ah[mt], ph);
                    mma16816(acc[mt][nt], al[mt], ph);
                    mma16816(acc[mt][nt], ah[mt], pl);
                }
        }
        __syncthreads();
    }

    const int g = lane >> 2, t4 = lane & 3;
#pragma unroll
    for (int mt = 0; mt < 4; mt++)
#pragma unroll
        for (int nt = 0; nt < 4; nt++) {
            int r = m0 + wm + mt * 16 + g;
            int cc = n0 + wn + nt * 8 + t4 * 2;
#pragma unroll
            for (int half = 0; half < 2; half++) {
                int rr = r + half * 8;
                float v0 = acc[mt][nt][half * 2], v1 = acc[mt][nt][half * 2 + 1];
                if (mode == 0) {
                    *(float2*)(C + (size_t)rr * 1024 + cc) = make_float2(v0, v1);
                } else {
                    __nv_bfloat16 b0, b1;
                    if (cc < 1024) {
                        *(float2*)(g_q + (size_t)rr * 1024 + cc) = make_float2(v0, v1);
                        uint32_t hh = pack_hi(v0, v1, b0, b1);
                        *(uint32_t*)(g_qh + (size_t)rr * 1024 + cc) = hh;
                        *(uint32_t*)(g_ql + (size_t)rr * 1024 + cc) =
                            pack_bf16x2(v0 - __bfloat162float(b0), v1 - __bfloat162float(b1));
                    } else if (cc < 1088) {
                        int k = cc - 1024;
                        *(float2*)(g_k + (size_t)rr * 64 + k) = make_float2(v0, v1);
                        uint32_t hh = pack_hi(v0, v1, b0, b1);
                        *(uint32_t*)(g_kh + (size_t)rr * 64 + k) = hh;
                        *(uint32_t*)(g_kl + (size_t)rr * 64 + k) =
                            pack_bf16x2(v0 - __bfloat162float(b0), v1 - __bfloat162float(b1));
                    } else if (cc < 1152) {
                        int k = cc - 1088;
                        *(float2*)(g_v + (size_t)rr * 64 + k) = make_float2(v0, v1);
                        uint32_t hh = pack_hi(v0, v1, b0, b1);
                        *(uint32_t*)(g_vh + (size_t)rr * 64 + k) = hh;
                        *(uint32_t*)(g_vl + (size_t)rr * 64 + k) =
                            pack_bf16x2(v0 - __bfloat162float(b0), v1 - __bfloat162float(b1));
                    } else if (cc < 1200) {
                        int k = cc - 1152;
                        *(float2*)(g_g + (size_t)rr * 48 + k) = make_float2(v0, v1);
                    }
                }
            }
        }
}

// ---------------- mean-pool K,V (bf16 hi/lo) ---------------------------------
__global__ void pool_kv() {
    int c = blockIdx.x, d = threadIdx.x;
    float sk = 0.f, sv = 0.f;
    for (int i = 0; i < 64; i++) {
        sk += g_k[(size_t)(c * 64 + i) * 64 + d];
        sv += g_v[(size_t)(c * 64 + i) * 64 + d];
    }
    sk *= (1.f / 64.f); sv *= (1.f / 64.f);
    int idx = c * 64 + d;
    __nv_bfloat16 hk = __float2bfloat16(sk);
    __nv_bfloat16 hv2 = __float2bfloat16(sv);
    g_kch[idx] = hk; g_kcl[idx] = __float2bfloat16(sk - __bfloat162float(hk));
    g_vch[idx] = hv2; g_vcl[idx] = __float2bfloat16(sv - __bfloat162float(hv2));
}

// ====== FUSED: cmp attn + top-k + union selected attn, 14 tokens/CTA ========
#define SQL14     32256
#define KC14      64512
#define STG14     82944
#define STG_SZ    36864
#define KV_T      9216
#define META14    156672
#define IMP14     (META14 + 256)
#define SLC14_SMEM (IMP14 + 2048)

__global__ __launch_bounds__(448, 1) void slc14() {
    extern __shared__ char smc[];
    const uint32_t sb0 = smem_u32(smc);
    const int tid = threadIdx.x;
    const int lane = tid & 31, w = tid >> 5;
    const int T0 = blockIdx.x * 14;
    const int ntok = min(14, T_LEN - T0);
    const bool act = (w < ntok);
    const int tt = act ? (T0 + w) : (T_LEN - 1);

    uint32_t* smask = (uint32_t*)(smc + META14);
    int* ulist = (int*)(smc + META14 + 128);
    int* ucnt  = (int*)(smc + META14 + 124);
    float* impsm = (float*)(smc + IMP14);

    // ---- stage Q hi/lo ----
#pragma unroll
    for (int i = 0; i < 8; i++) {
        int idx = i * 448 + tid;
        int tile = idx / 1792;
        int wi = idx - tile * 1792;
        int row = wi >> 3, u = wi & 7;
        int token = T0 + (row >> 4);
        if (token > T_LEN - 1) token = T_LEN - 1;
        int head = row & 15;
        size_t go = (size_t)token * 1024 + head * 64 + u * 8;
        cp_async16(sb0 + tile * SQL14 + row * 144 + u * 16, (tile ? g_ql : g_qh) + go);
    }
    // ---- stage pooled Kc/Vc hi/lo ----
#pragma unroll
    for (int i = 0; i < 3; i++) {
        int idx = i * 448 + tid;
        if (idx < 1024) {
            int tile = idx >> 8, r = (idx >> 3) & 31, u = idx & 7;
            const __nv_bfloat16* gp = (tile == 0) ? g_kch : (tile == 1) ? g_kcl
                                    : (tile == 2) ? g_vch : g_vcl;
            cp_async16(sb0 + KC14 + tile * 4608 + r * 144 + u * 16, gp + r * 64 + u * 8);
        }
    }
    cp_commit();

    auto issueKV = [&](int c, int stage) {
        uint32_t base = sb0 + STG14 + stage * STG_SZ;
#pragma unroll
        for (int i = 0; i < 5; i++) {
            int cid = i * 448 + tid;
            if (cid < 2048) {
                int tile = cid >> 9, r = (cid >> 3) & 63, u = cid & 7;
                const __nv_bfloat16* gp = (tile == 0) ? g_kh : (tile == 1) ? g_kl
                                        : (tile == 2) ? g_vh : g_vl;
                cp_async16(base + tile * KV_T + r * 144 + u * 16,
                           gp + (size_t)(c * 64 + r) * 64 + u * 8);
            }
        }
        cp_commit();
    };

    issueKV(0, 0);
    cp_wait1();
    __syncthreads();

    const int nvis = (tt + 1) >> 6;
    const int cur = tt >> 6;

    uint32_t mymsk = 0;
    uint32_t pch0[4], pch1[4], pcl0[4], pcl1[4];

    // B-frag ldsm4 lane addressing offset (row within nt-pair, k-half select)
    const uint32_t bln = (((lane >> 4) << 3) + (lane & 7)) * 144 + ((lane >> 3) & 1) * 16;

    if (act) {
        // =========== compressed branch: QK over pooled Kc (bf16x3) ===========
        float d4[4][4];
#pragma unroll
        for (int nt = 0; nt < 4; nt++)
#pragma unroll
            for (int j = 0; j < 4; j++) d4[nt][j] = 0.f;

#pragma unroll
        for (int ks = 0; ks < 4; ks++) {
            uint32_t qa = sb0 + (w * 16 + (lane & 15)) * 144 + ((lane >> 4) << 4) + ks * 32;
            uint32_t qh4[4], ql4[4];
            ldsm4(qh4, qa);
            ldsm4(ql4, qa + SQL14);
#pragma unroll
            for (int ntp = 0; ntp < 2; ntp++) {
                uint32_t bh4[4], bl4[4];
                uint32_t ba = sb0 + KC14 + ntp * 16 * 144 + bln + ks * 32;
                ldsm4(bh4, ba);
                ldsm4(bl4, ba + 4608);
                mma16816(d4[ntp * 2],     qh4, bh4);
                mma16816(d4[ntp * 2],     ql4, bh4);
                mma16816(d4[ntp * 2],     qh4, bl4);
                mma16816(d4[ntp * 2 + 1], qh4, bh4 + 2);
                mma16816(d4[ntp * 2 + 1], ql4, bh4 + 2);
                mma16816(d4[ntp * 2 + 1], qh4, bl4 + 2);
            }
        }

        float bm0 = NEGS, bm1 = NEGS;
#pragma unroll
        for (int nt = 0; nt < 4; nt++) {
            int c0 = nt * 8 + ((lane & 3) << 1);
            bool v0 = c0 < nvis, v1 = c0 + 1 < nvis;
            d4[nt][0] = v0 ? d4[nt][0] * 0.125f : NEGS;
            d4[nt][1] = v1 ? d4[nt][1] * 0.125f : NEGS;
            d4[nt][2] = v0 ? d4[nt][2] * 0.125f : NEGS;
            d4[nt][3] = v1 ? d4[nt][3] * 0.125f : NEGS;
            bm0 = fmaxf(bm0, fmaxf(d4[nt][0], d4[nt][1]));
            bm1 = fmaxf(bm1, fmaxf(d4[nt][2], d4[nt][3]));
        }
        bm0 = fmaxf(bm0, __shfl_xor_sync(0xffffffffu, bm0, 1));
        bm0 = fmaxf(bm0, __shfl_xor_sync(0xffffffffu, bm0, 2));
        bm1 = fmaxf(bm1, __shfl_xor_sync(0xffffffffu, bm1, 1));
        bm1 = fmaxf(bm1, __shfl_xor_sync(0xffffffffu, bm1, 2));

        float ps0 = 0.f, ps1 = 0.f;
#pragma unroll
        for (int nt = 0; nt < 4; nt++) {
            d4[nt][0] = __expf(d4[nt][0] - bm0);
            d4[nt][1] = __expf(d4[nt][1] - bm0);
            d4[nt][2] = __expf(d4[nt][2] - bm1);
            d4[nt][3] = __expf(d4[nt][3] - bm1);
            ps0 += d4[nt][0] + d4[nt][1];
            ps1 += d4[nt][2] + d4[nt][3];
        }
        ps0 += __shfl_xor_sync(0xffffffffu, ps0, 1);
        ps0 += __shfl_xor_sync(0xffffffffu, ps0, 2);
        ps1 += __shfl_xor_sync(0xffffffffu, ps1, 1);
        ps1 += __shfl_xor_sync(0xffffffffu, ps1, 2);
        float iv0 = (nvis > 0) ? 1.f / ps0 : 0.f;
        float iv1 = (nvis > 0) ? 1.f / ps1 : 0.f;
#pragma unroll
        for (int nt = 0; nt < 4; nt++) {
            d4[nt][0] *= iv0; d4[nt][1] *= iv0;
            d4[nt][2] *= iv1; d4[nt][3] *= iv1;
        }

#pragma unroll
        for (int nt = 0; nt < 4; nt++) {
            float t0 = d4[nt][0] + d4[nt][2];
            float t1 = d4[nt][1] + d4[nt][3];
            t0 += __shfl_xor_sync(0xffffffffu, t0, 4);
            t0 += __shfl_xor_sync(0xffffffffu, t0, 8);
            t0 += __shfl_xor_sync(0xffffffffu, t0, 16);
            t1 += __shfl_xor_sync(0xffffffffu, t1, 4);
            t1 += __shfl_xor_sync(0xffffffffu, t1, 8);
            t1 += __shfl_xor_sync(0xffffffffu, t1, 16);
            int c0 = nt * 8 + ((lane & 3) << 1);
            impsm[w * 32 + c0] = t0;
            impsm[w * 32 + c0 + 1] = t1;
        }
        __syncwarp();

        {
            float base = impsm[w * 32 + lane];
            float v = (lane == 0 || lane == cur) ? INFINITY
                    : (lane > cur ? NEGV : base);
#pragma unroll
            for (int s = 0; s < SSEL; s++) {
                float bv = v; int bi = lane;
#pragma unroll
                for (int off = 16; off >= 1; off >>= 1) {
                    float ov2 = __shfl_xor_sync(0xffffffffu, bv, off);
                    int   oi = __shfl_xor_sync(0xffffffffu, bi, off);
                    if (ov2 > bv || (ov2 == bv && oi < bi)) { bv = ov2; bi = oi; }
                }
                mymsk |= 1u << bi;
                if (lane == bi) v = -INFINITY;
            }
        }

        {
            float gc0 = 1.f / (1.f + __expf(-g_g[tt * 48 + (lane >> 2) * 3]));
            float gc1 = 1.f / (1.f + __expf(-g_g[tt * 48 + ((lane >> 2) + 8) * 3]));
#pragma unroll
            for (int nt = 0; nt < 4; nt++) {
                float q0 = d4[nt][0] * gc0, q1 = d4[nt][1] * gc0;
                float q2 = d4[nt][2] * gc1, q3 = d4[nt][3] * gc1;
                __nv_bfloat16 b0, b1, b2, b3;
                pch0[nt] = pack_hi(q0, q1, b0, b1);
                pch1[nt] = pack_hi(q2, q3, b2, b3);
                pcl0[nt] = pack_bf16x2(q0 - __bfloat162float(b0), q1 - __bfloat162float(b1));
                pcl1[nt] = pack_bf16x2(q2 - __bfloat162float(b2), q3 - __bfloat162float(b3));
            }
        }
    }
    if (lane == 0 && w < 14) smask[w] = mymsk;

    __syncthreads();
    if (tid == 0) {
        uint32_t u = 0;
        for (int i = 0; i < 14; i++) u |= smask[i];
        int cnt = 0;
        for (int c = 0; c < NB; c++)
            if ((u >> c) & 1u) ulist[cnt++] = c;
        *ucnt = cnt;
    }
    __syncthreads();
    const int nu = *ucnt;

    // =========== selected block-sparse attention over the union ===========
    float ov[8][4];
#pragma unroll
    for (int vt = 0; vt < 8; vt++)
#pragma unroll
        for (int j = 0; j < 4; j++) ov[vt][j] = 0.f;
    float mrow[2] = {NEGS, NEGS};
    float srow[2] = {0.f, 0.f};

    for (int i = 0; i < nu; i++) {
        cp_wait0();
        __syncthreads();
        if (i + 1 < nu) issueKV(ulist[i + 1], (i + 1) & 1);

        const int c = ulist[i];
        // skip unselected AND fully-future blocks (future: contribution exactly 0
        // because block 0 processed first makes mrow finite -> p underflows to 0)
        if (((mymsk >> c) & 1u) && c <= cur) {
            const uint32_t base = sb0 + STG14 + (i & 1) * STG_SZ;

            float d[8][4];
#pragma unroll
            for (int nt = 0; nt < 8; nt++)
#pragma unroll
                for (int j = 0; j < 4; j++) d[nt][j] = 0.f;

#pragma unroll
            for (int ks = 0; ks < 4; ks++) {
                uint32_t qa = sb0 + (w * 16 + (lane & 15)) * 144 + ((lane >> 4) << 4) + ks * 32;
                uint32_t qh4[4], ql4[4];
                ldsm4(qh4, qa);
                ldsm4(ql4, qa + SQL14);
#pragma unroll
                for (int ntp = 0; ntp < 4; ntp++) {
                    uint32_t bh4[4], bl4[4];
                    uint32_t ba = base + ntp * 16 * 144 + bln + ks * 32;
                    ldsm4(bh4, ba);
                    ldsm4(bl4, ba + KV_T);
                    mma16816(d[ntp * 2],     qh4, bh4);
                    mma16816(d[ntp * 2],     ql4, bh4);
                    mma16816(d[ntp * 2],     qh4, bl4);
                    mma16816(d[ntp * 2 + 1], qh4, bh4 + 2);
                    mma16816(d[ntp * 2 + 1], ql4, bh4 + 2);
                    mma16816(d[ntp * 2 + 1], qh4, bl4 + 2);
                }
            }

            // ---- scale (+ causal mask only when c == cur) + block max ----
            float bq0 = NEGS, bq1 = NEGS;
            if (c == cur) {
                const int colb = c * 64 + ((lane & 3) << 1);
#pragma unroll
                for (int nt = 0; nt < 8; nt++) {
                    int tok0 = colb + nt * 8;
                    bool v0 = tok0 <= tt, v1 = tok0 + 1 <= tt;
                    d[nt][0] = v0 ? d[nt][0] * 0.125f : NEGS;
                    d[nt][1] = v1 ? d[nt][1] * 0.125f : NEGS;
                    d[nt][2] = v0 ? d[nt][2] * 0.125f : NEGS;
                    d[nt][3] = v1 ? d[nt][3] * 0.125f : NEGS;
                    bq0 = fmaxf(bq0, fmaxf(d[nt][0], d[nt][1]));
                    bq1 = fmaxf(bq1, fmaxf(d[nt][2], d[nt][3]));
                }
            } else {
#pragma unroll
                for (int nt = 0; nt < 8; nt++) {
                    d[nt][0] *= 0.125f; d[nt][1] *= 0.125f;
                    d[nt][2] *= 0.125f; d[nt][3] *= 0.125f;
                    bq0 = fmaxf(bq0, fmaxf(d[nt][0], d[nt][1]));
                    bq1 = fmaxf(bq1, fmaxf(d[nt][2], d[nt][3]));
                }
            }
            bq0 = fmaxf(bq0, __shfl_xor_sync(0xffffffffu, bq0, 1));
            bq0 = fmaxf(bq0, __shfl_xor_sync(0xffffffffu, bq0, 2));
            bq1 = fmaxf(bq1, __shfl_xor_sync(0xffffffffu, bq1, 1));
            bq1 = fmaxf(bq1, __shfl_xor_sync(0xffffffffu, bq1, 2));
            float mn0 = fmaxf(mrow[0], bq0), mn1 = fmaxf(mrow[1], bq1);
            float a0 = __expf(mrow[0] - mn0), a1 = __expf(mrow[1] - mn1);
            mrow[0] = mn0; mrow[1] = mn1;
            // skip identity rescale (a==1 exact when max unchanged)
            if (__any_sync(0xffffffffu, (a0 != 1.f) | (a1 != 1.f))) {
                srow[0] *= a0; srow[1] *= a1;
#pragma unroll
                for (int vt = 0; vt < 8; vt++) {
                    ov[vt][0] *= a0; ov[vt][1] *= a0;
                    ov[vt][2] *= a1; ov[vt][3] *= a1;
                }
            }

            // ---- exp + PV via m16n8k16 over token-octet PAIRS (bf16x3) ----
#pragma unroll
            for (int ntp = 0; ntp < 4; ntp++) {
                const int ntE = ntp * 2, ntO = ntE + 1;
                float pE0 = __expf(d[ntE][0] - mrow[0]);
                float pE1 = __expf(d[ntE][1] - mrow[0]);
                float pE2 = __expf(d[ntE][2] - mrow[1]);
                float pE3 = __expf(d[ntE][3] - mrow[1]);
                float pO0 = __expf(d[ntO][0] - mrow[0]);
                float pO1 = __expf(d[ntO][1] - mrow[0]);
                float pO2 = __expf(d[ntO][2] - mrow[1]);
                float pO3 = __expf(d[ntO][3] - mrow[1]);
                srow[0] += pE0 + pE1 + pO0 + pO1;
                srow[1] += pE2 + pE3 + pO2 + pO3;
                __nv_bfloat16 b0, b1, b2, b3, b4, b5, b6, b7;
                uint32_t Ah4[4], Al4[4];
                Ah4[0] = pack_hi(pE0, pE1, b0, b1);
                Ah4[1] = pack_hi(pE2, pE3, b2, b3);
                Ah4[2] = pack_hi(pO0, pO1, b4, b5);
                Ah4[3] = pack_hi(pO2, pO3, b6, b7);
                Al4[0] = pack_bf16x2(pE0 - __bfloat162float(b0), pE1 - __bfloat162float(b1));
                Al4[1] = pack_bf16x2(pE2 - __bfloat162float(b2), pE3 - __bfloat162float(b3));
                Al4[2] = pack_bf16x2(pO0 - __bfloat162float(b4), pO1 - __bfloat162float(b5));
                Al4[3] = pack_bf16x2(pO2 - __bfloat162float(b6), pO3 - __bfloat162float(b7));

                uint32_t vE[8], vO[8];
                uint32_t vaE = base + 2 * KV_T + (ntE * 8 + (lane & 7)) * 144 + (lane >> 3) * 16;
                uint32_t vaO = vaE + 8 * 144;
                ldsm4t(vE, vaE);     ldsm4t(vE + 4, vaE + 64);
                ldsm4t(vO, vaO);     ldsm4t(vO + 4, vaO + 64);
#pragma unroll
                for (int vt = 0; vt < 8; vt++) {
                    uint32_t bb[2] = {vE[vt], vO[vt]};
                    mma16816(ov[vt], Ah4, bb);
                    mma16816(ov[vt], Al4, bb);
                }
                ldsm4t(vE, vaE + KV_T);  ldsm4t(vE + 4, vaE + KV_T + 64);
                ldsm4t(vO, vaO + KV_T);  ldsm4t(vO + 4, vaO + KV_T + 64);
#pragma unroll
                for (int vt = 0; vt < 8; vt++) {
                    uint32_t bb[2] = {vE[vt], vO[vt]};
                    mma16816(ov[vt], Ah4, bb);
                }
            }
        }
    }

    if (act) {
        {
            float s0 = srow[0], s1 = srow[1];
            s0 += __shfl_xor_sync(0xffffffffu, s0, 1);
            s0 += __shfl_xor_sync(0xffffffffu, s0, 2);
            s1 += __shfl_xor_sync(0xffffffffu, s1, 1);
            s1 += __shfl_xor_sync(0xffffffffu, s1, 2);
            float gs0 = 1.f / (1.f + __expf(-g_g[tt * 48 + (lane >> 2) * 3 + 1]));
            float gs1 = 1.f / (1.f + __expf(-g_g[tt * 48 + ((lane >> 2) + 8) * 3 + 1]));
            float f0 = gs0 / s0, f1 = gs1 / s1;
#pragma unroll
            for (int vt = 0; vt < 8; vt++) {
                ov[vt][0] *= f0; ov[vt][1] *= f0;
                ov[vt][2] *= f1; ov[vt][3] *= f1;
            }
        }
        // cmp PV via m16n8k16 pairs: ov += (p_cmp*gc) @ Vc
#pragma unroll
        for (int kp = 0; kp < 2; kp++) {
            const int kE = kp * 2, kO = kE + 1;
            uint32_t A_h[4] = {pch0[kE], pch1[kE], pch0[kO], pch1[kO]};
            uint32_t A_l[4] = {pcl0[kE], pcl1[kE], pcl0[kO], pcl1[kO]};
            uint32_t vE[8], vO[8];
            uint32_t vaE = sb0 + KC14 + 9216 + (kE * 8 + (lane & 7)) * 144 + (lane >> 3) * 16;
            uint32_t vaO = vaE + 8 * 144;
            ldsm4t(vE, vaE);     ldsm4t(vE + 4, vaE + 64);
            ldsm4t(vO, vaO);     ldsm4t(vO + 4, vaO + 64);
#pragma unroll
            for (int vt = 0; vt < 8; vt++) {
                uint32_t bb[2] = {vE[vt], vO[vt]};
                mma16816(ov[vt], A_h, bb);
                mma16816(ov[vt], A_l, bb);
            }
            ldsm4t(vE, vaE + 4608);  ldsm4t(vE + 4, vaE + 4608 + 64);
            ldsm4t(vO, vaO + 4608);  ldsm4t(vO + 4, vaO + 4608 + 64);
#pragma unroll
            for (int vt = 0; vt < 8; vt++) {
                uint32_t bb[2] = {vE[vt], vO[vt]};
                mma16816(ov[vt], A_h, bb);
            }
        }

        // ---- write comb as bf16 hi/lo ----
#pragma unroll
        for (int half = 0; half < 2; half++) {
            int h = (lane >> 2) + half * 8;
#pragma unroll
            for (int vt = 0; vt < 8; vt++) {
                int col = vt * 8 + ((lane & 3) << 1);
                size_t off = (size_t)tt * 1024 + h * 64 + col;
                float c0 = ov[vt][half * 2], c1 = ov[vt][half * 2 + 1];
                __nv_bfloat16 b0, b1;
                *(uint32_t*)(g_ch + off) = pack_hi(c0, c1, b0, b1);
                *(uint32_t*)(g_cl + off) =
                    pack_bf16x2(c0 - __bfloat162float(b0), c1 - __bfloat162float(b1));
            }
        }
    }
}

// ---------------- launch ----------------------------------------------------
extern "C" void kernel_launch(void* const* d_in, const int* in_sizes, int n_in,
                              void* d_out, int out_size) {
    const float* x  = (const float*)d_in[0];
    const float* Wq = (const float*)d_in[1];
    const float* Wk = (const float*)d_in[2];
    const float* Wv = (const float*)d_in[3];
    const float* Wg = (const float*)d_in[4];
    const float* Wo = (const float*)d_in[5];
    float* out = (float*)d_out;

    void *pq, *pxh, *pxl, *pch, *pcl, *pwch, *pwcl, *pwoh, *pwol;
    cudaGetSymbolAddress(&pq, g_q);
    cudaGetSymbolAddress(&pxh, g_xh);   cudaGetSymbolAddress(&pxl, g_xl);
    cudaGetSymbolAddress(&pch, g_ch);   cudaGetSymbolAddress(&pcl, g_cl);
    cudaGetSymbolAddress(&pwch, g_wch); cudaGetSymbolAddress(&pwcl, g_wcl);
    cudaGetSymbolAddress(&pwoh, g_woh); cudaGetSymbolAddress(&pwol, g_wol);

    cudaFuncSetAttribute(gemm_mma, cudaFuncAttributeMaxDynamicSharedMemorySize, GEMM_SMEM);
    cudaFuncSetAttribute(slc14, cudaFuncAttributeMaxDynamicSharedMemorySize, SLC14_SMEM);

    conv_all<<<4352, 256>>>((const float4*)x, (const float4*)Wq, (const float4*)Wk,
                            (const float4*)Wv, (const float4*)Wg, (const float4*)Wo);

    gemm_mma<<<dim3(10, 16), 256, GEMM_SMEM>>>((const __nv_bfloat16*)pxh, (const __nv_bfloat16*)pxl,
                                               (const __nv_bfloat16*)pwch, (const __nv_bfloat16*)pwcl,
                                               (float*)pq, 1);
    pool_kv<<<NB, 64>>>();
    slc14<<<(T_LEN + 13) / 14, 448, SLC14_SMEM>>>();

    gemm_mma<<<dim3(8, 16), 256, GEMM_SMEM>>>((const __nv_bfloat16*)pch, (const __nv_bfloat16*)pcl,
                                              (const __nv_bfloat16*)pwoh, (const __nv_bfloat16*)pwol,
                                              out, 0);
}

// round 15
// speedup vs baseline: 1.5253x; 1.0273x over previous
#include <cuda_runtime.h>
#include <cuda_bf16.h>
#include <cstdint>

// ---------------- problem constants ----------------
#define T_LEN 2048
#define DM    1024
#define NHEAD 16
#define HDIM  64
#define NB    32
#define SSEL  16
#define NEGV  (-1e30f)
#define NEGS  (-1.25e29f)
#define SEXP  0.180336880f   // 0.125 * log2(e); p = ex2(d * SEXP) = e^(d/8)

// ---------------- scratch ----------------------------------------------------
__device__ float g_q   [T_LEN * DM];
__device__ float g_k   [T_LEN * HDIM];
__device__ float g_v   [T_LEN * HDIM];
__device__ float g_g   [T_LEN * 48];

__device__ __nv_bfloat16 g_xh [T_LEN * DM], g_xl [T_LEN * DM];
__device__ __nv_bfloat16 g_qh [T_LEN * DM], g_ql [T_LEN * DM];
__device__ __nv_bfloat16 g_ch [T_LEN * DM], g_cl [T_LEN * DM];
__device__ __nv_bfloat16 g_kh [T_LEN * HDIM], g_kl [T_LEN * HDIM];
__device__ __nv_bfloat16 g_vh [T_LEN * HDIM], g_vl [T_LEN * HDIM];
__device__ __nv_bfloat16 g_kch[NB * HDIM], g_kcl[NB * HDIM];
__device__ __nv_bfloat16 g_vch[NB * HDIM], g_vcl[NB * HDIM];
__device__ __nv_bfloat16 g_wch[1280 * DM], g_wcl[1280 * DM];
__device__ __nv_bfloat16 g_woh[DM * DM],   g_wol[DM * DM];

// ================= helpers ==================================================
__device__ __forceinline__ uint32_t smem_u32(const void* p) {
    uint32_t a;
    asm("{ .reg .u64 t; cvta.to.shared.u64 t, %1; cvt.u32.u64 %0, t; }"
        : "=r"(a) : "l"(p));
    return a;
}
__device__ __forceinline__ void cp_async16(uint32_t saddr, const void* gaddr) {
    asm volatile("cp.async.cg.shared.global [%0], [%1], 16;"
                 :: "r"(saddr), "l"(gaddr));
}
__device__ __forceinline__ void cp_commit() {
    asm volatile("cp.async.commit_group;" ::: "memory");
}
__device__ __forceinline__ void cp_wait0() {
    asm volatile("cp.async.wait_group 0;" ::: "memory");
}
__device__ __forceinline__ void cp_wait1() {
    asm volatile("cp.async.wait_group 1;" ::: "memory");
}
__device__ __forceinline__ void ldsm4(uint32_t* r, uint32_t addr) {
    asm volatile("ldmatrix.sync.aligned.m8n8.x4.shared.b16 {%0,%1,%2,%3}, [%4];"
                 : "=r"(r[0]), "=r"(r[1]), "=r"(r[2]), "=r"(r[3]) : "r"(addr));
}
__device__ __forceinline__ void ldsm4t(uint32_t* r, uint32_t addr) {
    asm volatile("ldmatrix.sync.aligned.m8n8.x4.trans.shared.b16 {%0,%1,%2,%3}, [%4];"
                 : "=r"(r[0]), "=r"(r[1]), "=r"(r[2]), "=r"(r[3]) : "r"(addr));
}
__device__ __forceinline__ void mma16816(float* d, const uint32_t* a, const uint32_t* b) {
    asm volatile(
        "mma.sync.aligned.m16n8k16.row.col.f32.bf16.bf16.f32 "
        "{%0,%1,%2,%3}, {%4,%5,%6,%7}, {%8,%9}, {%0,%1,%2,%3};"
        : "+f"(d[0]), "+f"(d[1]), "+f"(d[2]), "+f"(d[3])
        : "r"(a[0]), "r"(a[1]), "r"(a[2]), "r"(a[3]), "r"(b[0]), "r"(b[1]));
}
__device__ __forceinline__ uint32_t pack_bf16x2(float lo, float hi) {
    uint32_t r;
    asm("cvt.rn.bf16x2.f32 %0, %1, %2;" : "=r"(r) : "f"(hi), "f"(lo));
    return r;
}
__device__ __forceinline__ uint32_t pack_hi(float a, float b, __nv_bfloat16& ha, __nv_bfloat16& hb) {
    ha = __float2bfloat16(a); hb = __float2bfloat16(b);
    return (uint32_t)__bfloat16_as_ushort(ha) | ((uint32_t)__bfloat16_as_ushort(hb) << 16);
}
__device__ __forceinline__ float fexp2(float x) {
    float y;
    asm("ex2.approx.f32 %0, %1;" : "=f"(y) : "f"(x));
    return y;
}

// ====== single-launch fp32 -> bf16 hi/lo conversion for all weights/x =======
__global__ __launch_bounds__(256) void conv_all(const float4* __restrict__ x,
                                                const float4* __restrict__ Wq,
                                                const float4* __restrict__ Wk,
                                                const float4* __restrict__ Wv,
                                                const float4* __restrict__ Wg,
                                                const float4* __restrict__ Wo) {
    int i = blockIdx.x * 256 + threadIdx.x;
    const float4* src; uint2 *h, *l; int di;
    if (i < 524288)       { src = x;  di = i;           h = (uint2*)g_xh;  l = (uint2*)g_xl; }
    else if (i < 786432)  { src = Wq; di = i - 524288;  h = (uint2*)g_wch; l = (uint2*)g_wcl; }
    else if (i < 802816)  { src = Wk; di = i - 786432;  h = (uint2*)g_wch + 262144; l = (uint2*)g_wcl + 262144; }
    else if (i < 819200)  { src = Wv; di = i - 802816;  h = (uint2*)g_wch + 278528; l = (uint2*)g_wcl + 278528; }
    else if (i < 831488)  { src = Wg; di = i - 819200;  h = (uint2*)g_wch + 294912; l = (uint2*)g_wcl + 294912; }
    else if (i < 1093632) { src = Wo; di = i - 831488;  h = (uint2*)g_woh; l = (uint2*)g_wol; }
    else {
        int dz = i - 1093632;
        uint2 z = make_uint2(0u, 0u);
        ((uint2*)g_wch)[307200 + dz] = z;
        ((uint2*)g_wcl)[307200 + dz] = z;
        return;
    }
    float4 v = src[di];
    __nv_bfloat16 h0, h1, h2, h3;
    uint2 hv, lv;
    hv.x = pack_hi(v.x, v.y, h0, h1);
    hv.y = pack_hi(v.z, v.w, h2, h3);
    lv.x = pack_bf16x2(v.x - __bfloat162float(h0), v.y - __bfloat162float(h1));
    lv.y = pack_bf16x2(v.z - __bfloat162float(h2), v.w - __bfloat162float(h3));
    h[di] = hv;
    l[di] = lv;
}

// ================= tensor-core GEMM via mma.sync (bf16x3, 2-stage) ==========
#define TSTRIDE 80
#define TILE_BYTES (128 * TSTRIDE)
#define BUF_BYTES  (4 * TILE_BYTES)
#define GEMM_SMEM  (2 * BUF_BYTES)

__global__ __launch_bounds__(256, 2) void gemm_mma(const __nv_bfloat16* __restrict__ Ah,
                                                   const __nv_bfloat16* __restrict__ Al,
                                                   const __nv_bfloat16* __restrict__ Bh,
                                                   const __nv_bfloat16* __restrict__ Bl,
                                                   float* __restrict__ C,
                                                   int mode) {
    extern __shared__ char sm[];
    const uint32_t sbase = smem_u32(sm);
    const int tid = threadIdx.x;
    const int lane = tid & 31, wid = tid >> 5;
    const int m0 = blockIdx.y * 128;
    const int n0 = blockIdx.x * 128;
    const int wm = (wid >> 2) * 64;
    const int wn = (wid & 3) * 32;

    const __nv_bfloat16* gsrc[4] = {Ah, Al, Bh, Bl};

    float acc[4][4][4];
#pragma unroll
    for (int i = 0; i < 4; i++)
#pragma unroll
        for (int j = 0; j < 4; j++)
#pragma unroll
            for (int k = 0; k < 4; k++) acc[i][j][k] = 0.f;

    const int arow = wm + (lane & 15);
    const int akc  = (lane >> 4) << 3;
    const int brow = wn + (lane & 7) + ((lane >> 4) << 3);
    const int bkc  = ((lane >> 3) & 1) << 3;

    auto issue = [&](int c, int buf) {
#pragma unroll
        for (int T = 0; T < 4; T++) {
            const __nv_bfloat16* src = gsrc[T];
            const int rb = (T < 2) ? m0 : n0;
#pragma unroll
            for (int i = 0; i < 2; i++) {
                int idx = i * 256 + tid;
                int row = idx >> 2;
                int u   = idx & 3;
                uint32_t sa = sbase + buf * BUF_BYTES + T * TILE_BYTES + row * TSTRIDE + u * 16;
                cp_async16(sa, src + (size_t)(rb + row) * 1024 + c * 32 + u * 8);
            }
        }
        cp_commit();
    };

    issue(0, 0);

    for (int c = 0; c < 32; c++) {
        const int buf = c & 1;
        cp_wait0();
        __syncthreads();
        if (c + 1 < 32) issue(c + 1, buf ^ 1);

        const uint32_t base = sbase + buf * BUF_BYTES;
#pragma unroll
        for (int ks = 0; ks < 2; ks++) {
            uint32_t ah[4][4], al[4][4], bh[2][4], bl[2][4];
#pragma unroll
            for (int mt = 0; mt < 4; mt++) {
                uint32_t aa = base + (arow + mt * 16) * TSTRIDE + (ks * 16 + akc) * 2;
                ldsm4(ah[mt], aa);
                ldsm4(al[mt], aa + TILE_BYTES);
            }
#pragma unroll
            for (int np = 0; np < 2; np++) {
                uint32_t ba = base + 2 * TILE_BYTES + (brow + np * 16) * TSTRIDE + (ks * 16 + bkc) * 2;
                ldsm4(bh[np], ba);
                ldsm4(bl[np], ba + TILE_BYTES);
            }
#pragma unroll
            for (int mt = 0; mt < 4; mt++)
#pragma unroll
                for (int nt = 0; nt < 4; nt++) {
                    const uint32_t* ph = &bh[nt >> 1][(nt & 1) * 2];
                    const uint32_t* pl = &bl[nt >> 1][(nt & 1) * 2];
                    mma16816(acc[mt][nt], ah[mt], ph);
                    mma16816(acc[mt][nt], al[mt], ph);
                    mma16816(acc[mt][nt], ah[mt], pl);
                }
        }
        __syncthreads();
    }

    const int g = lane >> 2, t4 = lane & 3;
#pragma unroll
    for (int mt = 0; mt < 4; mt++)
#pragma unroll
        for (int nt = 0; nt < 4; nt++) {
            int r = m0 + wm + mt * 16 + g;
            int cc = n0 + wn + nt * 8 + t4 * 2;
#pragma unroll
            for (int half = 0; half < 2; half++) {
                int rr = r + half * 8;
                float v0 = acc[mt][nt][half * 2], v1 = acc[mt][nt][half * 2 + 1];
                if (mode == 0) {
                    *(float2*)(C + (size_t)rr * 1024 + cc) = make_float2(v0, v1);
                } else {
                    __nv_bfloat16 b0, b1;
                    if (cc < 1024) {
                        *(float2*)(g_q + (size_t)rr * 1024 + cc) = make_float2(v0, v1);
                        uint32_t hh = pack_hi(v0, v1, b0, b1);
                        *(uint32_t*)(g_qh + (size_t)rr * 1024 + cc) = hh;
                        *(uint32_t*)(g_ql + (size_t)rr * 1024 + cc) =
                            pack_bf16x2(v0 - __bfloat162float(b0), v1 - __bfloat162float(b1));
                    } else if (cc < 1088) {
                        int k = cc - 1024;
                        *(float2*)(g_k + (size_t)rr * 64 + k) = make_float2(v0, v1);
                        uint32_t hh = pack_hi(v0, v1, b0, b1);
                        *(uint32_t*)(g_kh + (size_t)rr * 64 + k) = hh;
                        *(uint32_t*)(g_kl + (size_t)rr * 64 + k) =
                            pack_bf16x2(v0 - __bfloat162float(b0), v1 - __bfloat162float(b1));
                    } else if (cc < 1152) {
                        int k = cc - 1088;
                        *(float2*)(g_v + (size_t)rr * 64 + k) = make_float2(v0, v1);
                        uint32_t hh = pack_hi(v0, v1, b0, b1);
                        *(uint32_t*)(g_vh + (size_t)rr * 64 + k) = hh;
                        *(uint32_t*)(g_vl + (size_t)rr * 64 + k) =
                            pack_bf16x2(v0 - __bfloat162float(b0), v1 - __bfloat162float(b1));
                    } else if (cc < 1200) {
                        int k = cc - 1152;
                        *(float2*)(g_g + (size_t)rr * 48 + k) = make_float2(v0, v1);
                    }
                }
            }
        }
}

// ---------------- mean-pool K,V (bf16 hi/lo) ---------------------------------
__global__ void pool_kv() {
    int c = blockIdx.x, d = threadIdx.x;
    float sk = 0.f, sv = 0.f;
    for (int i = 0; i < 64; i++) {
        sk += g_k[(size_t)(c * 64 + i) * 64 + d];
        sv += g_v[(size_t)(c * 64 + i) * 64 + d];
    }
    sk *= (1.f / 64.f); sv *= (1.f / 64.f);
    int idx = c * 64 + d;
    __nv_bfloat16 hk = __float2bfloat16(sk);
    __nv_bfloat16 hv2 = __float2bfloat16(sv);
    g_kch[idx] = hk; g_kcl[idx] = __float2bfloat16(sk - __bfloat162float(hk));
    g_vch[idx] = hv2; g_vcl[idx] = __float2bfloat16(sv - __bfloat162float(hv2));
}

// ====== FUSED: cmp attn + top-k + union selected attn, 14 tokens/CTA ========
#define SQL14     32256
#define KC14      64512
#define STG14     82944
#define STG_SZ    36864
#define KV_T      9216
#define META14    156672
#define IMP14     (META14 + 256)
#define SLC14_SMEM (IMP14 + 2048)

__global__ __launch_bounds__(448, 1) void slc14() {
    extern __shared__ char smc[];
    const uint32_t sb0 = smem_u32(smc);
    const int tid = threadIdx.x;
    const int lane = tid & 31, w = tid >> 5;
    const int T0 = blockIdx.x * 14;
    const int ntok = min(14, T_LEN - T0);
    const bool act = (w < ntok);
    const int tt = act ? (T0 + w) : (T_LEN - 1);

    uint32_t* smask = (uint32_t*)(smc + META14);
    int* ulist = (int*)(smc + META14 + 128);
    int* ucnt  = (int*)(smc + META14 + 124);
    float* impsm = (float*)(smc + IMP14);

    // ---- stage Q hi/lo ----
#pragma unroll
    for (int i = 0; i < 8; i++) {
        int idx = i * 448 + tid;
        int tile = idx / 1792;
        int wi = idx - tile * 1792;
        int row = wi >> 3, u = wi & 7;
        int token = T0 + (row >> 4);
        if (token > T_LEN - 1) token = T_LEN - 1;
        int head = row & 15;
        size_t go = (size_t)token * 1024 + head * 64 + u * 8;
        cp_async16(sb0 + tile * SQL14 + row * 144 + u * 16, (tile ? g_ql : g_qh) + go);
    }
    // ---- stage pooled Kc/Vc hi/lo ----
#pragma unroll
    for (int i = 0; i < 3; i++) {
        int idx = i * 448 + tid;
        if (idx < 1024) {
            int tile = idx >> 8, r = (idx >> 3) & 31, u = idx & 7;
            const __nv_bfloat16* gp = (tile == 0) ? g_kch : (tile == 1) ? g_kcl
                                    : (tile == 2) ? g_vch : g_vcl;
            cp_async16(sb0 + KC14 + tile * 4608 + r * 144 + u * 16, gp + r * 64 + u * 8);
        }
    }
    cp_commit();

    auto issueKV = [&](int c, int stage) {
        uint32_t base = sb0 + STG14 + stage * STG_SZ;
#pragma unroll
        for (int i = 0; i < 5; i++) {
            int cid = i * 448 + tid;
            if (cid < 2048) {
                int tile = cid >> 9, r = (cid >> 3) & 63, u = cid & 7;
                const __nv_bfloat16* gp = (tile == 0) ? g_kh : (tile == 1) ? g_kl
                                        : (tile == 2) ? g_vh : g_vl;
                cp_async16(base + tile * KV_T + r * 144 + u * 16,
                           gp + (size_t)(c * 64 + r) * 64 + u * 8);
            }
        }
        cp_commit();
    };

    issueKV(0, 0);
    cp_wait1();
    __syncthreads();

    const int nvis = (tt + 1) >> 6;
    const int cur = tt >> 6;

    uint32_t mymsk = 0;
    uint32_t pch0[4], pch1[4], pcl0[4], pcl1[4];

    const uint32_t bln = (((lane >> 4) << 3) + (lane & 7)) * 144 + ((lane >> 3) & 1) * 16;

    if (act) {
        // =========== compressed branch: QK over pooled Kc (bf16x3) ===========
        float d4[4][4];
#pragma unroll
        for (int nt = 0; nt < 4; nt++)
#pragma unroll
            for (int j = 0; j < 4; j++) d4[nt][j] = 0.f;

#pragma unroll
        for (int ks = 0; ks < 4; ks++) {
            uint32_t qa = sb0 + (w * 16 + (lane & 15)) * 144 + ((lane >> 4) << 4) + ks * 32;
            uint32_t qh4[4], ql4[4];
            ldsm4(qh4, qa);
            ldsm4(ql4, qa + SQL14);
#pragma unroll
            for (int ntp = 0; ntp < 2; ntp++) {
                uint32_t bh4[4], bl4[4];
                uint32_t ba = sb0 + KC14 + ntp * 16 * 144 + bln + ks * 32;
                ldsm4(bh4, ba);
                ldsm4(bl4, ba + 4608);
                mma16816(d4[ntp * 2],     qh4, bh4);
                mma16816(d4[ntp * 2],     ql4, bh4);
                mma16816(d4[ntp * 2],     qh4, bl4);
                mma16816(d4[ntp * 2 + 1], qh4, bh4 + 2);
                mma16816(d4[ntp * 2 + 1], ql4, bh4 + 2);
                mma16816(d4[ntp * 2 + 1], qh4, bl4 + 2);
            }
        }

        float bm0 = NEGS, bm1 = NEGS;
#pragma unroll
        for (int nt = 0; nt < 4; nt++) {
            int c0 = nt * 8 + ((lane & 3) << 1);
            bool v0 = c0 < nvis, v1 = c0 + 1 < nvis;
            d4[nt][0] = v0 ? d4[nt][0] * 0.125f : NEGS;
            d4[nt][1] = v1 ? d4[nt][1] * 0.125f : NEGS;
            d4[nt][2] = v0 ? d4[nt][2] * 0.125f : NEGS;
            d4[nt][3] = v1 ? d4[nt][3] * 0.125f : NEGS;
            bm0 = fmaxf(bm0, fmaxf(d4[nt][0], d4[nt][1]));
            bm1 = fmaxf(bm1, fmaxf(d4[nt][2], d4[nt][3]));
        }
        bm0 = fmaxf(bm0, __shfl_xor_sync(0xffffffffu, bm0, 1));
        bm0 = fmaxf(bm0, __shfl_xor_sync(0xffffffffu, bm0, 2));
        bm1 = fmaxf(bm1, __shfl_xor_sync(0xffffffffu, bm1, 1));
        bm1 = fmaxf(bm1, __shfl_xor_sync(0xffffffffu, bm1, 2));

        float ps0 = 0.f, ps1 = 0.f;
#pragma unroll
        for (int nt = 0; nt < 4; nt++) {
            d4[nt][0] = __expf(d4[nt][0] - bm0);
            d4[nt][1] = __expf(d4[nt][1] - bm0);
            d4[nt][2] = __expf(d4[nt][2] - bm1);
            d4[nt][3] = __expf(d4[nt][3] - bm1);
            ps0 += d4[nt][0] + d4[nt][1];
            ps1 += d4[nt][2] + d4[nt][3];
        }
        ps0 += __shfl_xor_sync(0xffffffffu, ps0, 1);
        ps0 += __shfl_xor_sync(0xffffffffu, ps0, 2);
        ps1 += __shfl_xor_sync(0xffffffffu, ps1, 1);
        ps1 += __shfl_xor_sync(0xffffffffu, ps1, 2);
        float iv0 = (nvis > 0) ? 1.f / ps0 : 0.f;
        float iv1 = (nvis > 0) ? 1.f / ps1 : 0.f;
#pragma unroll
        for (int nt = 0; nt < 4; nt++) {
            d4[nt][0] *= iv0; d4[nt][1] *= iv0;
            d4[nt][2] *= iv1; d4[nt][3] *= iv1;
        }

#pragma unroll
        for (int nt = 0; nt < 4; nt++) {
            float t0 = d4[nt][0] + d4[nt][2];
            float t1 = d4[nt][1] + d4[nt][3];
            t0 += __shfl_xor_sync(0xffffffffu, t0, 4);
            t0 += __shfl_xor_sync(0xffffffffu, t0, 8);
            t0 += __shfl_xor_sync(0xffffffffu, t0, 16);
            t1 += __shfl_xor_sync(0xffffffffu, t1, 4);
            t1 += __shfl_xor_sync(0xffffffffu, t1, 8);
            t1 += __shfl_xor_sync(0xffffffffu, t1, 16);
            int c0 = nt * 8 + ((lane & 3) << 1);
            impsm[w * 32 + c0] = t0;
            impsm[w * 32 + c0 + 1] = t1;
        }
        __syncwarp();

        {
            float base = impsm[w * 32 + lane];
            float v = (lane == 0 || lane == cur) ? INFINITY
                    : (lane > cur ? NEGV : base);
#pragma unroll
            for (int s = 0; s < SSEL; s++) {
                float bv = v; int bi = lane;
#pragma unroll
                for (int off = 16; off >= 1; off >>= 1) {
                    float ov2 = __shfl_xor_sync(0xffffffffu, bv, off);
                    int   oi = __shfl_xor_sync(0xffffffffu, bi, off);
                    if (ov2 > bv || (ov2 == bv && oi < bi)) { bv = ov2; bi = oi; }
                }
                mymsk |= 1u << bi;
                if (lane == bi) v = -INFINITY;
            }
        }

        {
            float gc0 = 1.f / (1.f + __expf(-g_g[tt * 48 + (lane >> 2) * 3]));
            float gc1 = 1.f / (1.f + __expf(-g_g[tt * 48 + ((lane >> 2) + 8) * 3]));
#pragma unroll
            for (int nt = 0; nt < 4; nt++) {
                float q0 = d4[nt][0] * gc0, q1 = d4[nt][1] * gc0;
                float q2 = d4[nt][2] * gc1, q3 = d4[nt][3] * gc1;
                __nv_bfloat16 b0, b1, b2, b3;
                pch0[nt] = pack_hi(q0, q1, b0, b1);
                pch1[nt] = pack_hi(q2, q3, b2, b3);
                pcl0[nt] = pack_bf16x2(q0 - __bfloat162float(b0), q1 - __bfloat162float(b1));
                pcl1[nt] = pack_bf16x2(q2 - __bfloat162float(b2), q3 - __bfloat162float(b3));
            }
        }
    }
    if (lane == 0 && w < 14) smask[w] = mymsk;

    __syncthreads();
    if (tid == 0) {
        uint32_t u = 0;
        for (int i = 0; i < 14; i++) u |= smask[i];
        int cnt = 0;
        for (int c = 0; c < NB; c++)
            if ((u >> c) & 1u) ulist[cnt++] = c;
        *ucnt = cnt;
    }
    __syncthreads();
    const int nu = *ucnt;

    // =========== selected block-sparse attention over the union ===========
    // No online max: p = e^(s/8) directly (scores bounded, fp32-safe);
    // normalize by sum at the end — identical softmax after normalization.
    float ov[8][4];
#pragma unroll
    for (int vt = 0; vt < 8; vt++)
#pragma unroll
        for (int j = 0; j < 4; j++) ov[vt][j] = 0.f;
    float srow[2] = {0.f, 0.f};

    for (int i = 0; i < nu; i++) {
        cp_wait0();
        __syncthreads();
        if (i + 1 < nu) issueKV(ulist[i + 1], (i + 1) & 1);

        const int c = ulist[i];
        if (((mymsk >> c) & 1u) && c <= cur) {
            const uint32_t base = sb0 + STG14 + (i & 1) * STG_SZ;

            float d[8][4];
#pragma unroll
            for (int nt = 0; nt < 8; nt++)
#pragma unroll
                for (int j = 0; j < 4; j++) d[nt][j] = 0.f;

#pragma unroll
            for (int ks = 0; ks < 4; ks++) {
                uint32_t qa = sb0 + (w * 16 + (lane & 15)) * 144 + ((lane >> 4) << 4) + ks * 32;
                uint32_t qh4[4], ql4[4];
                ldsm4(qh4, qa);
                ldsm4(ql4, qa + SQL14);
#pragma unroll
                for (int ntp = 0; ntp < 4; ntp++) {
                    uint32_t bh4[4], bl4[4];
                    uint32_t ba = base + ntp * 16 * 144 + bln + ks * 32;
                    ldsm4(bh4, ba);
                    ldsm4(bl4, ba + KV_T);
                    mma16816(d[ntp * 2],     qh4, bh4);
                    mma16816(d[ntp * 2],     ql4, bh4);
                    mma16816(d[ntp * 2],     qh4, bl4);
                    mma16816(d[ntp * 2 + 1], qh4, bh4 + 2);
                    mma16816(d[ntp * 2 + 1], ql4, bh4 + 2);
                    mma16816(d[ntp * 2 + 1], qh4, bl4 + 2);
                }
            }

            // ---- causal mask only for the diagonal block (no scale pass) ----
            if (c == cur) {
                const int colb = c * 64 + ((lane & 3) << 1);
#pragma unroll
                for (int nt = 0; nt < 8; nt++) {
                    int tok0 = colb + nt * 8;
                    bool v0 = tok0 <= tt, v1 = tok0 + 1 <= tt;
                    d[nt][0] = v0 ? d[nt][0] : NEGS;
                    d[nt][1] = v1 ? d[nt][1] : NEGS;
                    d[nt][2] = v0 ? d[nt][2] : NEGS;
                    d[nt][3] = v1 ? d[nt][3] : NEGS;
                }
            }

            // ---- exp (scale folded into SEXP) + PV via m16n8k16 pairs ----
#pragma unroll
            for (int ntp = 0; ntp < 4; ntp++) {
                const int ntE = ntp * 2, ntO = ntE + 1;
                float pE0 = fexp2(d[ntE][0] * SEXP);
                float pE1 = fexp2(d[ntE][1] * SEXP);
                float pE2 = fexp2(d[ntE][2] * SEXP);
                float pE3 = fexp2(d[ntE][3] * SEXP);
                float pO0 = fexp2(d[ntO][0] * SEXP);
                float pO1 = fexp2(d[ntO][1] * SEXP);
                float pO2 = fexp2(d[ntO][2] * SEXP);
                float pO3 = fexp2(d[ntO][3] * SEXP);
                srow[0] += pE0 + pE1 + pO0 + pO1;
                srow[1] += pE2 + pE3 + pO2 + pO3;
                __nv_bfloat16 b0, b1, b2, b3, b4, b5, b6, b7;
                uint32_t Ah4[4], Al4[4];
                Ah4[0] = pack_hi(pE0, pE1, b0, b1);
                Ah4[1] = pack_hi(pE2, pE3, b2, b3);
                Ah4[2] = pack_hi(pO0, pO1, b4, b5);
                Ah4[3] = pack_hi(pO2, pO3, b6, b7);
                Al4[0] = pack_bf16x2(pE0 - __bfloat162float(b0), pE1 - __bfloat162float(b1));
                Al4[1] = pack_bf16x2(pE2 - __bfloat162float(b2), pE3 - __bfloat162float(b3));
                Al4[2] = pack_bf16x2(pO0 - __bfloat162float(b4), pO1 - __bfloat162float(b5));
                Al4[3] = pack_bf16x2(pO2 - __bfloat162float(b6), pO3 - __bfloat162float(b7));

                uint32_t vE[8], vO[8];
                uint32_t vaE = base + 2 * KV_T + (ntE * 8 + (lane & 7)) * 144 + (lane >> 3) * 16;
                uint32_t vaO = vaE + 8 * 144;
                ldsm4t(vE, vaE);     ldsm4t(vE + 4, vaE + 64);
                ldsm4t(vO, vaO);     ldsm4t(vO + 4, vaO + 64);
#pragma unroll
                for (int vt = 0; vt < 8; vt++) {
                    uint32_t bb[2] = {vE[vt], vO[vt]};
                    mma16816(ov[vt], Ah4, bb);
                    mma16816(ov[vt], Al4, bb);
                }
                ldsm4t(vE, vaE + KV_T);  ldsm4t(vE + 4, vaE + KV_T + 64);
                ldsm4t(vO, vaO + KV_T);  ldsm4t(vO + 4, vaO + KV_T + 64);
#pragma unroll
                for (int vt = 0; vt < 8; vt++) {
                    uint32_t bb[2] = {vE[vt], vO[vt]};
                    mma16816(ov[vt], Ah4, bb);
                }
            }
        }
    }

    if (act) {
        {
            float s0 = srow[0], s1 = srow[1];
            s0 += __shfl_xor_sync(0xffffffffu, s0, 1);
            s0 += __shfl_xor_sync(0xffffffffu, s0, 2);
            s1 += __shfl_xor_sync(0xffffffffu, s1, 1);
            s1 += __shfl_xor_sync(0xffffffffu, s1, 2);
            float gs0 = 1.f / (1.f + __expf(-g_g[tt * 48 + (lane >> 2) * 3 + 1]));
            float gs1 = 1.f / (1.f + __expf(-g_g[tt * 48 + ((lane >> 2) + 8) * 3 + 1]));
            float f0 = gs0 / s0, f1 = gs1 / s1;
#pragma unroll
            for (int vt = 0; vt < 8; vt++) {
                ov[vt][0] *= f0; ov[vt][1] *= f0;
                ov[vt][2] *= f1; ov[vt][3] *= f1;
            }
        }
        // cmp PV via m16n8k16 pairs: ov += (p_cmp*gc) @ Vc
#pragma unroll
        for (int kp = 0; kp < 2; kp++) {
            const int kE = kp * 2, kO = kE + 1;
            uint32_t A_h[4] = {pch0[kE], pch1[kE], pch0[kO], pch1[kO]};
            uint32_t A_l[4] = {pcl0[kE], pcl1[kE], pcl0[kO], pcl1[kO]};
            uint32_t vE[8], vO[8];
            uint32_t vaE = sb0 + KC14 + 9216 + (kE * 8 + (lane & 7)) * 144 + (lane >> 3) * 16;
            uint32_t vaO = vaE + 8 * 144;
            ldsm4t(vE, vaE);     ldsm4t(vE + 4, vaE + 64);
            ldsm4t(vO, vaO);     ldsm4t(vO + 4, vaO + 64);
#pragma unroll
            for (int vt = 0; vt < 8; vt++) {
                uint32_t bb[2] = {vE[vt], vO[vt]};
                mma16816(ov[vt], A_h, bb);
                mma16816(ov[vt], A_l, bb);
            }
            ldsm4t(vE, vaE + 4608);  ldsm4t(vE + 4, vaE + 4608 + 64);
            ldsm4t(vO, vaO + 4608);  ldsm4t(vO + 4, vaO + 4608 + 64);
#pragma unroll
            for (int vt = 0; vt < 8; vt++) {
                uint32_t bb[2] = {vE[vt], vO[vt]};
                mma16816(ov[vt], A_h, bb);
            }
        }

        // ---- write comb as bf16 hi/lo ----
#pragma unroll
        for (int half = 0; half < 2; half++) {
            int h = (lane >> 2) + half * 8;
#pragma unroll
            for (int vt = 0; vt < 8; vt++) {
                int col = vt * 8 + ((lane & 3) << 1);
                size_t off = (size_t)tt * 1024 + h * 64 + col;
                float c0 = ov[vt][half * 2], c1 = ov[vt][half * 2 + 1];
                __nv_bfloat16 b0, b1;
                *(uint32_t*)(g_ch + off) = pack_hi(c0, c1, b0, b1);
                *(uint32_t*)(g_cl + off) =
                    pack_bf16x2(c0 - __bfloat162float(b0), c1 - __bfloat162float(b1));
            }
        }
    }
}

// ---------------- launch ----------------------------------------------------
extern "C" void kernel_launch(void* const* d_in, const int* in_sizes, int n_in,
                              void* d_out, int out_size) {
    const float* x  = (const float*)d_in[0];
    const float* Wq = (const float*)d_in[1];
    const float* Wk = (const float*)d_in[2];
    const float* Wv = (const float*)d_in[3];
    const float* Wg = (const float*)d_in[4];
    const float* Wo = (const float*)d_in[5];
    float* out = (float*)d_out;

    void *pq, *pxh, *pxl, *pch, *pcl, *pwch, *pwcl, *pwoh, *pwol;
    cudaGetSymbolAddress(&pq, g_q);
    cudaGetSymbolAddress(&pxh, g_xh);   cudaGetSymbolAddress(&pxl, g_xl);
    cudaGetSymbolAddress(&pch, g_ch);   cudaGetSymbolAddress(&pcl, g_cl);
    cudaGetSymbolAddress(&pwch, g_wch); cudaGetSymbolAddress(&pwcl, g_wcl);
    cudaGetSymbolAddress(&pwoh, g_woh); cudaGetSymbolAddress(&pwol, g_wol);

    cudaFuncSetAttribute(gemm_mma, cudaFuncAttributeMaxDynamicSharedMemorySize, GEMM_SMEM);
    cudaFuncSetAttribute(slc14, cudaFuncAttributeMaxDynamicSharedMemorySize, SLC14_SMEM);

    conv_all<<<4352, 256>>>((const float4*)x, (const float4*)Wq, (const float4*)Wk,
                            (const float4*)Wv, (const float4*)Wg, (const float4*)Wo);

    gemm_mma<<<dim3(10, 16), 256, GEMM_SMEM>>>((const __nv_bfloat16*)pxh, (const __nv_bfloat16*)pxl,
                                               (const __nv_bfloat16*)pwch, (const __nv_bfloat16*)pwcl,
                                               (float*)pq, 1);
    pool_kv<<<NB, 64>>>();
    slc14<<<(T_LEN + 13) / 14, 448, SLC14_SMEM>>>();

    gemm_mma<<<dim3(8, 16), 256, GEMM_SMEM>>>((const __nv_bfloat16*)pch, (const __nv_bfloat16*)pcl,
                                              (const __nv_bfloat16*)pwoh, (const __nv_bfloat16*)pwol,
                                              out, 0);
}

// round 16
// speedup vs baseline: 1.5261x; 1.0005x over previous
#include <cuda_runtime.h>
#include <cuda_bf16.h>
#include <cstdint>

// ---------------- problem constants ----------------
#define T_LEN 2048
#define DM    1024
#define NHEAD 16
#define HDIM  64
#define NB    32
#define SSEL  16
#define NEGV  (-1e30f)
#define NEGS  (-1.25e29f)
#define SEXP  0.180336880f   // 0.125 * log2(e); p = ex2(d * SEXP) = e^(d/8)

// ---------------- scratch ----------------------------------------------------
__device__ float g_q   [T_LEN * DM];
__device__ float g_k   [T_LEN * HDIM];
__device__ float g_v   [T_LEN * HDIM];
__device__ float g_g   [T_LEN * 48];

__device__ __nv_bfloat16 g_xh [T_LEN * DM], g_xl [T_LEN * DM];
__device__ __nv_bfloat16 g_qh [T_LEN * DM], g_ql [T_LEN * DM];
__device__ __nv_bfloat16 g_ch [T_LEN * DM], g_cl [T_LEN * DM];
__device__ __nv_bfloat16 g_kh [T_LEN * HDIM], g_kl [T_LEN * HDIM];
__device__ __nv_bfloat16 g_vh [T_LEN * HDIM], g_vl [T_LEN * HDIM];
__device__ __nv_bfloat16 g_kch[NB * HDIM], g_kcl[NB * HDIM];
__device__ __nv_bfloat16 g_vch[NB * HDIM], g_vcl[NB * HDIM];
__device__ __nv_bfloat16 g_wch[1280 * DM], g_wcl[1280 * DM];
__device__ __nv_bfloat16 g_woh[DM * DM],   g_wol[DM * DM];

// ================= helpers ==================================================
__device__ __forceinline__ uint32_t smem_u32(const void* p) {
    uint32_t a;
    asm("{ .reg .u64 t; cvta.to.shared.u64 t, %1; cvt.u32.u64 %0, t; }"
        : "=r"(a) : "l"(p));
    return a;
}
__device__ __forceinline__ void cp_async16(uint32_t saddr, const void* gaddr) {
    asm volatile("cp.async.cg.shared.global [%0], [%1], 16;"
                 :: "r"(saddr), "l"(gaddr));
}
__device__ __forceinline__ void cp_commit() {
    asm volatile("cp.async.commit_group;" ::: "memory");
}
__device__ __forceinline__ void cp_wait0() {
    asm volatile("cp.async.wait_group 0;" ::: "memory");
}
__device__ __forceinline__ void cp_wait1() {
    asm volatile("cp.async.wait_group 1;" ::: "memory");
}
__device__ __forceinline__ void ldsm4(uint32_t* r, uint32_t addr) {
    asm volatile("ldmatrix.sync.aligned.m8n8.x4.shared.b16 {%0,%1,%2,%3}, [%4];"
                 : "=r"(r[0]), "=r"(r[1]), "=r"(r[2]), "=r"(r[3]) : "r"(addr));
}
__device__ __forceinline__ void ldsm4t(uint32_t* r, uint32_t addr) {
    asm volatile("ldmatrix.sync.aligned.m8n8.x4.trans.shared.b16 {%0,%1,%2,%3}, [%4];"
                 : "=r"(r[0]), "=r"(r[1]), "=r"(r[2]), "=r"(r[3]) : "r"(addr));
}
__device__ __forceinline__ void mma16816(float* d, const uint32_t* a, const uint32_t* b) {
    asm volatile(
        "mma.sync.aligned.m16n8k16.row.col.f32.bf16.bf16.f32 "
        "{%0,%1,%2,%3}, {%4,%5,%6,%7}, {%8,%9}, {%0,%1,%2,%3};"
        : "+f"(d[0]), "+f"(d[1]), "+f"(d[2]), "+f"(d[3])
        : "r"(a[0]), "r"(a[1]), "r"(a[2]), "r"(a[3]), "r"(b[0]), "r"(b[1]));
}
__device__ __forceinline__ uint32_t pack_bf16x2(float lo, float hi) {
    uint32_t r;
    asm("cvt.rn.bf16x2.f32 %0, %1, %2;" : "=r"(r) : "f"(hi), "f"(lo));
    return r;
}
__device__ __forceinline__ uint32_t pack_hi(float a, float b, __nv_bfloat16& ha, __nv_bfloat16& hb) {
    ha = __float2bfloat16(a); hb = __float2bfloat16(b);
    return (uint32_t)__bfloat16_as_ushort(ha) | ((uint32_t)__bfloat16_as_ushort(hb) << 16);
}
__device__ __forceinline__ float fexp2(float x) {
    float y;
    asm("ex2.approx.f32 %0, %1;" : "=f"(y) : "f"(x));
    return y;
}

// ====== single-launch fp32 -> bf16 hi/lo conversion for all weights/x =======
__global__ __launch_bounds__(256) void conv_all(const float4* __restrict__ x,
                                                const float4* __restrict__ Wq,
                                                const float4* __restrict__ Wk,
                                                const float4* __restrict__ Wv,
                                                const float4* __restrict__ Wg,
                                                const float4* __restrict__ Wo) {
    int i = blockIdx.x * 256 + threadIdx.x;
    const float4* src; uint2 *h, *l; int di;
    if (i < 524288)       { src = x;  di = i;           h = (uint2*)g_xh;  l = (uint2*)g_xl; }
    else if (i < 786432)  { src = Wq; di = i - 524288;  h = (uint2*)g_wch; l = (uint2*)g_wcl; }
    else if (i < 802816)  { src = Wk; di = i - 786432;  h = (uint2*)g_wch + 262144; l = (uint2*)g_wcl + 262144; }
    else if (i < 819200)  { src = Wv; di = i - 802816;  h = (uint2*)g_wch + 278528; l = (uint2*)g_wcl + 278528; }
    else if (i < 831488)  { src = Wg; di = i - 819200;  h = (uint2*)g_wch + 294912; l = (uint2*)g_wcl + 294912; }
    else if (i < 1093632) { src = Wo; di = i - 831488;  h = (uint2*)g_woh; l = (uint2*)g_wol; }
    else {
        int dz = i - 1093632;
        uint2 z = make_uint2(0u, 0u);
        ((uint2*)g_wch)[307200 + dz] = z;
        ((uint2*)g_wcl)[307200 + dz] = z;
        return;
    }
    float4 v = src[di];
    __nv_bfloat16 h0, h1, h2, h3;
    uint2 hv, lv;
    hv.x = pack_hi(v.x, v.y, h0, h1);
    hv.y = pack_hi(v.z, v.w, h2, h3);
    lv.x = pack_bf16x2(v.x - __bfloat162float(h0), v.y - __bfloat162float(h1));
    lv.y = pack_bf16x2(v.z - __bfloat162float(h2), v.w - __bfloat162float(h3));
    h[di] = hv;
    l[di] = lv;
}

// ================= tensor-core GEMM via mma.sync (bf16x3, 2-stage) ==========
#define TSTRIDE 80
#define TILE_BYTES (128 * TSTRIDE)
#define BUF_BYTES  (4 * TILE_BYTES)
#define GEMM_SMEM  (2 * BUF_BYTES)

__global__ __launch_bounds__(256, 2) void gemm_mma(const __nv_bfloat16* __restrict__ Ah,
                                                   const __nv_bfloat16* __restrict__ Al,
                                                   const __nv_bfloat16* __restrict__ Bh,
                                                   const __nv_bfloat16* __restrict__ Bl,
                                                   float* __restrict__ C,
                                                   int mode) {
    extern __shared__ char sm[];
    const uint32_t sbase = smem_u32(sm);
    const int tid = threadIdx.x;
    const int lane = tid & 31, wid = tid >> 5;
    const int m0 = blockIdx.y * 128;
    const int n0 = blockIdx.x * 128;
    const int wm = (wid >> 2) * 64;
    const int wn = (wid & 3) * 32;

    const __nv_bfloat16* gsrc[4] = {Ah, Al, Bh, Bl};

    float acc[4][4][4];
#pragma unroll
    for (int i = 0; i < 4; i++)
#pragma unroll
        for (int j = 0; j < 4; j++)
#pragma unroll
            for (int k = 0; k < 4; k++) acc[i][j][k] = 0.f;

    const int arow = wm + (lane & 15);
    const int akc  = (lane >> 4) << 3;
    const int brow = wn + (lane & 7) + ((lane >> 4) << 3);
    const int bkc  = ((lane >> 3) & 1) << 3;

    auto issue = [&](int c, int buf) {
#pragma unroll
        for (int T = 0; T < 4; T++) {
            const __nv_bfloat16* src = gsrc[T];
            const int rb = (T < 2) ? m0 : n0;
#pragma unroll
            for (int i = 0; i < 2; i++) {
                int idx = i * 256 + tid;
                int row = idx >> 2;
                int u   = idx & 3;
                uint32_t sa = sbase + buf * BUF_BYTES + T * TILE_BYTES + row * TSTRIDE + u * 16;
                cp_async16(sa, src + (size_t)(rb + row) * 1024 + c * 32 + u * 8);
            }
        }
        cp_commit();
    };

    issue(0, 0);

    for (int c = 0; c < 32; c++) {
        const int buf = c & 1;
        cp_wait0();
        __syncthreads();
        if (c + 1 < 32) issue(c + 1, buf ^ 1);

        const uint32_t base = sbase + buf * BUF_BYTES;
#pragma unroll
        for (int ks = 0; ks < 2; ks++) {
            uint32_t ah[4][4], al[4][4], bh[2][4], bl[2][4];
#pragma unroll
            for (int mt = 0; mt < 4; mt++) {
                uint32_t aa = base + (arow + mt * 16) * TSTRIDE + (ks * 16 + akc) * 2;
                ldsm4(ah[mt], aa);
                ldsm4(al[mt], aa + TILE_BYTES);
            }
#pragma unroll
            for (int np = 0; np < 2; np++) {
                uint32_t ba = base + 2 * TILE_BYTES + (brow + np * 16) * TSTRIDE + (ks * 16 + bkc) * 2;
                ldsm4(bh[np], ba);
                ldsm4(bl[np], ba + TILE_BYTES);
            }
#pragma unroll
            for (int mt = 0; mt < 4; mt++)
#pragma unroll
                for (int nt = 0; nt < 4; nt++) {
                    const uint32_t* ph = &bh[nt >> 1][(nt & 1) * 2];
                    const uint32_t* pl = &bl[nt >> 1][(nt & 1) * 2];
                    mma16816(acc[mt][nt], ah[mt], ph);
                    mma16816(acc[mt][nt], al[mt], ph);
                    mma16816(acc[mt][nt], ah[mt], pl);
                }
        }
        __syncthreads();
    }

    const int g = lane >> 2, t4 = lane & 3;
#pragma unroll
    for (int mt = 0; mt < 4; mt++)
#pragma unroll
        for (int nt = 0; nt < 4; nt++) {
            int r = m0 + wm + mt * 16 + g;
            int cc = n0 + wn + nt * 8 + t4 * 2;
#pragma unroll
            for (int half = 0; half < 2; half++) {
                int rr = r + half * 8;
                float v0 = acc[mt][nt][half * 2], v1 = acc[mt][nt][half * 2 + 1];
                if (mode == 0) {
                    *(float2*)(C + (size_t)rr * 1024 + cc) = make_float2(v0, v1);
                } else {
                    __nv_bfloat16 b0, b1;
                    if (cc < 1024) {
                        *(float2*)(g_q + (size_t)rr * 1024 + cc) = make_float2(v0, v1);
                        uint32_t hh = pack_hi(v0, v1, b0, b1);
                        *(uint32_t*)(g_qh + (size_t)rr * 1024 + cc) = hh;
                        *(uint32_t*)(g_ql + (size_t)rr * 1024 + cc) =
                            pack_bf16x2(v0 - __bfloat162float(b0), v1 - __bfloat162float(b1));
                    } else if (cc < 1088) {
                        int k = cc - 1024;
                        *(float2*)(g_k + (size_t)rr * 64 + k) = make_float2(v0, v1);
                        uint32_t hh = pack_hi(v0, v1, b0, b1);
                        *(uint32_t*)(g_kh + (size_t)rr * 64 + k) = hh;
                        *(uint32_t*)(g_kl + (size_t)rr * 64 + k) =
                            pack_bf16x2(v0 - __bfloat162float(b0), v1 - __bfloat162float(b1));
                    } else if (cc < 1152) {
                        int k = cc - 1088;
                        *(float2*)(g_v + (size_t)rr * 64 + k) = make_float2(v0, v1);
                        uint32_t hh = pack_hi(v0, v1, b0, b1);
                        *(uint32_t*)(g_vh + (size_t)rr * 64 + k) = hh;
                        *(uint32_t*)(g_vl + (size_t)rr * 64 + k) =
                            pack_bf16x2(v0 - __bfloat162float(b0), v1 - __bfloat162float(b1));
                    } else if (cc < 1200) {
                        int k = cc - 1152;
                        *(float2*)(g_g + (size_t)rr * 48 + k) = make_float2(v0, v1);
                    }
                }
            }
        }
}

// ---------------- mean-pool K,V (bf16 hi/lo) ---------------------------------
__global__ void pool_kv() {
    int c = blockIdx.x, d = threadIdx.x;
    float sk = 0.f, sv = 0.f;
    for (int i = 0; i < 64; i++) {
        sk += g_k[(size_t)(c * 64 + i) * 64 + d];
        sv += g_v[(size_t)(c * 64 + i) * 64 + d];
    }
    sk *= (1.f / 64.f); sv *= (1.f / 64.f);
    int idx = c * 64 + d;
    __nv_bfloat16 hk = __float2bfloat16(sk);
    __nv_bfloat16 hv2 = __float2bfloat16(sv);
    g_kch[idx] = hk; g_kcl[idx] = __float2bfloat16(sk - __bfloat162float(hk));
    g_vch[idx] = hv2; g_vcl[idx] = __float2bfloat16(sv - __bfloat162float(hv2));
}

// ====== FUSED: cmp attn + top-k + union selected attn, 7 tokens/CTA =========
// 224 threads (1 token/warp), grid 293, 2 CTAs/SM.
// smem: Qh 112x144 | Ql | 2 KV stages (stage0 doubles as Kc/Vc during cmp,
//       and as restaged Vc for the epilogue) | meta+imp. 107264 B
#define SQL7      16128
#define STG7      32256
#define STG_SZ    36864
#define KV_T      9216
#define META7     105984
#define IMP7      (META7 + 256)
#define SLC7_SMEM (IMP7 + 1024)   // 107264

__global__ __launch_bounds__(224, 2) void slc7() {
    extern __shared__ char smc[];
    const uint32_t sb0 = smem_u32(smc);
    const int tid = threadIdx.x;
    const int lane = tid & 31, w = tid >> 5;      // w = 0..6
    const int T0 = blockIdx.x * 7;
    const int ntok = min(7, T_LEN - T0);
    const bool act = (w < ntok);
    const int tt = act ? (T0 + w) : (T_LEN - 1);

    uint32_t* smask = (uint32_t*)(smc + META7);
    int* ulist = (int*)(smc + META7 + 128);
    int* ucnt  = (int*)(smc + META7 + 124);
    float* impsm = (float*)(smc + IMP7);

    // ---- group A: Q hi/lo (112 rows x 2) + Kc/Vc hi/lo into stage0 ----
#pragma unroll
    for (int i = 0; i < 8; i++) {
        int idx = i * 224 + tid;                 // 0..1791
        int tile = idx / 896;
        int wi = idx - tile * 896;
        int row = wi >> 3, u = wi & 7;
        int token = T0 + (row >> 4);
        if (token > T_LEN - 1) token = T_LEN - 1;
        int head = row & 15;
        size_t go = (size_t)token * 1024 + head * 64 + u * 8;
        cp_async16(sb0 + tile * SQL7 + row * 144 + u * 16, (tile ? g_ql : g_qh) + go);
    }
#pragma unroll
    for (int i = 0; i < 5; i++) {
        int idx = i * 224 + tid;                 // 0..1023 valid
        if (idx < 1024) {
            int tile = idx >> 8, r = (idx >> 3) & 31, u = idx & 7;
            const __nv_bfloat16* gp = (tile == 0) ? g_kch : (tile == 1) ? g_kcl
                                    : (tile == 2) ? g_vch : g_vcl;
            cp_async16(sb0 + STG7 + tile * 4608 + r * 144 + u * 16, gp + r * 64 + u * 8);
        }
    }
    cp_commit();

    auto issueKV = [&](int c, int stage) {
        uint32_t base = sb0 + STG7 + stage * STG_SZ;
#pragma unroll
        for (int i = 0; i < 10; i++) {
            int cid = i * 224 + tid;             // 0..2047 valid
            if (cid < 2048) {
                int tile = cid >> 9, r = (cid >> 3) & 63, u = cid & 7;
                const __nv_bfloat16* gp = (tile == 0) ? g_kh : (tile == 1) ? g_kl
                                        : (tile == 2) ? g_vh : g_vl;
                cp_async16(base + tile * KV_T + r * 144 + u * 16,
                           gp + (size_t)(c * 64 + r) * 64 + u * 8);
            }
        }
        cp_commit();
    };

    // group B: KV block 0 (always selected/forced) into STAGE 1
    issueKV(0, 1);
    cp_wait1();        // group A complete (Q + Kc/Vc); KV0 may be in flight
    __syncthreads();

    const int nvis = (tt + 1) >> 6;
    const int cur = tt >> 6;

    uint32_t mymsk = 0;
    uint32_t pch0[4], pch1[4], pcl0[4], pcl1[4];

    const uint32_t bln = (((lane >> 4) << 3) + (lane & 7)) * 144 + ((lane >> 3) & 1) * 16;

    if (act) {
        // =========== compressed branch: QK over pooled Kc (bf16x3) ===========
        float d4[4][4];
#pragma unroll
        for (int nt = 0; nt < 4; nt++)
#pragma unroll
            for (int j = 0; j < 4; j++) d4[nt][j] = 0.f;

#pragma unroll
        for (int ks = 0; ks < 4; ks++) {
            uint32_t qa = sb0 + (w * 16 + (lane & 15)) * 144 + ((lane >> 4) << 4) + ks * 32;
            uint32_t qh4[4], ql4[4];
            ldsm4(qh4, qa);
            ldsm4(ql4, qa + SQL7);
#pragma unroll
            for (int ntp = 0; ntp < 2; ntp++) {
                uint32_t bh4[4], bl4[4];
                uint32_t ba = sb0 + STG7 + ntp * 16 * 144 + bln + ks * 32;
                ldsm4(bh4, ba);
                ldsm4(bl4, ba + 4608);
                mma16816(d4[ntp * 2],     qh4, bh4);
                mma16816(d4[ntp * 2],     ql4, bh4);
                mma16816(d4[ntp * 2],     qh4, bl4);
                mma16816(d4[ntp * 2 + 1], qh4, bh4 + 2);
                mma16816(d4[ntp * 2 + 1], ql4, bh4 + 2);
                mma16816(d4[ntp * 2 + 1], qh4, bl4 + 2);
            }
        }

        float bm0 = NEGS, bm1 = NEGS;
#pragma unroll
        for (int nt = 0; nt < 4; nt++) {
            int c0 = nt * 8 + ((lane & 3) << 1);
            bool v0 = c0 < nvis, v1 = c0 + 1 < nvis;
            d4[nt][0] = v0 ? d4[nt][0] * 0.125f : NEGS;
            d4[nt][1] = v1 ? d4[nt][1] * 0.125f : NEGS;
            d4[nt][2] = v0 ? d4[nt][2] * 0.125f : NEGS;
            d4[nt][3] = v1 ? d4[nt][3] * 0.125f : NEGS;
            bm0 = fmaxf(bm0, fmaxf(d4[nt][0], d4[nt][1]));
            bm1 = fmaxf(bm1, fmaxf(d4[nt][2], d4[nt][3]));
        }
        bm0 = fmaxf(bm0, __shfl_xor_sync(0xffffffffu, bm0, 1));
        bm0 = fmaxf(bm0, __shfl_xor_sync(0xffffffffu, bm0, 2));
        bm1 = fmaxf(bm1, __shfl_xor_sync(0xffffffffu, bm1, 1));
        bm1 = fmaxf(bm1, __shfl_xor_sync(0xffffffffu, bm1, 2));

        float ps0 = 0.f, ps1 = 0.f;
#pragma unroll
        for (int nt = 0; nt < 4; nt++) {
            d4[nt][0] = __expf(d4[nt][0] - bm0);
            d4[nt][1] = __expf(d4[nt][1] - bm0);
            d4[nt][2] = __expf(d4[nt][2] - bm1);
            d4[nt][3] = __expf(d4[nt][3] - bm1);
            ps0 += d4[nt][0] + d4[nt][1];
            ps1 += d4[nt][2] + d4[nt][3];
        }
        ps0 += __shfl_xor_sync(0xffffffffu, ps0, 1);
        ps0 += __shfl_xor_sync(0xffffffffu, ps0, 2);
        ps1 += __shfl_xor_sync(0xffffffffu, ps1, 1);
        ps1 += __shfl_xor_sync(0xffffffffu, ps1, 2);
        float iv0 = (nvis > 0) ? 1.f / ps0 : 0.f;
        float iv1 = (nvis > 0) ? 1.f / ps1 : 0.f;
#pragma unroll
        for (int nt = 0; nt < 4; nt++) {
            d4[nt][0] *= iv0; d4[nt][1] *= iv0;
            d4[nt][2] *= iv1; d4[nt][3] *= iv1;
        }

#pragma unroll
        for (int nt = 0; nt < 4; nt++) {
            float t0 = d4[nt][0] + d4[nt][2];
            float t1 = d4[nt][1] + d4[nt][3];
            t0 += __shfl_xor_sync(0xffffffffu, t0, 4);
            t0 += __shfl_xor_sync(0xffffffffu, t0, 8);
            t0 += __shfl_xor_sync(0xffffffffu, t0, 16);
            t1 += __shfl_xor_sync(0xffffffffu, t1, 4);
            t1 += __shfl_xor_sync(0xffffffffu, t1, 8);
            t1 += __shfl_xor_sync(0xffffffffu, t1, 16);
            int c0 = nt * 8 + ((lane & 3) << 1);
            impsm[w * 32 + c0] = t0;
            impsm[w * 32 + c0 + 1] = t1;
        }
        __syncwarp();

        {
            float base = impsm[w * 32 + lane];
            float v = (lane == 0 || lane == cur) ? INFINITY
                    : (lane > cur ? NEGV : base);
#pragma unroll
            for (int s = 0; s < SSEL; s++) {
                float bv = v; int bi = lane;
#pragma unroll
                for (int off = 16; off >= 1; off >>= 1) {
                    float ov2 = __shfl_xor_sync(0xffffffffu, bv, off);
                    int   oi = __shfl_xor_sync(0xffffffffu, bi, off);
                    if (ov2 > bv || (ov2 == bv && oi < bi)) { bv = ov2; bi = oi; }
                }
                mymsk |= 1u << bi;
                if (lane == bi) v = -INFINITY;
            }
        }

        {
            float gc0 = 1.f / (1.f + __expf(-g_g[tt * 48 + (lane >> 2) * 3]));
            float gc1 = 1.f / (1.f + __expf(-g_g[tt * 48 + ((lane >> 2) + 8) * 3]));
#pragma unroll
            for (int nt = 0; nt < 4; nt++) {
                float q0 = d4[nt][0] * gc0, q1 = d4[nt][1] * gc0;
                float q2 = d4[nt][2] * gc1, q3 = d4[nt][3] * gc1;
                __nv_bfloat16 b0, b1, b2, b3;
                pch0[nt] = pack_hi(q0, q1, b0, b1);
                pch1[nt] = pack_hi(q2, q3, b2, b3);
                pcl0[nt] = pack_bf16x2(q0 - __bfloat162float(b0), q1 - __bfloat162float(b1));
                pcl1[nt] = pack_bf16x2(q2 - __bfloat162float(b2), q3 - __bfloat162float(b3));
            }
        }
    }
    if (lane == 0 && w < 7) smask[w] = mymsk;

    __syncthreads();
    if (tid == 0) {
        uint32_t u = 0;
        for (int i = 0; i < 7; i++) u |= smask[i];
        int cnt = 0;
        for (int c = 0; c < NB; c++)
            if ((u >> c) & 1u) ulist[cnt++] = c;
        *ucnt = cnt;       // ulist[0] == 0 always (forced)
    }
    __syncthreads();
    const int nu = *ucnt;

    // =========== selected block-sparse attention over the union ===========
    // Block i lives in stage ((i&1)^1): i=0 -> stage1 (pre-issued), i=1 -> stage0, ...
    float ov[8][4];
#pragma unroll
    for (int vt = 0; vt < 8; vt++)
#pragma unroll
        for (int j = 0; j < 4; j++) ov[vt][j] = 0.f;
    float srow[2] = {0.f, 0.f};

    for (int i = 0; i < nu; i++) {
        cp_wait0();
        __syncthreads();
        if (i + 1 < nu) issueKV(ulist[i + 1], (i & 1));   // next block into the other stage

        const int c = ulist[i];
        if (((mymsk >> c) & 1u) && c <= cur) {
            const uint32_t base = sb0 + STG7 + ((i & 1) ^ 1) * STG_SZ;

            float d[8][4];
#pragma unroll
            for (int nt = 0; nt < 8; nt++)
#pragma unroll
                for (int j = 0; j < 4; j++) d[nt][j] = 0.f;

#pragma unroll
            for (int ks = 0; ks < 4; ks++) {
                uint32_t qa = sb0 + (w * 16 + (lane & 15)) * 144 + ((lane >> 4) << 4) + ks * 32;
                uint32_t qh4[4], ql4[4];
                ldsm4(qh4, qa);
                ldsm4(ql4, qa + SQL7);
#pragma unroll
                for (int ntp = 0; ntp < 4; ntp++) {
                    uint32_t bh4[4], bl4[4];
                    uint32_t ba = base + ntp * 16 * 144 + bln + ks * 32;
                    ldsm4(bh4, ba);
                    ldsm4(bl4, ba + KV_T);
                    mma16816(d[ntp * 2],     qh4, bh4);
                    mma16816(d[ntp * 2],     ql4, bh4);
                    mma16816(d[ntp * 2],     qh4, bl4);
                    mma16816(d[ntp * 2 + 1], qh4, bh4 + 2);
                    mma16816(d[ntp * 2 + 1], ql4, bh4 + 2);
                    mma16816(d[ntp * 2 + 1], qh4, bl4 + 2);
                }
            }

            // ---- causal mask only for the diagonal block ----
            if (c == cur) {
                const int colb = c * 64 + ((lane & 3) << 1);
#pragma unroll
                for (int nt = 0; nt < 8; nt++) {
                    int tok0 = colb + nt * 8;
                    bool v0 = tok0 <= tt, v1 = tok0 + 1 <= tt;
                    d[nt][0] = v0 ? d[nt][0] : NEGS;
                    d[nt][1] = v1 ? d[nt][1] : NEGS;
                    d[nt][2] = v0 ? d[nt][2] : NEGS;
                    d[nt][3] = v1 ? d[nt][3] : NEGS;
                }
            }

            // ---- exp (scale folded) + PV via m16n8k16 pairs (bf16x3) ----
#pragma unroll
            for (int ntp = 0; ntp < 4; ntp++) {
                const int ntE = ntp * 2, ntO = ntE + 1;
                float pE0 = fexp2(d[ntE][0] * SEXP);
                float pE1 = fexp2(d[ntE][1] * SEXP);
                float pE2 = fexp2(d[ntE][2] * SEXP);
                float pE3 = fexp2(d[ntE][3] * SEXP);
                float pO0 = fexp2(d[ntO][0] * SEXP);
                float pO1 = fexp2(d[ntO][1] * SEXP);
                float pO2 = fexp2(d[ntO][2] * SEXP);
                float pO3 = fexp2(d[ntO][3] * SEXP);
                srow[0] += pE0 + pE1 + pO0 + pO1;
                srow[1] += pE2 + pE3 + pO2 + pO3;
                __nv_bfloat16 b0, b1, b2, b3, b4, b5, b6, b7;
                uint32_t Ah4[4], Al4[4];
                Ah4[0] = pack_hi(pE0, pE1, b0, b1);
                Ah4[1] = pack_hi(pE2, pE3, b2, b3);
                Ah4[2] = pack_hi(pO0, pO1, b4, b5);
                Ah4[3] = pack_hi(pO2, pO3, b6, b7);
                Al4[0] = pack_bf16x2(pE0 - __bfloat162float(b0), pE1 - __bfloat162float(b1));
                Al4[1] = pack_bf16x2(pE2 - __bfloat162float(b2), pE3 - __bfloat162float(b3));
                Al4[2] = pack_bf16x2(pO0 - __bfloat162float(b4), pO1 - __bfloat162float(b5));
                Al4[3] = pack_bf16x2(pO2 - __bfloat162float(b6), pO3 - __bfloat162float(b7));

                uint32_t vE[8], vO[8];
                uint32_t vaE = base + 2 * KV_T + (ntE * 8 + (lane & 7)) * 144 + (lane >> 3) * 16;
                uint32_t vaO = vaE + 8 * 144;
                ldsm4t(vE, vaE);     ldsm4t(vE + 4, vaE + 64);
                ldsm4t(vO, vaO);     ldsm4t(vO + 4, vaO + 64);
#pragma unroll
                for (int vt = 0; vt < 8; vt++) {
                    uint32_t bb[2] = {vE[vt], vO[vt]};
                    mma16816(ov[vt], Ah4, bb);
                    mma16816(ov[vt], Al4, bb);
                }
                ldsm4t(vE, vaE + KV_T);  ldsm4t(vE + 4, vaE + KV_T + 64);
                ldsm4t(vO, vaO + KV_T);  ldsm4t(vO + 4, vaO + KV_T + 64);
#pragma unroll
                for (int vt = 0; vt < 8; vt++) {
                    uint32_t bb[2] = {vE[vt], vO[vt]};
                    mma16816(ov[vt], Ah4, bb);
                }
            }
        }
    }

    // ---- re-stage pooled Vc hi/lo into stage0 for the cmp-PV epilogue ----
    __syncthreads();                      // all PV reads done before overwrite
#pragma unroll
    for (int i = 0; i < 3; i++) {
        int idx = i * 224 + tid;          // 0..511 valid
        if (idx < 512) {
            int tile = idx >> 8, r = (idx >> 3) & 31, u = idx & 7;
            cp_async16(sb0 + STG7 + tile * 4608 + r * 144 + u * 16,
                       (tile ? g_vcl : g_vch) + r * 64 + u * 8);
        }
    }
    cp_commit();
    cp_wait0();
    __syncthreads();

    if (act) {
        {
            float s0 = srow[0], s1 = srow[1];
            s0 += __shfl_xor_sync(0xffffffffu, s0, 1);
            s0 += __shfl_xor_sync(0xffffffffu, s0, 2);
            s1 += __shfl_xor_sync(0xffffffffu, s1, 1);
            s1 += __shfl_xor_sync(0xffffffffu, s1, 2);
            float gs0 = 1.f / (1.f + __expf(-g_g[tt * 48 + (lane >> 2) * 3 + 1]));
            float gs1 = 1.f / (1.f + __expf(-g_g[tt * 48 + ((lane >> 2) + 8) * 3 + 1]));
            float f0 = gs0 / s0, f1 = gs1 / s1;
#pragma unroll
            for (int vt = 0; vt < 8; vt++) {
                ov[vt][0] *= f0; ov[vt][1] *= f0;
                ov[vt][2] *= f1; ov[vt][3] *= f1;
            }
        }
        // cmp PV via m16n8k16 pairs: ov += (p_cmp*gc) @ Vc  (restaged at STG7)
#pragma unroll
        for (int kp = 0; kp < 2; kp++) {
            const int kE = kp * 2, kO = kE + 1;
            uint32_t A_h[4] = {pch0[kE], pch1[kE], pch0[kO], pch1[kO]};
            uint32_t A_l[4] = {pcl0[kE], pcl1[kE], pcl0[kO], pcl1[kO]};
            uint32_t vE[8], vO[8];
            uint32_t vaE = sb0 + STG7 + (kE * 8 + (lane & 7)) * 144 + (lane >> 3) * 16;
            uint32_t vaO = vaE + 8 * 144;
            ldsm4t(vE, vaE);     ldsm4t(vE + 4, vaE + 64);
            ldsm4t(vO, vaO);     ldsm4t(vO + 4, vaO + 64);
#pragma unroll
            for (int vt = 0; vt < 8; vt++) {
                uint32_t bb[2] = {vE[vt], vO[vt]};
                mma16816(ov[vt], A_h, bb);
                mma16816(ov[vt], A_l, bb);
            }
            ldsm4t(vE, vaE + 4608);  ldsm4t(vE + 4, vaE + 4608 + 64);
            ldsm4t(vO, vaO + 4608);  ldsm4t(vO + 4, vaO + 4608 + 64);
#pragma unroll
            for (int vt = 0; vt < 8; vt++) {
                uint32_t bb[2] = {vE[vt], vO[vt]};
                mma16816(ov[vt], A_h, bb);
            }
        }

        // ---- write comb as bf16 hi/lo ----
#pragma unroll
        for (int half = 0; half < 2; half++) {
            int h = (lane >> 2) + half * 8;
#pragma unroll
            for (int vt = 0; vt < 8; vt++) {
                int col = vt * 8 + ((lane & 3) << 1);
                size_t off = (size_t)tt * 1024 + h * 64 + col;
                float c0 = ov[vt][half * 2], c1 = ov[vt][half * 2 + 1];
                __nv_bfloat16 b0, b1;
                *(uint32_t*)(g_ch + off) = pack_hi(c0, c1, b0, b1);
                *(uint32_t*)(g_cl + off) =
                    pack_bf16x2(c0 - __bfloat162float(b0), c1 - __bfloat162float(b1));
            }
        }
    }
}

// ---------------- launch ----------------------------------------------------
extern "C" void kernel_launch(void* const* d_in, const int* in_sizes, int n_in,
                              void* d_out, int out_size) {
    const float* x  = (const float*)d_in[0];
    const float* Wq = (const float*)d_in[1];
    const float* Wk = (const float*)d_in[2];
    const float* Wv = (const float*)d_in[3];
    const float* Wg = (const float*)d_in[4];
    const float* Wo = (const float*)d_in[5];
    float* out = (float*)d_out;

    void *pq, *pxh, *pxl, *pch, *pcl, *pwch, *pwcl, *pwoh, *pwol;
    cudaGetSymbolAddress(&pq, g_q);
    cudaGetSymbolAddress(&pxh, g_xh);   cudaGetSymbolAddress(&pxl, g_xl);
    cudaGetSymbolAddress(&pch, g_ch);   cudaGetSymbolAddress(&pcl, g_cl);
    cudaGetSymbolAddress(&pwch, g_wch); cudaGetSymbolAddress(&pwcl, g_wcl);
    cudaGetSymbolAddress(&pwoh, g_woh); cudaGetSymbolAddress(&pwol, g_wol);

    cudaFuncSetAttribute(gemm_mma, cudaFuncAttributeMaxDynamicSharedMemorySize, GEMM_SMEM);
    cudaFuncSetAttribute(slc7, cudaFuncAttributeMaxDynamicSharedMemorySize, SLC7_SMEM);

    conv_all<<<4352, 256>>>((const float4*)x, (const float4*)Wq, (const float4*)Wk,
                            (const float4*)Wv, (const float4*)Wg, (const float4*)Wo);

    gemm_mma<<<dim3(10, 16), 256, GEMM_SMEM>>>((const __nv_bfloat16*)pxh, (const __nv_bfloat16*)pxl,
                                               (const __nv_bfloat16*)pwch, (const __nv_bfloat16*)pwcl,
                                               (float*)pq, 1);
    pool_kv<<<NB, 64>>>();
    slc7<<<(T_LEN + 6) / 7, 224, SLC7_SMEM>>>();

    gemm_mma<<<dim3(8, 16), 256, GEMM_SMEM>>>((const __nv_bfloat16*)pch, (const __nv_bfloat16*)pcl,
                                              (const __nv_bfloat16*)pwoh, (const __nv_bfloat16*)pwol,
                                              out, 0);
}